// round 1
// baseline (speedup 1.0000x reference)
#include <cuda_runtime.h>
#include <math.h>

#define BB    128
#define SS    32
#define INSZ  512
#define HH    1024
#define OUTSZ 512
#define NN    16384
#define WW    128
#define CC    899
#define G4    4096
#define COLD  904      // co row stride (16B aligned)
#define NTSIM 256      // sim n-tiles of 64

// ---------------- device state / scratch ----------------
__device__ float d_mem[NN*WW];        // 8MB  memory matrix (mutable)
__device__ float d_meminv[NN];        // 1/max(||row||,1e-12)
__device__ float d_h[BB*HH];
__device__ float d_c[BB*HH];
__device__ float d_g[BB*G4];          // LSTM pre-activations
__device__ float d_co[BB*COLD];       // controller output
__device__ float d_keys[BB*2*WW];     // [b][rkey(128)|wkey(128)] raw (bias added)
__device__ float d_erad[BB*2*WW];     // [b][er(128)|ad(128)] activated
__device__ float d_scal[BB*4];        // rbeta,rgamma,wbeta,wgamma (transformed)
__device__ float d_sim[256*NN];       // 16MB sim rows (r = head*128+b)
__device__ float d_pmax[256*NTSIM];   // per-(row, ntile) max of sim
__device__ float d_rw[BB*NN];         // read weights (state)
__device__ float d_ww[BB*NN];         // write weights (per step)
__device__ float d_rv[BB*WW];         // read vector (state)
__device__ float d_rvpart[128*BB*WW]; // split-K partials for rv

__device__ __forceinline__ float sigmoidf_(float x){ return 1.f/(1.f+__expf(-x)); }
__device__ __forceinline__ float softplusf_(float x){ return x>15.f ? x : log1pf(__expf(x)); }

// ---------------- init ----------------
__global__ void k_init(const float* __restrict__ memory){
    int i = blockIdx.x*256 + threadIdx.x;   // 0..2097151
    d_mem[i] = memory[i];                   // NN*WW == 2097152
    d_rw[i]  = 1.0f/NN;                     // BB*NN == 2097152
    if (i < BB*HH){ d_h[i]=0.f; d_c[i]=0.f; }
    if (i < BB*WW) d_rv[i] = 0.f;
}

__global__ void k_rownorm(){
    int row  = blockIdx.x*8 + (threadIdx.x>>5);
    int lane = threadIdx.x & 31;
    const float4* p = (const float4*)(d_mem + (size_t)row*WW);
    float4 v = p[lane];
    float s = v.x*v.x + v.y*v.y + v.z*v.z + v.w*v.w;
    #pragma unroll
    for (int o=16;o;o>>=1) s += __shfl_xor_sync(0xffffffffu, s, o);
    if (!lane) d_meminv[row] = 1.f / fmaxf(sqrtf(s), 1e-12f);
}

// ---------------- LSTM gate GEMM: g[128,4096] = [x_t|rv|h] @ [Wih|Whh]^T + b ----------------
__global__ void k_lstm(const float* __restrict__ x, const float* __restrict__ Wih,
                       const float* __restrict__ Whh, const float* __restrict__ bih,
                       const float* __restrict__ bhh, int t){
    __shared__ float As[16][68];
    __shared__ float Bs[16][68];
    int n0 = blockIdx.x*64, m0 = blockIdx.y*64;
    int tid = threadIdx.x;
    int tx = tid & 15, ty = tid >> 4;
    int lk = tid & 15, lm = tid >> 4;
    float acc[4][4] = {};
    for (int k0 = 0; k0 < 1664; k0 += 16){
        #pragma unroll
        for (int p=0;p<4;p++){
            int m = lm + p*16;
            int b = m0 + m;
            int k = k0 + lk;
            float v;
            if (k < 512)      v = x[((size_t)b*SS + t)*INSZ + k];
            else if (k < 640) v = d_rv[b*WW + (k-512)];
            else              v = d_h[b*HH + (k-640)];
            As[lk][m] = v;
        }
        #pragma unroll
        for (int p=0;p<4;p++){
            int n = lm + p*16;
            int j = n0 + n;
            int k = k0 + lk;
            Bs[lk][n] = (k < 640) ? Wih[(size_t)j*640 + k] : Whh[(size_t)j*1024 + (k-640)];
        }
        __syncthreads();
        #pragma unroll
        for (int kk=0;kk<16;kk++){
            float a[4], bv[4];
            #pragma unroll
            for (int i=0;i<4;i++) a[i]  = As[kk][ty*4+i];
            #pragma unroll
            for (int j=0;j<4;j++) bv[j] = Bs[kk][tx*4+j];
            #pragma unroll
            for (int i=0;i<4;i++)
                #pragma unroll
                for (int j=0;j<4;j++) acc[i][j] += a[i]*bv[j];
        }
        __syncthreads();
    }
    #pragma unroll
    for (int i=0;i<4;i++){
        int m = m0 + ty*4 + i;
        #pragma unroll
        for (int j=0;j<4;j++){
            int n = n0 + tx*4 + j;
            d_g[(size_t)m*G4 + n] = acc[i][j] + bih[n] + bhh[n];
        }
    }
}

// ---------------- LSTM elementwise gates ----------------
__global__ void k_gates(){
    int i = blockIdx.x*256 + threadIdx.x;   // b*1024+u
    int b = i >> 10, u = i & 1023;
    const float* gb = d_g + (size_t)b*G4;
    float gi = gb[u], gf = gb[1024+u], gg = gb[2048+u], go = gb[3072+u];
    float c = sigmoidf_(gf)*d_c[i] + sigmoidf_(gi)*tanhf(gg);
    float h = sigmoidf_(go)*tanhf(c);
    d_c[i] = c; d_h[i] = h;
}

// ---------------- co = h @ Wout^T + bout ----------------
__global__ void k_co(const float* __restrict__ Wout, const float* __restrict__ bout){
    __shared__ float As[32][33];
    __shared__ float Bs[32][33];
    int n0 = blockIdx.x*32, m0 = blockIdx.y*32;
    int tid = threadIdx.x, tx = tid & 15, ty = tid >> 4;
    int lk = tid & 31, lr = tid >> 5;
    float acc[2][2] = {};
    for (int k0 = 0; k0 < HH; k0 += 32){
        #pragma unroll
        for (int p=0;p<4;p++){
            int m = lr + p*8;
            As[lk][m] = d_h[(size_t)(m0+m)*HH + k0 + lk];
            int n = lr + p*8;
            Bs[lk][n] = (n0+n < CC) ? Wout[(size_t)(n0+n)*HH + k0 + lk] : 0.f;
        }
        __syncthreads();
        #pragma unroll
        for (int kk=0;kk<32;kk++){
            float a0 = As[kk][ty*2], a1 = As[kk][ty*2+1];
            float b0 = Bs[kk][tx*2], b1 = Bs[kk][tx*2+1];
            acc[0][0]+=a0*b0; acc[0][1]+=a0*b1; acc[1][0]+=a1*b0; acc[1][1]+=a1*b1;
        }
        __syncthreads();
    }
    #pragma unroll
    for (int i=0;i<2;i++)
        #pragma unroll
        for (int j=0;j<2;j++){
            int m = m0 + ty*2+i, n = n0 + tx*2+j;
            if (n < CC) d_co[(size_t)m*COLD + n] = acc[i][j] + bout[n];
        }
}

// ---------------- all projections from co ----------------
// grid.x segments: 0-3 rkey | 4-7 wkey | 8-11 er(sig) | 12-15 ad(tanh) |
//                  16-31 out (pW, K=512) | 32 scalar heads
__global__ void k_projall(const float* __restrict__ rkW, const float* __restrict__ rkb,
                          const float* __restrict__ wkW, const float* __restrict__ wkb,
                          const float* __restrict__ erW, const float* __restrict__ erb,
                          const float* __restrict__ adW, const float* __restrict__ adb,
                          const float* __restrict__ rbW, const float* __restrict__ rbb,
                          const float* __restrict__ rgW, const float* __restrict__ rgb,
                          const float* __restrict__ wbW, const float* __restrict__ wbb,
                          const float* __restrict__ wgW, const float* __restrict__ wgb,
                          const float* __restrict__ pW,  const float* __restrict__ pb,
                          float* __restrict__ out, int t){
    int s  = blockIdx.x;
    int m0 = blockIdx.y*32;
    int tid = threadIdx.x;

    if (s == 32){   // scalar heads: rbeta, rgamma, wbeta, wgamma
        __shared__ float ws[4][900];
        for (int k = tid; k < CC; k += 256){
            ws[0][k]=rbW[k]; ws[1][k]=rgW[k]; ws[2][k]=wbW[k]; ws[3][k]=wgW[k];
        }
        __syncthreads();
        if (tid < 128){
            int b = m0 + (tid >> 2);
            int j = tid & 3;
            const float* crow = d_co + (size_t)b*COLD;
            float acc = 0.f;
            #pragma unroll 4
            for (int k = 0; k < CC; k++) acc += crow[k]*ws[j][k];
            float bias = (j==0) ? rbb[0] : (j==1) ? rgb[0] : (j==2) ? wbb[0] : wgb[0];
            float v = softplusf_(acc + bias);
            if (j & 1) v += 1.f;   // gamma = 1 + softplus
            d_scal[b*4 + j] = v;
        }
        return;
    }

    const float* Wseg; const float* bias; float* Cp; int ldc, Kseg, act, n0;
    if (s < 16){
        int head = s >> 2;
        n0 = (s & 3)*32;  Kseg = CC;
        if      (head==0){ Wseg=rkW; bias=rkb; Cp=d_keys;     ldc=256; act=0; }
        else if (head==1){ Wseg=wkW; bias=wkb; Cp=d_keys+128; ldc=256; act=0; }
        else if (head==2){ Wseg=erW; bias=erb; Cp=d_erad;     ldc=256; act=1; }
        else             { Wseg=adW; bias=adb; Cp=d_erad+128; ldc=256; act=2; }
    } else {
        n0 = (s-16)*32; Kseg = OUTSZ; Wseg = pW; bias = pb;
        Cp = out + (size_t)t*OUTSZ; ldc = SS*OUTSZ; act = 0;
    }

    __shared__ float As[32][33];
    __shared__ float Bs[32][33];
    int tx = tid & 15, ty = tid >> 4;
    int lk = tid & 31, lr = tid >> 5;
    float acc[2][2] = {};
    for (int k0 = 0; k0 < Kseg; k0 += 32){
        #pragma unroll
        for (int p=0;p<4;p++){
            int m = lr + p*8;
            int k = k0 + lk;
            As[lk][m] = (k < Kseg) ? d_co[(size_t)(m0+m)*COLD + k] : 0.f;
            int n = lr + p*8;
            Bs[lk][n] = (k < Kseg) ? Wseg[(size_t)(n0+n)*Kseg + k] : 0.f;
        }
        __syncthreads();
        #pragma unroll
        for (int kk=0;kk<32;kk++){
            float a0 = As[kk][ty*2], a1 = As[kk][ty*2+1];
            float b0 = Bs[kk][tx*2], b1 = Bs[kk][tx*2+1];
            acc[0][0]+=a0*b0; acc[0][1]+=a0*b1; acc[1][0]+=a1*b0; acc[1][1]+=a1*b1;
        }
        __syncthreads();
    }
    #pragma unroll
    for (int i=0;i<2;i++)
        #pragma unroll
        for (int j=0;j<2;j++){
            int m = m0 + ty*2+i, n = n0 + tx*2+j;
            float v = acc[i][j] + bias[n];
            if (act==1) v = sigmoidf_(v);
            else if (act==2) v = tanhf(v);
            Cp[(size_t)m*ldc + n] = v;
        }
}

// ---------------- similarity GEMM: sim[256,16384] = norm(keys) @ norm(mem)^T ----------------
__global__ void k_sim(){
    extern __shared__ float smem_dyn[];
    float (*As)[68] = (float (*)[68])smem_dyn;            // [128k][64m]
    float (*Bs)[68] = (float (*)[68])(smem_dyn + 128*68); // [128k][64n]
    __shared__ float minv[64], rinv[64];
    __shared__ float red[64][17];

    int nt = blockIdx.x, mt = blockIdx.y;
    int n0 = nt*64, m0 = mt*64;
    int tid = threadIdx.x;
    int kx = tid & 127, half = tid >> 7;

    if (tid < 64) minv[tid] = d_meminv[n0 + tid];
    __syncthreads();

    #pragma unroll
    for (int p=0;p<32;p++){
        int mloc = half + p*2;
        int r = m0 + mloc;
        As[kx][mloc] = d_keys[(r & 127)*256 + (r >> 7)*128 + kx];
        int nloc = half + p*2;
        Bs[kx][nloc] = d_mem[(size_t)(n0+nloc)*WW + kx] * minv[nloc];
    }
    __syncthreads();
    if (tid < 64){
        float ss = 0.f;
        #pragma unroll 4
        for (int k=0;k<128;k++){ float v = As[k][tid]; ss += v*v; }
        rinv[tid] = 1.f / fmaxf(sqrtf(ss), 1e-12f);
    }
    __syncthreads();
    #pragma unroll
    for (int p=0;p<32;p++){
        int mloc = half + p*2;
        As[kx][mloc] *= rinv[mloc];
    }
    __syncthreads();

    int tx = tid & 15, ty = tid >> 4;
    float acc[4][4] = {};
    #pragma unroll 4
    for (int k=0;k<128;k++){
        float4 a = *(const float4*)&As[k][ty*4];
        float4 b = *(const float4*)&Bs[k][tx*4];
        acc[0][0]+=a.x*b.x; acc[0][1]+=a.x*b.y; acc[0][2]+=a.x*b.z; acc[0][3]+=a.x*b.w;
        acc[1][0]+=a.y*b.x; acc[1][1]+=a.y*b.y; acc[1][2]+=a.y*b.z; acc[1][3]+=a.y*b.w;
        acc[2][0]+=a.z*b.x; acc[2][1]+=a.z*b.y; acc[2][2]+=a.z*b.z; acc[2][3]+=a.z*b.w;
        acc[3][0]+=a.w*b.x; acc[3][1]+=a.w*b.y; acc[3][2]+=a.w*b.z; acc[3][3]+=a.w*b.w;
    }
    #pragma unroll
    for (int i=0;i<4;i++){
        int r = m0 + ty*4 + i;
        float4 v = make_float4(acc[i][0], acc[i][1], acc[i][2], acc[i][3]);
        *(float4*)&d_sim[(size_t)r*NN + n0 + tx*4] = v;
        float mx = fmaxf(fmaxf(acc[i][0],acc[i][1]), fmaxf(acc[i][2],acc[i][3]));
        red[ty*4+i][tx] = mx;
    }
    __syncthreads();
    if (tid < 64){
        float mx = red[tid][0];
        #pragma unroll
        for (int q=1;q<16;q++) mx = fmaxf(mx, red[tid][q]);
        d_pmax[(size_t)(m0+tid)*NTSIM + nt] = mx;
    }
}

// ---------------- softmax + interpolation → rw / ww ----------------
__global__ void k_smax(){
    extern __shared__ float esm[];       // 16384 exp values
    __shared__ float red[256];
    int r = blockIdx.x;
    int head = r >> 7, b = r & 127;
    float beta  = d_scal[b*4 + head*2];
    float gamma = d_scal[b*4 + head*2 + 1];
    int tid = threadIdx.x;

    red[tid] = d_pmax[(size_t)r*NTSIM + tid];
    __syncthreads();
    for (int o=128;o;o>>=1){ if (tid<o) red[tid] = fmaxf(red[tid], red[tid+o]); __syncthreads(); }
    float m = red[0];
    __syncthreads();

    const float* simrow = d_sim + (size_t)r*NN;
    float s = 0.f;
    for (int n = tid; n < NN; n += 256){
        float e = __expf(beta*(simrow[n] - m));
        esm[n] = e; s += e;
    }
    red[tid] = s; __syncthreads();
    for (int o=128;o;o>>=1){ if (tid<o) red[tid] += red[tid+o]; __syncthreads(); }
    float inv = 1.f / red[0];

    if (head == 0){
        float* rw = d_rw + (size_t)b*NN;
        for (int n = tid; n < NN; n += 256){
            float w = esm[n]*inv;
            rw[n] = gamma*w + (1.f-gamma)*rw[n];
        }
    } else {
        float* ww = d_ww + (size_t)b*NN;
        const float u = 1.f/NN;
        for (int n = tid; n < NN; n += 256){
            float w = esm[n]*inv;
            ww[n] = gamma*w + (1.f-gamma)*u;
        }
    }
}

// ---------------- memory update: mem = mem*(1-ww^T er) + ww^T ad, + row norms ----------------
__global__ void k_memupd(){
    __shared__ float wws[16][36];
    __shared__ float ers[16][132];
    __shared__ float ads[16][132];
    __shared__ float red[32][17];
    int n0 = blockIdx.x*32;
    int tid = threadIdx.x, tx = tid & 15, ty = tid >> 4;
    float ae[2][8] = {}, aa[2][8] = {};
    for (int b0 = 0; b0 < BB; b0 += 16){
        #pragma unroll
        for (int p=0;p<2;p++){
            int bb = (tid>>5) + p*8;
            int n  = tid & 31;
            wws[bb][n] = d_ww[(size_t)(b0+bb)*NN + n0 + n];
        }
        #pragma unroll
        for (int p=0;p<8;p++){
            int bb = (tid>>7) + p*2;
            int w  = tid & 127;
            ers[bb][w] = d_erad[(b0+bb)*256 + w];
            ads[bb][w] = d_erad[(b0+bb)*256 + 128 + w];
        }
        __syncthreads();
        #pragma unroll
        for (int kk=0;kk<16;kk++){
            float a0 = wws[kk][ty*2], a1 = wws[kk][ty*2+1];
            float4 e0 = *(const float4*)&ers[kk][tx*8];
            float4 e1 = *(const float4*)&ers[kk][tx*8+4];
            float4 d0 = *(const float4*)&ads[kk][tx*8];
            float4 d1 = *(const float4*)&ads[kk][tx*8+4];
            float ev[8] = {e0.x,e0.y,e0.z,e0.w,e1.x,e1.y,e1.z,e1.w};
            float dv[8] = {d0.x,d0.y,d0.z,d0.w,d1.x,d1.y,d1.z,d1.w};
            #pragma unroll
            for (int j=0;j<8;j++){
                ae[0][j]+=a0*ev[j]; ae[1][j]+=a1*ev[j];
                aa[0][j]+=a0*dv[j]; aa[1][j]+=a1*dv[j];
            }
        }
        __syncthreads();
    }
    float sq[2] = {0.f, 0.f};
    #pragma unroll
    for (int i=0;i<2;i++){
        int n = n0 + ty*2 + i;
        float* mrow = d_mem + (size_t)n*WW;
        #pragma unroll
        for (int j=0;j<8;j++){
            int w = tx*8 + j;
            float v = mrow[w]*(1.f - ae[i][j]) + aa[i][j];
            mrow[w] = v;
            sq[i] += v*v;
        }
    }
    red[ty*2][tx] = sq[0]; red[ty*2+1][tx] = sq[1];
    __syncthreads();
    if (tid < 32){
        float s = red[tid][0];
        #pragma unroll
        for (int q=1;q<16;q++) s += red[tid][q];
        d_meminv[n0 + tid] = 1.f / fmaxf(sqrtf(s), 1e-12f);
    }
}

// ---------------- rv = rw @ mem (split-K) ----------------
__global__ void k_rv(){
    __shared__ float As[8][132];  // [kk][b]
    __shared__ float Bs[8][132];  // [kk][w]
    int s = blockIdx.x;
    int n0 = s*128;
    int tid = threadIdx.x, tx = tid & 15, ty = tid >> 4;
    float acc[8][8] = {};
    for (int k0 = 0; k0 < 128; k0 += 8){
        #pragma unroll
        for (int p=0;p<4;p++){
            int b  = (tid>>3) + p*32;
            int kk = tid & 7;
            As[kk][b] = d_rw[(size_t)b*NN + n0 + k0 + kk];
        }
        #pragma unroll
        for (int p=0;p<4;p++){
            int kk = (tid>>7) + p*2;
            int w  = tid & 127;
            Bs[kk][w] = d_mem[(size_t)(n0+k0+kk)*WW + w];
        }
        __syncthreads();
        #pragma unroll
        for (int kk=0;kk<8;kk++){
            float4 a0 = *(const float4*)&As[kk][ty*8];
            float4 a1 = *(const float4*)&As[kk][ty*8+4];
            float4 b0 = *(const float4*)&Bs[kk][tx*8];
            float4 b1 = *(const float4*)&Bs[kk][tx*8+4];
            float av[8] = {a0.x,a0.y,a0.z,a0.w,a1.x,a1.y,a1.z,a1.w};
            float bv[8] = {b0.x,b0.y,b0.z,b0.w,b1.x,b1.y,b1.z,b1.w};
            #pragma unroll
            for (int i=0;i<8;i++)
                #pragma unroll
                for (int j=0;j<8;j++) acc[i][j] += av[i]*bv[j];
        }
        __syncthreads();
    }
    #pragma unroll
    for (int i=0;i<8;i++){
        int b = ty*8+i;
        #pragma unroll
        for (int j=0;j<8;j+=4){
            float4 v = make_float4(acc[i][j],acc[i][j+1],acc[i][j+2],acc[i][j+3]);
            *(float4*)&d_rvpart[((size_t)s*BB + b)*WW + tx*8 + j] = v;
        }
    }
}

__global__ void k_rvred(){
    int i = blockIdx.x*256 + threadIdx.x;   // 16384 outputs
    float s = 0.f;
    for (int p=0;p<128;p++) s += d_rvpart[(size_t)p*16384 + i];
    d_rv[i] = s;
}

// ---------------- launch ----------------
extern "C" void kernel_launch(void* const* d_in, const int* in_sizes, int n_in,
                              void* d_out, int out_size){
    const float* x      = (const float*)d_in[0];
    const float* memory = (const float*)d_in[1];
    const float* Wih    = (const float*)d_in[2];
    const float* Whh    = (const float*)d_in[3];
    const float* bih    = (const float*)d_in[4];
    const float* bhh    = (const float*)d_in[5];
    const float* Wout   = (const float*)d_in[6];
    const float* bout   = (const float*)d_in[7];
    const float* rkW    = (const float*)d_in[8];
    const float* rkb    = (const float*)d_in[9];
    const float* rbW    = (const float*)d_in[10];
    const float* rbb    = (const float*)d_in[11];
    const float* rgW    = (const float*)d_in[12];
    const float* rgb    = (const float*)d_in[13];
    const float* wkW    = (const float*)d_in[14];
    const float* wkb    = (const float*)d_in[15];
    const float* wbW    = (const float*)d_in[16];
    const float* wbb    = (const float*)d_in[17];
    const float* wgW    = (const float*)d_in[18];
    const float* wgb    = (const float*)d_in[19];
    const float* erW    = (const float*)d_in[20];
    const float* erb    = (const float*)d_in[21];
    const float* adW    = (const float*)d_in[22];
    const float* adb    = (const float*)d_in[23];
    const float* pW     = (const float*)d_in[24];
    const float* pb     = (const float*)d_in[25];
    float* out = (float*)d_out;

    const int SIM_SMEM = 2*128*68*4;   // 69632
    cudaFuncSetAttribute(k_sim,  cudaFuncAttributeMaxDynamicSharedMemorySize, SIM_SMEM);
    cudaFuncSetAttribute(k_smax, cudaFuncAttributeMaxDynamicSharedMemorySize, 65536);

    k_init<<<8192, 256>>>(memory);
    k_rownorm<<<2048, 256>>>();
    for (int t = 0; t < SS; t++){
        k_lstm<<<dim3(64,2), 256>>>(x, Wih, Whh, bih, bhh, t);
        k_gates<<<512, 256>>>();
        k_co<<<dim3(29,4), 256>>>(Wout, bout);
        k_projall<<<dim3(33,4), 256>>>(rkW,rkb,wkW,wkb,erW,erb,adW,adb,
                                       rbW,rbb,rgW,rgb,wbW,wbb,wgW,wgb,
                                       pW,pb,out,t);
        if (t + 1 < SS){   // addressing/memory pipeline only feeds future steps
            k_sim<<<dim3(NTSIM,4), 256, SIM_SMEM>>>();
            k_smax<<<256, 256, 65536>>>();
            k_memupd<<<512, 256>>>();
            k_rv<<<128, 256>>>();
            k_rvred<<<64, 256>>>();
        }
    }
}

// round 5
// speedup vs baseline: 1.1468x; 1.1468x over previous
#include <cuda_runtime.h>
#include <cuda_bf16.h>
#include <cstdint>
#include <stdint.h>
#include <math.h>

#define BB    128
#define SS    32
#define INSZ  512
#define HH    1024
#define OUTSZ 512
#define NN    16384
#define WW    128
#define CC    899
#define G4    4096
#define COLD  904
#define NTSIM 128      // sim n-tiles of 128

// ================= warp-level bf16 MMA =================
#define MMA16816(c, a, b) \
    asm volatile("mma.sync.aligned.m16n8k16.row.col.f32.bf16.bf16.f32 " \
        "{%0,%1,%2,%3}, {%4,%5,%6,%7}, {%8,%9}, {%0,%1,%2,%3};" \
        : "+f"((c)[0]), "+f"((c)[1]), "+f"((c)[2]), "+f"((c)[3]) \
        : "r"((a)[0]), "r"((a)[1]), "r"((a)[2]), "r"((a)[3]), "r"((b)[0]), "r"((b)[1]))

// load 128 rows x 64 cols bf16 into smem [128][72]
__device__ __forceinline__ void load_chunk(__nv_bfloat16* sm, const __nv_bfloat16* src,
                                           size_t ld, int tid){
    #pragma unroll
    for (int i=0;i<4;i++){
        int idx = tid + i*256;          // 1024 uint4
        int row = idx >> 3, c4 = idx & 7;
        *(uint4*)(sm + row*72 + c4*8) = *(const uint4*)(src + (size_t)row*ld + c4*8);
    }
}

// one 64-wide K chunk: CTA tile 128x128, 8 warps as 4(m) x 2(n); warp = 32m x 64n
__device__ __forceinline__ void mma_chunk(const __nv_bfloat16* As, const __nv_bfloat16* Bs,
                                          float cacc[2][8][4], int wm, int wn, int g, int t){
    #pragma unroll
    for (int ks=0;ks<4;ks++){
        int k = ks*16;
        uint32_t afr[2][4], bfr[8][2];
        #pragma unroll
        for (int mi=0;mi<2;mi++){
            const __nv_bfloat16* ap = As + (wm*32 + mi*16)*72 + k + 2*t;
            afr[mi][0] = *(const uint32_t*)(ap + g*72);
            afr[mi][1] = *(const uint32_t*)(ap + (g+8)*72);
            afr[mi][2] = *(const uint32_t*)(ap + g*72 + 8);
            afr[mi][3] = *(const uint32_t*)(ap + (g+8)*72 + 8);
        }
        #pragma unroll
        for (int nj=0;nj<8;nj++){
            const __nv_bfloat16* bp = Bs + (wn*64 + nj*8 + g)*72 + k + 2*t;
            bfr[nj][0] = *(const uint32_t*)(bp);
            bfr[nj][1] = *(const uint32_t*)(bp + 8);
        }
        #pragma unroll
        for (int mi=0;mi<2;mi++)
            #pragma unroll
            for (int nj=0;nj<8;nj++)
                MMA16816(cacc[mi][nj], afr[mi], bfr[nj]);
    }
}

// ================= device state =================
__device__ float d_mem[NN * WW];
__device__ __nv_bfloat16 d_memn[NN * WW];        // normalized rows bf16
__device__ __nv_bfloat16 d_memTb[WW * NN];       // mem^T raw bf16
__device__ float d_h[BB * HH];
__device__ float d_c[BB * HH];
__device__ float d_g[BB * G4];
__device__ float d_co[BB * COLD];
__device__ float d_keys[BB * 2 * WW];
__device__ __nv_bfloat16 d_keysn[256 * WW];      // normalized keys (r = head*128+b)
__device__ float d_erad[BB * 2 * WW];
__device__ __nv_bfloat16 d_eradT[256 * BB];      // [er(128)|ad(128)][b]
__device__ float d_scal[BB * 4];
__device__ float d_sim[256 * NN];
__device__ float d_pmax[256 * NTSIM];
__device__ float d_rw[BB * NN];
__device__ __nv_bfloat16 d_rwb[BB * NN];
__device__ __nv_bfloat16 d_wwT[NN * BB];
__device__ float d_rv[BB * WW];
__device__ float d_rvpart[8 * BB * WW];

__device__ __forceinline__ float sigmoidf_(float x){ return 1.f/(1.f+__expf(-x)); }
__device__ __forceinline__ float softplusf_(float x){ return x>15.f ? x : log1pf(__expf(x)); }

// ================= init =================
__global__ void k_init(const float* __restrict__ memory){
    int i = blockIdx.x*256 + threadIdx.x;
    d_mem[i] = memory[i];
    d_rw[i]  = 1.0f/NN;
    if (i < BB*HH){ d_h[i]=0.f; d_c[i]=0.f; }
    if (i < BB*WW) d_rv[i] = 0.f;
}

__global__ void k_rownorm(){
    int row  = blockIdx.x*8 + (threadIdx.x>>5);
    int lane = threadIdx.x & 31;
    const float4* p = (const float4*)(d_mem + (size_t)row*WW);
    float4 v = p[lane];
    float s = v.x*v.x + v.y*v.y + v.z*v.z + v.w*v.w;
    #pragma unroll
    for (int o=16;o;o>>=1) s += __shfl_xor_sync(0xffffffffu, s, o);
    s = __shfl_sync(0xffffffffu, s, 0);
    float inv = 1.f / fmaxf(sqrtf(s), 1e-12f);
    __nv_bfloat162* nm = (__nv_bfloat162*)(d_memn + (size_t)row*WW + lane*4);
    nm[0] = __floats2bfloat162_rn(v.x*inv, v.y*inv);
    nm[1] = __floats2bfloat162_rn(v.z*inv, v.w*inv);
    float vv[4] = {v.x, v.y, v.z, v.w};
    #pragma unroll
    for (int j=0;j<4;j++) d_memTb[(size_t)(lane*4+j)*NN + row] = __float2bfloat16(vv[j]);
}

// ================= LSTM (fp32 SIMT) =================
__global__ void k_lstm(const float* __restrict__ x, const float* __restrict__ Wih,
                       const float* __restrict__ Whh, const float* __restrict__ bih,
                       const float* __restrict__ bhh, int t){
    __shared__ float As[16][68];
    __shared__ float Bs[16][68];
    int n0 = blockIdx.x*64, m0 = blockIdx.y*64;
    int tid = threadIdx.x;
    int tx = tid & 15, ty = tid >> 4;
    int lk = tid & 15, lm = tid >> 4;
    float acc[4][4] = {};
    for (int k0 = 0; k0 < 1664; k0 += 16){
        #pragma unroll
        for (int p=0;p<4;p++){
            int m = lm + p*16;
            int b = m0 + m;
            int k = k0 + lk;
            float v;
            if (k < 512)      v = x[((size_t)b*SS + t)*INSZ + k];
            else if (k < 640) v = d_rv[b*WW + (k-512)];
            else              v = d_h[b*HH + (k-640)];
            As[lk][m] = v;
        }
        #pragma unroll
        for (int p=0;p<4;p++){
            int n = lm + p*16;
            int j = n0 + n;
            int k = k0 + lk;
            Bs[lk][n] = (k < 640) ? Wih[(size_t)j*640 + k] : Whh[(size_t)j*1024 + (k-640)];
        }
        __syncthreads();
        #pragma unroll
        for (int kk=0;kk<16;kk++){
            float a[4], bv[4];
            #pragma unroll
            for (int i=0;i<4;i++) a[i]  = As[kk][ty*4+i];
            #pragma unroll
            for (int j=0;j<4;j++) bv[j] = Bs[kk][tx*4+j];
            #pragma unroll
            for (int i=0;i<4;i++)
                #pragma unroll
                for (int j=0;j<4;j++) acc[i][j] += a[i]*bv[j];
        }
        __syncthreads();
    }
    #pragma unroll
    for (int i=0;i<4;i++){
        int m = m0 + ty*4 + i;
        #pragma unroll
        for (int j=0;j<4;j++){
            int n = n0 + tx*4 + j;
            d_g[(size_t)m*G4 + n] = acc[i][j] + bih[n] + bhh[n];
        }
    }
}

__global__ void k_gates(){
    int i = blockIdx.x*256 + threadIdx.x;
    int b = i >> 10, u = i & 1023;
    const float* gb = d_g + (size_t)b*G4;
    float gi = gb[u], gf = gb[1024+u], gg = gb[2048+u], go = gb[3072+u];
    float c = sigmoidf_(gf)*d_c[i] + sigmoidf_(gi)*tanhf(gg);
    float h = sigmoidf_(go)*tanhf(c);
    d_c[i] = c; d_h[i] = h;
}

__global__ void k_co(const float* __restrict__ Wout, const float* __restrict__ bout){
    __shared__ float As[32][33];
    __shared__ float Bs[32][33];
    int n0 = blockIdx.x*32, m0 = blockIdx.y*32;
    int tid = threadIdx.x, tx = tid & 15, ty = tid >> 4;
    int lk = tid & 31, lr = tid >> 5;
    float acc[2][2] = {};
    for (int k0 = 0; k0 < HH; k0 += 32){
        #pragma unroll
        for (int p=0;p<4;p++){
            int m = lr + p*8;
            As[lk][m] = d_h[(size_t)(m0+m)*HH + k0 + lk];
            int n = lr + p*8;
            Bs[lk][n] = (n0+n < CC) ? Wout[(size_t)(n0+n)*HH + k0 + lk] : 0.f;
        }
        __syncthreads();
        #pragma unroll
        for (int kk=0;kk<32;kk++){
            float a0 = As[kk][ty*2], a1 = As[kk][ty*2+1];
            float b0 = Bs[kk][tx*2], b1 = Bs[kk][tx*2+1];
            acc[0][0]+=a0*b0; acc[0][1]+=a0*b1; acc[1][0]+=a1*b0; acc[1][1]+=a1*b1;
        }
        __syncthreads();
    }
    #pragma unroll
    for (int i=0;i<2;i++)
        #pragma unroll
        for (int j=0;j<2;j++){
            int m = m0 + ty*2+i, n = n0 + tx*2+j;
            if (n < CC) d_co[(size_t)m*COLD + n] = acc[i][j] + bout[n];
        }
}

// ================= projections =================
__global__ void k_projall(const float* __restrict__ rkW, const float* __restrict__ rkb,
                          const float* __restrict__ wkW, const float* __restrict__ wkb,
                          const float* __restrict__ erW, const float* __restrict__ erb,
                          const float* __restrict__ adW, const float* __restrict__ adb,
                          const float* __restrict__ rbW, const float* __restrict__ rbb,
                          const float* __restrict__ rgW, const float* __restrict__ rgb,
                          const float* __restrict__ wbW, const float* __restrict__ wbb,
                          const float* __restrict__ wgW, const float* __restrict__ wgb,
                          const float* __restrict__ pW,  const float* __restrict__ pb,
                          float* __restrict__ out, int t){
    int s  = blockIdx.x;
    int m0 = blockIdx.y*32;
    int tid = threadIdx.x;

    if (s == 32){
        __shared__ float ws[4][900];
        for (int k = tid; k < CC; k += 256){
            ws[0][k]=rbW[k]; ws[1][k]=rgW[k]; ws[2][k]=wbW[k]; ws[3][k]=wgW[k];
        }
        __syncthreads();
        if (tid < 128){
            int b = m0 + (tid >> 2);
            int j = tid & 3;
            const float* crow = d_co + (size_t)b*COLD;
            float acc = 0.f;
            #pragma unroll 4
            for (int k = 0; k < CC; k++) acc += crow[k]*ws[j][k];
            float bias = (j==0) ? rbb[0] : (j==1) ? rgb[0] : (j==2) ? wbb[0] : wgb[0];
            float v = softplusf_(acc + bias);
            if (j & 1) v += 1.f;
            d_scal[b*4 + j] = v;
        }
        return;
    }

    const float* Wseg; const float* bias; float* Cp; int ldc, Kseg, act, n0, head = -1;
    if (s < 16){
        head = s >> 2;
        n0 = (s & 3)*32;  Kseg = CC;
        if      (head==0){ Wseg=rkW; bias=rkb; Cp=d_keys;     ldc=256; act=0; }
        else if (head==1){ Wseg=wkW; bias=wkb; Cp=d_keys+128; ldc=256; act=0; }
        else if (head==2){ Wseg=erW; bias=erb; Cp=d_erad;     ldc=256; act=1; }
        else             { Wseg=adW; bias=adb; Cp=d_erad+128; ldc=256; act=2; }
    } else {
        n0 = (s-16)*32; Kseg = OUTSZ; Wseg = pW; bias = pb;
        Cp = out + (size_t)t*OUTSZ; ldc = SS*OUTSZ; act = 0;
    }

    __shared__ float As[32][33];
    __shared__ float Bs[32][33];
    int tx = tid & 15, ty = tid >> 4;
    int lk = tid & 31, lr = tid >> 5;
    float acc[2][2] = {};
    for (int k0 = 0; k0 < Kseg; k0 += 32){
        #pragma unroll
        for (int p=0;p<4;p++){
            int m = lr + p*8;
            int k = k0 + lk;
            As[lk][m] = (k < Kseg) ? d_co[(size_t)(m0+m)*COLD + k] : 0.f;
            int n = lr + p*8;
            Bs[lk][n] = (k < Kseg) ? Wseg[(size_t)(n0+n)*Kseg + k] : 0.f;
        }
        __syncthreads();
        #pragma unroll
        for (int kk=0;kk<32;kk++){
            float a0 = As[kk][ty*2], a1 = As[kk][ty*2+1];
            float b0 = Bs[kk][tx*2], b1 = Bs[kk][tx*2+1];
            acc[0][0]+=a0*b0; acc[0][1]+=a0*b1; acc[1][0]+=a1*b0; acc[1][1]+=a1*b1;
        }
        __syncthreads();
    }
    #pragma unroll
    for (int i=0;i<2;i++)
        #pragma unroll
        for (int j=0;j<2;j++){
            int m = m0 + ty*2+i, n = n0 + tx*2+j;
            float v = acc[i][j] + bias[n];
            if (act==1) v = sigmoidf_(v);
            else if (act==2) v = tanhf(v);
            Cp[(size_t)m*ldc + n] = v;
            if (head >= 2){
                int rrow = (head==2 ? 0 : 128) + n;
                d_eradT[rrow*BB + m] = __float2bfloat16(v);
            }
        }
}

// normalize keys -> bf16 (row r = head*128 + b)
__global__ void k_keysnorm(){
    int row  = blockIdx.x*8 + (threadIdx.x>>5);
    int lane = threadIdx.x & 31;
    int head = row >> 7, b = row & 127;
    const float4* p = (const float4*)(d_keys + b*256 + head*128);
    float4 v = p[lane];
    float s = v.x*v.x + v.y*v.y + v.z*v.z + v.w*v.w;
    #pragma unroll
    for (int o=16;o;o>>=1) s += __shfl_xor_sync(0xffffffffu, s, o);
    s = __shfl_sync(0xffffffffu, s, 0);
    float inv = 1.f / fmaxf(sqrtf(s), 1e-12f);
    __nv_bfloat162* kn = (__nv_bfloat162*)(d_keysn + (size_t)row*WW + lane*4);
    kn[0] = __floats2bfloat162_rn(v.x*inv, v.y*inv);
    kn[1] = __floats2bfloat162_rn(v.z*inv, v.w*inv);
}

// ================= sim: [256 x 16384] = keysn @ memn^T =================
__global__ void __launch_bounds__(256) k_simT(){
    extern __shared__ __nv_bfloat16 smb[];
    __nv_bfloat16* As = smb;              // [128][72]
    __nv_bfloat16* Bs = smb + 128*72;
    __shared__ float redm[128][2];
    int tid = threadIdx.x, lane = tid & 31, wid = tid >> 5;
    int wm = wid >> 1, wn = wid & 1, g = lane >> 2, t = lane & 3;
    int m0 = blockIdx.y*128, n0 = blockIdx.x*128;

    float cacc[2][8][4] = {};
    #pragma unroll
    for (int kc=0;kc<2;kc++){
        load_chunk(As, d_keysn + (size_t)m0*WW + kc*64, WW, tid);
        load_chunk(Bs, d_memn  + (size_t)n0*WW + kc*64, WW, tid);
        __syncthreads();
        mma_chunk(As, Bs, cacc, wm, wn, g, t);
        __syncthreads();
    }
    #pragma unroll
    for (int mi=0;mi<2;mi++){
        int rl0 = wm*32 + mi*16 + g, rl1 = rl0 + 8;
        float mx0 = -3.0e38f, mx1 = -3.0e38f;
        #pragma unroll
        for (int nj=0;nj<8;nj++){
            int col = n0 + wn*64 + nj*8 + 2*t;
            float c0 = cacc[mi][nj][0], c1 = cacc[mi][nj][1];
            float c2 = cacc[mi][nj][2], c3 = cacc[mi][nj][3];
            *(float2*)&d_sim[(size_t)(m0+rl0)*NN + col] = make_float2(c0, c1);
            *(float2*)&d_sim[(size_t)(m0+rl1)*NN + col] = make_float2(c2, c3);
            mx0 = fmaxf(mx0, fmaxf(c0, c1));
            mx1 = fmaxf(mx1, fmaxf(c2, c3));
        }
        mx0 = fmaxf(mx0, __shfl_xor_sync(0xffffffffu, mx0, 1));
        mx0 = fmaxf(mx0, __shfl_xor_sync(0xffffffffu, mx0, 2));
        mx1 = fmaxf(mx1, __shfl_xor_sync(0xffffffffu, mx1, 1));
        mx1 = fmaxf(mx1, __shfl_xor_sync(0xffffffffu, mx1, 2));
        if (t == 0){ redm[rl0][wn] = mx0; redm[rl1][wn] = mx1; }
    }
    __syncthreads();
    if (tid < 128)
        d_pmax[(size_t)(m0+tid)*NTSIM + blockIdx.x] = fmaxf(redm[tid][0], redm[tid][1]);
}

// ================= softmax + interpolation =================
__global__ void k_smax(){
    extern __shared__ float esm[];
    __shared__ float red[256];
    int r = blockIdx.x;
    int head = r >> 7, b = r & 127;
    float beta  = d_scal[b*4 + head*2];
    float gamma = d_scal[b*4 + head*2 + 1];
    int tid = threadIdx.x;

    red[tid] = (tid < NTSIM) ? d_pmax[(size_t)r*NTSIM + tid] : -3.0e38f;
    __syncthreads();
    for (int o=128;o;o>>=1){ if (tid<o) red[tid] = fmaxf(red[tid], red[tid+o]); __syncthreads(); }
    float m = red[0];
    __syncthreads();

    const float* simrow = d_sim + (size_t)r*NN;
    float s = 0.f;
    for (int n = tid; n < NN; n += 256){
        float e = __expf(beta*(simrow[n] - m));
        esm[n] = e; s += e;
    }
    red[tid] = s; __syncthreads();
    for (int o=128;o;o>>=1){ if (tid<o) red[tid] += red[tid+o]; __syncthreads(); }
    float inv = 1.f / red[0];

    if (head == 0){
        float* rw = d_rw + (size_t)b*NN;
        __nv_bfloat16* rwb = d_rwb + (size_t)b*NN;
        for (int n = tid; n < NN; n += 256){
            float w = esm[n]*inv;
            float v = gamma*w + (1.f-gamma)*rw[n];
            rw[n] = v;
            rwb[n] = __float2bfloat16(v);
        }
    } else {
        const float u = 1.f/NN;
        for (int n = tid; n < NN; n += 256){
            float w = esm[n]*inv;
            float v = gamma*w + (1.f-gamma)*u;
            d_wwT[(size_t)n*BB + b] = __float2bfloat16(v);
        }
    }
}

// ================= memory update =================
// E = wwT_tile @ er^T, A = wwT_tile @ ad^T; mem = mem*(1-E)+A; row norms; bf16 copies
__global__ void __launch_bounds__(256) k_memupdT(){
    extern __shared__ __nv_bfloat16 smb[];
    __nv_bfloat16* As = smb;                       // [128][72]
    __nv_bfloat16* Bs = smb + 128*72;              // [128][72]
    float* Esm = (float*)(smb + 2*128*72);         // [128][132]
    __shared__ float redm[128][2];
    __shared__ float invsm[128];
    int tid = threadIdx.x, lane = tid & 31, wid = tid >> 5;
    int wm = wid >> 1, wn = wid & 1, g = lane >> 2, t = lane & 3;
    int q0 = blockIdx.x*128;

    float cacc[2][8][4] = {};
    #pragma unroll
    for (int ph=0; ph<2; ph++){
        #pragma unroll
        for (int kc=0;kc<2;kc++){
            load_chunk(As, d_wwT + (size_t)q0*BB + kc*64, BB, tid);
            load_chunk(Bs, d_eradT + ph*128*BB + kc*64, BB, tid);
            __syncthreads();
            mma_chunk(As, Bs, cacc, wm, wn, g, t);
            __syncthreads();
        }
        if (ph == 0){
            // stash E (same-thread write/read; no sync needed)
            #pragma unroll
            for (int mi=0;mi<2;mi++){
                int rl0 = wm*32 + mi*16 + g, rl1 = rl0 + 8;
                #pragma unroll
                for (int nj=0;nj<8;nj++){
                    int cl = wn*64 + nj*8 + 2*t;
                    Esm[rl0*132 + cl]   = cacc[mi][nj][0];
                    Esm[rl0*132 + cl+1] = cacc[mi][nj][1];
                    Esm[rl1*132 + cl]   = cacc[mi][nj][2];
                    Esm[rl1*132 + cl+1] = cacc[mi][nj][3];
                    cacc[mi][nj][0]=0.f; cacc[mi][nj][1]=0.f;
                    cacc[mi][nj][2]=0.f; cacc[mi][nj][3]=0.f;
                }
            }
        }
    }
    // v = mem*(1-E) + A  (store v back into cacc), partial row sumsq
    float ssq[2][2] = {};
    #pragma unroll
    for (int mi=0;mi<2;mi++){
        int rl0 = wm*32 + mi*16 + g, rl1 = rl0 + 8;
        #pragma unroll
        for (int nj=0;nj<8;nj++){
            int cl = wn*64 + nj*8 + 2*t;
            float2 m0v = *(const float2*)&d_mem[(size_t)(q0+rl0)*WW + cl];
            float2 m1v = *(const float2*)&d_mem[(size_t)(q0+rl1)*WW + cl];
            float v00 = m0v.x*(1.f - Esm[rl0*132+cl])   + cacc[mi][nj][0];
            float v01 = m0v.y*(1.f - Esm[rl0*132+cl+1]) + cacc[mi][nj][1];
            float v10 = m1v.x*(1.f - Esm[rl1*132+cl])   + cacc[mi][nj][2];
            float v11 = m1v.y*(1.f - Esm[rl1*132+cl+1]) + cacc[mi][nj][3];
            cacc[mi][nj][0]=v00; cacc[mi][nj][1]=v01; cacc[mi][nj][2]=v10; cacc[mi][nj][3]=v11;
            ssq[mi][0] += v00*v00 + v01*v01;
            ssq[mi][1] += v10*v10 + v11*v11;
        }
    }
    #pragma unroll
    for (int mi=0;mi<2;mi++){
        #pragma unroll
        for (int h=0;h<2;h++){
            float s = ssq[mi][h];
            s += __shfl_xor_sync(0xffffffffu, s, 1);
            s += __shfl_xor_sync(0xffffffffu, s, 2);
            if (t == 0) redm[wm*32 + mi*16 + h*8 + g][wn] = s;
        }
    }
    __syncthreads();
    if (tid < 128) invsm[tid] = 1.f / fmaxf(sqrtf(redm[tid][0] + redm[tid][1]), 1e-12f);
    __syncthreads();
    // write mem fp32 + memn bf16; stage transposed bf16 into Vsm
    __nv_bfloat16* Vsm = (__nv_bfloat16*)Esm;      // [128][136]
    #pragma unroll
    for (int mi=0;mi<2;mi++){
        int rl0 = wm*32 + mi*16 + g, rl1 = rl0 + 8;
        float i0 = invsm[rl0], i1 = invsm[rl1];
        #pragma unroll
        for (int nj=0;nj<8;nj++){
            int cl = wn*64 + nj*8 + 2*t;
            float v00=cacc[mi][nj][0], v01=cacc[mi][nj][1], v10=cacc[mi][nj][2], v11=cacc[mi][nj][3];
            *(float2*)&d_mem[(size_t)(q0+rl0)*WW + cl] = make_float2(v00, v01);
            *(float2*)&d_mem[(size_t)(q0+rl1)*WW + cl] = make_float2(v10, v11);
            *(__nv_bfloat162*)&d_memn[(size_t)(q0+rl0)*WW + cl] = __floats2bfloat162_rn(v00*i0, v01*i0);
            *(__nv_bfloat162*)&d_memn[(size_t)(q0+rl1)*WW + cl] = __floats2bfloat162_rn(v10*i1, v11*i1);
            Vsm[cl*136 + rl0]     = __float2bfloat16(v00);
            Vsm[(cl+1)*136 + rl0] = __float2bfloat16(v01);
            Vsm[cl*136 + rl1]     = __float2bfloat16(v10);
            Vsm[(cl+1)*136 + rl1] = __float2bfloat16(v11);
        }
    }
    __syncthreads();
    // coalesced memT write: 128 w-rows x 128 bf16
    #pragma unroll
    for (int i=0;i<8;i++){
        int idx = tid + i*256;                 // 2048 uint4
        int w = idx >> 4, c4 = idx & 15;
        *(uint4*)&d_memTb[(size_t)w*NN + q0 + c4*8] = *(const uint4*)&Vsm[w*136 + c4*8];
    }
}

// ================= rv = rw @ mem (split-K, 8 CTAs) =================
__global__ void __launch_bounds__(256) k_rvT(){
    extern __shared__ __nv_bfloat16 smb[];
    __nv_bfloat16* As = smb;
    __nv_bfloat16* Bs = smb + 128*72;
    int tid = threadIdx.x, lane = tid & 31, wid = tid >> 5;
    int wm = wid >> 1, wn = wid & 1, g = lane >> 2, t = lane & 3;
    size_t kb = (size_t)blockIdx.x * 2048;

    float cacc[2][8][4] = {};
    for (int kc=0;kc<32;kc++){
        load_chunk(As, d_rwb   + kb + kc*64, NN, tid);
        load_chunk(Bs, d_memTb + kb + kc*64, NN, tid);
        __syncthreads();
        mma_chunk(As, Bs, cacc, wm, wn, g, t);
        __syncthreads();
    }
    float* dst = d_rvpart + (size_t)blockIdx.x*BB*WW;
    #pragma unroll
    for (int mi=0;mi<2;mi++){
        int rl0 = wm*32 + mi*16 + g, rl1 = rl0 + 8;
        #pragma unroll
        for (int nj=0;nj<8;nj++){
            int cl = wn*64 + nj*8 + 2*t;
            *(float2*)&dst[(size_t)rl0*WW + cl] = make_float2(cacc[mi][nj][0], cacc[mi][nj][1]);
            *(float2*)&dst[(size_t)rl1*WW + cl] = make_float2(cacc[mi][nj][2], cacc[mi][nj][3]);
        }
    }
}

__global__ void k_rvred(){
    int i = blockIdx.x*256 + threadIdx.x;
    float s = 0.f;
    #pragma unroll
    for (int p=0;p<8;p++) s += d_rvpart[(size_t)p*16384 + i];
    d_rv[i] = s;
}

// ================= launch =================
extern "C" void kernel_launch(void* const* d_in, const int* in_sizes, int n_in,
                              void* d_out, int out_size){
    const float* x      = (const float*)d_in[0];
    const float* memory = (const float*)d_in[1];
    const float* Wih    = (const float*)d_in[2];
    const float* Whh    = (const float*)d_in[3];
    const float* bih    = (const float*)d_in[4];
    const float* bhh    = (const float*)d_in[5];
    const float* Wout   = (const float*)d_in[6];
    const float* bout   = (const float*)d_in[7];
    const float* rkW    = (const float*)d_in[8];
    const float* rkb    = (const float*)d_in[9];
    const float* rbW    = (const float*)d_in[10];
    const float* rbb    = (const float*)d_in[11];
    const float* rgW    = (const float*)d_in[12];
    const float* rgb    = (const float*)d_in[13];
    const float* wkW    = (const float*)d_in[14];
    const float* wkb    = (const float*)d_in[15];
    const float* wbW    = (const float*)d_in[16];
    const float* wbb    = (const float*)d_in[17];
    const float* wgW    = (const float*)d_in[18];
    const float* wgb    = (const float*)d_in[19];
    const float* erW    = (const float*)d_in[20];
    const float* erb    = (const float*)d_in[21];
    const float* adW    = (const float*)d_in[22];
    const float* adb    = (const float*)d_in[23];
    const float* pW     = (const float*)d_in[24];
    const float* pb     = (const float*)d_in[25];
    float* out = (float*)d_out;

    const int SM_GEMM = 2*128*72*2;                  // 36864
    const int SM_MUPD = SM_GEMM + 128*132*4;         // 104448
    cudaFuncSetAttribute(k_memupdT, cudaFuncAttributeMaxDynamicSharedMemorySize, SM_MUPD);
    cudaFuncSetAttribute(k_smax,    cudaFuncAttributeMaxDynamicSharedMemorySize, 65536);

    k_init<<<8192, 256>>>(memory);
    k_rownorm<<<2048, 256>>>();
    for (int t = 0; t < SS; t++){
        k_lstm<<<dim3(64,2), 256>>>(x, Wih, Whh, bih, bhh, t);
        k_gates<<<512, 256>>>();
        k_co<<<dim3(29,4), 256>>>(Wout, bout);
        k_projall<<<dim3(33,4), 256>>>(rkW,rkb,wkW,wkb,erW,erb,adW,adb,
                                       rbW,rbb,rgW,rgb,wbW,wbb,wgW,wgb,
                                       pW,pb,out,t);
        if (t + 1 < SS){
            k_keysnorm<<<32, 256>>>();
            k_simT<<<dim3(128,2), 256, SM_GEMM>>>();
            k_smax<<<256, 256, 65536>>>();
            k_memupdT<<<128, 256, SM_MUPD>>>();
            k_rvT<<<8, 256, SM_GEMM>>>();
            k_rvred<<<64, 256>>>();
        }
    }
}

// round 6
// speedup vs baseline: 2.3933x; 2.0870x over previous
#include <cuda_runtime.h>
#include <cuda_bf16.h>
#include <cstdint>
#include <stdint.h>
#include <math.h>

#define BB    128
#define SS    32
#define INSZ  512
#define HH    1024
#define OUTSZ 512
#define NN    16384
#define WW    128
#define CC    899
#define G4    4096
#define COLD  904
#define KLSTM 1664
#define NTSIM 128      // sim n-tiles of 128
#define RVSPL 32       // rv split-K CTAs

// ================= warp-level bf16 MMA =================
#define MMA16816(c, a, b) \
    asm volatile("mma.sync.aligned.m16n8k16.row.col.f32.bf16.bf16.f32 " \
        "{%0,%1,%2,%3}, {%4,%5,%6,%7}, {%8,%9}, {%0,%1,%2,%3};" \
        : "+f"((c)[0]), "+f"((c)[1]), "+f"((c)[2]), "+f"((c)[3]) \
        : "r"((a)[0]), "r"((a)[1]), "r"((a)[2]), "r"((a)[3]), "r"((b)[0]), "r"((b)[1]))

// load 128 rows x 64 cols bf16 into smem [128][72]
__device__ __forceinline__ void load_chunk(__nv_bfloat16* sm, const __nv_bfloat16* src,
                                           size_t ld, int tid){
    #pragma unroll
    for (int i=0;i<4;i++){
        int idx = tid + i*256;          // 1024 uint4
        int row = idx >> 3, c4 = idx & 7;
        *(uint4*)(sm + row*72 + c4*8) = *(const uint4*)(src + (size_t)row*ld + c4*8);
    }
}
// load 64 rows x 64 cols
__device__ __forceinline__ void load_chunk64(__nv_bfloat16* sm, const __nv_bfloat16* src,
                                             size_t ld, int tid){
    #pragma unroll
    for (int i=0;i<2;i++){
        int idx = tid + i*256;          // 512 uint4
        int row = idx >> 3, c4 = idx & 7;
        *(uint4*)(sm + row*72 + c4*8) = *(const uint4*)(src + (size_t)row*ld + c4*8);
    }
}

// CTA 128x128, 8 warps 4(m)x2(n), warp 32m x 64n
__device__ __forceinline__ void mma_chunk(const __nv_bfloat16* As, const __nv_bfloat16* Bs,
                                          float cacc[2][8][4], int wm, int wn, int g, int t){
    #pragma unroll
    for (int ks=0;ks<4;ks++){
        int k = ks*16;
        uint32_t afr[2][4], bfr[8][2];
        #pragma unroll
        for (int mi=0;mi<2;mi++){
            const __nv_bfloat16* ap = As + (wm*32 + mi*16)*72 + k + 2*t;
            afr[mi][0] = *(const uint32_t*)(ap + g*72);
            afr[mi][1] = *(const uint32_t*)(ap + (g+8)*72);
            afr[mi][2] = *(const uint32_t*)(ap + g*72 + 8);
            afr[mi][3] = *(const uint32_t*)(ap + (g+8)*72 + 8);
        }
        #pragma unroll
        for (int nj=0;nj<8;nj++){
            const __nv_bfloat16* bp = Bs + (wn*64 + nj*8 + g)*72 + k + 2*t;
            bfr[nj][0] = *(const uint32_t*)(bp);
            bfr[nj][1] = *(const uint32_t*)(bp + 8);
        }
        #pragma unroll
        for (int mi=0;mi<2;mi++)
            #pragma unroll
            for (int nj=0;nj<8;nj++)
                MMA16816(cacc[mi][nj], afr[mi], bfr[nj]);
    }
}

// CTA 128x64, 8 warps 4(m)x2(n), warp 32m x 32n
__device__ __forceinline__ void mma_chunk4(const __nv_bfloat16* As, const __nv_bfloat16* Bs,
                                           float cacc[2][4][4], int wm, int wn, int g, int t){
    #pragma unroll
    for (int ks=0;ks<4;ks++){
        int k = ks*16;
        uint32_t afr[2][4], bfr[4][2];
        #pragma unroll
        for (int mi=0;mi<2;mi++){
            const __nv_bfloat16* ap = As + (wm*32 + mi*16)*72 + k + 2*t;
            afr[mi][0] = *(const uint32_t*)(ap + g*72);
            afr[mi][1] = *(const uint32_t*)(ap + (g+8)*72);
            afr[mi][2] = *(const uint32_t*)(ap + g*72 + 8);
            afr[mi][3] = *(const uint32_t*)(ap + (g+8)*72 + 8);
        }
        #pragma unroll
        for (int nj=0;nj<4;nj++){
            const __nv_bfloat16* bp = Bs + (wn*32 + nj*8 + g)*72 + k + 2*t;
            bfr[nj][0] = *(const uint32_t*)(bp);
            bfr[nj][1] = *(const uint32_t*)(bp + 8);
        }
        #pragma unroll
        for (int mi=0;mi<2;mi++)
            #pragma unroll
            for (int nj=0;nj<4;nj++)
                MMA16816(cacc[mi][nj], afr[mi], bfr[nj]);
    }
}

// ================= device state =================
__device__ float d_mem[NN * WW];
__device__ __nv_bfloat16 d_memn[NN * WW];
__device__ __nv_bfloat16 d_memTb[WW * NN];
__device__ float d_h[BB * HH];
__device__ float d_c[BB * HH];
__device__ float d_co[BB * COLD];
__device__ float d_keys[BB * 2 * WW];
__device__ __nv_bfloat16 d_keysn[256 * WW];
__device__ float d_erad[BB * 2 * WW];
__device__ __nv_bfloat16 d_eradT[256 * BB];
__device__ float d_scal[BB * 4];
__device__ float d_sim[256 * NN];
__device__ float d_pmax[256 * NTSIM];
__device__ float d_rw[BB * NN];
__device__ __nv_bfloat16 d_rwb[BB * NN];
__device__ __nv_bfloat16 d_wwT[NN * BB];
__device__ float d_rv[BB * WW];
__device__ float d_rvpart[RVSPL * BB * WW];
// split-bf16 LSTM operands
__device__ __nv_bfloat16 d_Whi[G4 * KLSTM];      // combined [Wih|Whh] hi
__device__ __nv_bfloat16 d_Wlo[G4 * KLSTM];      // lo
__device__ __nv_bfloat16 d_xhi[BB * SS * INSZ];
__device__ __nv_bfloat16 d_xlo[BB * SS * INSZ];
__device__ __nv_bfloat16 d_hhi[BB * HH];
__device__ __nv_bfloat16 d_hlo[BB * HH];
__device__ __nv_bfloat16 d_rvhi[BB * WW];
__device__ __nv_bfloat16 d_rvlo[BB * WW];
__device__ float d_gpart[2 * BB * G4];           // split-K partials

__device__ __forceinline__ float sigmoidf_(float x){ return 1.f/(1.f+__expf(-x)); }
__device__ __forceinline__ float softplusf_(float x){ return x>15.f ? x : log1pf(__expf(x)); }

// ================= init =================
__global__ void k_init(const float* __restrict__ memory){
    int i = blockIdx.x*256 + threadIdx.x;
    d_mem[i] = memory[i];
    d_rw[i]  = 1.0f/NN;
    if (i < BB*HH){ d_h[i]=0.f; d_c[i]=0.f;
        d_hhi[i]=__float2bfloat16(0.f); d_hlo[i]=__float2bfloat16(0.f); }
    if (i < BB*WW){ d_rv[i]=0.f;
        d_rvhi[i]=__float2bfloat16(0.f); d_rvlo[i]=__float2bfloat16(0.f); }
}

__global__ void k_wsplit(const float* __restrict__ Wih, const float* __restrict__ Whh){
    int i = blockIdx.x*256 + threadIdx.x;          // 0 .. 4096*1664-1
    int j = i / KLSTM, k = i - j*KLSTM;
    float w = (k < 640) ? Wih[(size_t)j*640 + k] : Whh[(size_t)j*1024 + (k-640)];
    __nv_bfloat16 hi = __float2bfloat16(w);
    d_Whi[i] = hi;
    d_Wlo[i] = __float2bfloat16(w - __bfloat162float(hi));
}

__global__ void k_xsplit(const float* __restrict__ x){
    int i = blockIdx.x*256 + threadIdx.x;          // 0 .. 128*32*512-1
    float v = x[i];
    __nv_bfloat16 hi = __float2bfloat16(v);
    d_xhi[i] = hi;
    d_xlo[i] = __float2bfloat16(v - __bfloat162float(hi));
}

__global__ void k_rownorm(){
    int row  = blockIdx.x*8 + (threadIdx.x>>5);
    int lane = threadIdx.x & 31;
    const float4* p = (const float4*)(d_mem + (size_t)row*WW);
    float4 v = p[lane];
    float s = v.x*v.x + v.y*v.y + v.z*v.z + v.w*v.w;
    #pragma unroll
    for (int o=16;o;o>>=1) s += __shfl_xor_sync(0xffffffffu, s, o);
    s = __shfl_sync(0xffffffffu, s, 0);
    float inv = 1.f / fmaxf(sqrtf(s), 1e-12f);
    __nv_bfloat162* nm = (__nv_bfloat162*)(d_memn + (size_t)row*WW + lane*4);
    nm[0] = __floats2bfloat162_rn(v.x*inv, v.y*inv);
    nm[1] = __floats2bfloat162_rn(v.z*inv, v.w*inv);
    float vv[4] = {v.x, v.y, v.z, v.w};
    #pragma unroll
    for (int j=0;j<4;j++) d_memTb[(size_t)(lane*4+j)*NN + row] = __float2bfloat16(vv[j]);
}

// ================= LSTM via split-bf16 MMA =================
// grid (64 n-tiles, 2 k-splits). CTA: 128m x 64n, K half = 832 per pass (13 chunks)
__global__ void __launch_bounds__(256) k_lstmT(int t){
    __shared__ __nv_bfloat16 As[128*72];
    __shared__ __nv_bfloat16 Bs[64*72];
    int tid = threadIdx.x, lane = tid & 31, wid = tid >> 5;
    int wm = wid >> 1, wn = wid & 1, g = lane >> 2, tq = lane & 3;
    int n0 = blockIdx.x*64;
    int ks = blockIdx.y;

    float cacc[2][4][4] = {};
    #pragma unroll
    for (int pass=0; pass<3; pass++){
        const __nv_bfloat16* Wb = (pass==2) ? d_Wlo : d_Whi;
        #pragma unroll
        for (int cc=0; cc<13; cc++){
            int k0 = (ks*13 + cc)*64;
            const __nv_bfloat16* Asrc; size_t lda;
            if (k0 < 512){
                Asrc = ((pass==1) ? d_xlo : d_xhi) + (size_t)t*INSZ + k0; lda = (size_t)SS*INSZ;
            } else if (k0 < 640){
                Asrc = ((pass==1) ? d_rvlo : d_rvhi) + (k0-512); lda = WW;
            } else {
                Asrc = ((pass==1) ? d_hlo : d_hhi) + (k0-640); lda = HH;
            }
            load_chunk(As, Asrc, lda, tid);
            load_chunk64(Bs, Wb + (size_t)n0*KLSTM + k0, KLSTM, tid);
            __syncthreads();
            mma_chunk4(As, Bs, cacc, wm, wn, g, tq);
            __syncthreads();
        }
    }
    float* gp = d_gpart + (size_t)ks*BB*G4;
    #pragma unroll
    for (int mi=0;mi<2;mi++){
        int rl0 = wm*32 + mi*16 + g, rl1 = rl0 + 8;
        #pragma unroll
        for (int nj=0;nj<4;nj++){
            int col = n0 + wn*32 + nj*8 + 2*tq;
            *(float2*)&gp[(size_t)rl0*G4 + col] = make_float2(cacc[mi][nj][0], cacc[mi][nj][1]);
            *(float2*)&gp[(size_t)rl1*G4 + col] = make_float2(cacc[mi][nj][2], cacc[mi][nj][3]);
        }
    }
}

__global__ void k_gates(const float* __restrict__ bih, const float* __restrict__ bhh){
    int i = blockIdx.x*256 + threadIdx.x;
    int b = i >> 10, u = i & 1023;
    const float* g0 = d_gpart + (size_t)b*G4;
    const float* g1 = d_gpart + (size_t)BB*G4 + (size_t)b*G4;
    float gi = g0[u]      + g1[u]      + bih[u]      + bhh[u];
    float gf = g0[1024+u] + g1[1024+u] + bih[1024+u] + bhh[1024+u];
    float gg = g0[2048+u] + g1[2048+u] + bih[2048+u] + bhh[2048+u];
    float go = g0[3072+u] + g1[3072+u] + bih[3072+u] + bhh[3072+u];
    float c = sigmoidf_(gf)*d_c[i] + sigmoidf_(gi)*tanhf(gg);
    float h = sigmoidf_(go)*tanhf(c);
    d_c[i] = c; d_h[i] = h;
    __nv_bfloat16 hi = __float2bfloat16(h);
    d_hhi[i] = hi;
    d_hlo[i] = __float2bfloat16(h - __bfloat162float(hi));
}

__global__ void k_co(const float* __restrict__ Wout, const float* __restrict__ bout){
    __shared__ float As[32][33];
    __shared__ float Bs[32][33];
    int n0 = blockIdx.x*32, m0 = blockIdx.y*32;
    int tid = threadIdx.x, tx = tid & 15, ty = tid >> 4;
    int lk = tid & 31, lr = tid >> 5;
    float acc[2][2] = {};
    for (int k0 = 0; k0 < HH; k0 += 32){
        #pragma unroll
        for (int p=0;p<4;p++){
            int m = lr + p*8;
            As[lk][m] = d_h[(size_t)(m0+m)*HH + k0 + lk];
            int n = lr + p*8;
            Bs[lk][n] = (n0+n < CC) ? Wout[(size_t)(n0+n)*HH + k0 + lk] : 0.f;
        }
        __syncthreads();
        #pragma unroll
        for (int kk=0;kk<32;kk++){
            float a0 = As[kk][ty*2], a1 = As[kk][ty*2+1];
            float b0 = Bs[kk][tx*2], b1 = Bs[kk][tx*2+1];
            acc[0][0]+=a0*b0; acc[0][1]+=a0*b1; acc[1][0]+=a1*b0; acc[1][1]+=a1*b1;
        }
        __syncthreads();
    }
    #pragma unroll
    for (int i=0;i<2;i++)
        #pragma unroll
        for (int j=0;j<2;j++){
            int m = m0 + ty*2+i, n = n0 + tx*2+j;
            if (n < CC) d_co[(size_t)m*COLD + n] = acc[i][j] + bout[n];
        }
}

// ================= projections =================
__global__ void k_projall(const float* __restrict__ rkW, const float* __restrict__ rkb,
                          const float* __restrict__ wkW, const float* __restrict__ wkb,
                          const float* __restrict__ erW, const float* __restrict__ erb,
                          const float* __restrict__ adW, const float* __restrict__ adb,
                          const float* __restrict__ rbW, const float* __restrict__ rbb,
                          const float* __restrict__ rgW, const float* __restrict__ rgb,
                          const float* __restrict__ wbW, const float* __restrict__ wbb,
                          const float* __restrict__ wgW, const float* __restrict__ wgb,
                          const float* __restrict__ pW,  const float* __restrict__ pb,
                          float* __restrict__ out, int t){
    int s  = blockIdx.x;
    int m0 = blockIdx.y*32;
    int tid = threadIdx.x;

    if (s == 32){
        __shared__ float ws[4][900];
        for (int k = tid; k < CC; k += 256){
            ws[0][k]=rbW[k]; ws[1][k]=rgW[k]; ws[2][k]=wbW[k]; ws[3][k]=wgW[k];
        }
        __syncthreads();
        if (tid < 128){
            int b = m0 + (tid >> 2);
            int j = tid & 3;
            const float* crow = d_co + (size_t)b*COLD;
            float acc = 0.f;
            #pragma unroll 4
            for (int k = 0; k < CC; k++) acc += crow[k]*ws[j][k];
            float bias = (j==0) ? rbb[0] : (j==1) ? rgb[0] : (j==2) ? wbb[0] : wgb[0];
            float v = softplusf_(acc + bias);
            if (j & 1) v += 1.f;
            d_scal[b*4 + j] = v;
        }
        return;
    }

    const float* Wseg; const float* bias; float* Cp; int ldc, Kseg, act, n0, head = -1;
    if (s < 16){
        head = s >> 2;
        n0 = (s & 3)*32;  Kseg = CC;
        if      (head==0){ Wseg=rkW; bias=rkb; Cp=d_keys;     ldc=256; act=0; }
        else if (head==1){ Wseg=wkW; bias=wkb; Cp=d_keys+128; ldc=256; act=0; }
        else if (head==2){ Wseg=erW; bias=erb; Cp=d_erad;     ldc=256; act=1; }
        else             { Wseg=adW; bias=adb; Cp=d_erad+128; ldc=256; act=2; }
    } else {
        n0 = (s-16)*32; Kseg = OUTSZ; Wseg = pW; bias = pb;
        Cp = out + (size_t)t*OUTSZ; ldc = SS*OUTSZ; act = 0;
    }

    __shared__ float As[32][33];
    __shared__ float Bs[32][33];
    int tx = tid & 15, ty = tid >> 4;
    int lk = tid & 31, lr = tid >> 5;
    float acc[2][2] = {};
    for (int k0 = 0; k0 < Kseg; k0 += 32){
        #pragma unroll
        for (int p=0;p<4;p++){
            int m = lr + p*8;
            int k = k0 + lk;
            As[lk][m] = (k < Kseg) ? d_co[(size_t)(m0+m)*COLD + k] : 0.f;
            int n = lr + p*8;
            Bs[lk][n] = (k < Kseg) ? Wseg[(size_t)(n0+n)*Kseg + k] : 0.f;
        }
        __syncthreads();
        #pragma unroll
        for (int kk=0;kk<32;kk++){
            float a0 = As[kk][ty*2], a1 = As[kk][ty*2+1];
            float b0 = Bs[kk][tx*2], b1 = Bs[kk][tx*2+1];
            acc[0][0]+=a0*b0; acc[0][1]+=a0*b1; acc[1][0]+=a1*b0; acc[1][1]+=a1*b1;
        }
        __syncthreads();
    }
    #pragma unroll
    for (int i=0;i<2;i++)
        #pragma unroll
        for (int j=0;j<2;j++){
            int m = m0 + ty*2+i, n = n0 + tx*2+j;
            float v = acc[i][j] + bias[n];
            if (act==1) v = sigmoidf_(v);
            else if (act==2) v = tanhf(v);
            Cp[(size_t)m*ldc + n] = v;
            if (head >= 2){
                int rrow = (head==2 ? 0 : 128) + n;
                d_eradT[rrow*BB + m] = __float2bfloat16(v);
            }
        }
}

__global__ void k_keysnorm(){
    int row  = blockIdx.x*8 + (threadIdx.x>>5);
    int lane = threadIdx.x & 31;
    int head = row >> 7, b = row & 127;
    const float4* p = (const float4*)(d_keys + b*256 + head*128);
    float4 v = p[lane];
    float s = v.x*v.x + v.y*v.y + v.z*v.z + v.w*v.w;
    #pragma unroll
    for (int o=16;o;o>>=1) s += __shfl_xor_sync(0xffffffffu, s, o);
    s = __shfl_sync(0xffffffffu, s, 0);
    float inv = 1.f / fmaxf(sqrtf(s), 1e-12f);
    __nv_bfloat162* kn = (__nv_bfloat162*)(d_keysn + (size_t)row*WW + lane*4);
    kn[0] = __floats2bfloat162_rn(v.x*inv, v.y*inv);
    kn[1] = __floats2bfloat162_rn(v.z*inv, v.w*inv);
}

// ================= sim =================
__global__ void __launch_bounds__(256) k_simT(){
    extern __shared__ __nv_bfloat16 smb[];
    __nv_bfloat16* As = smb;
    __nv_bfloat16* Bs = smb + 128*72;
    __shared__ float redm[128][2];
    int tid = threadIdx.x, lane = tid & 31, wid = tid >> 5;
    int wm = wid >> 1, wn = wid & 1, g = lane >> 2, t = lane & 3;
    int m0 = blockIdx.y*128, n0 = blockIdx.x*128;

    float cacc[2][8][4] = {};
    #pragma unroll
    for (int kc=0;kc<2;kc++){
        load_chunk(As, d_keysn + (size_t)m0*WW + kc*64, WW, tid);
        load_chunk(Bs, d_memn  + (size_t)n0*WW + kc*64, WW, tid);
        __syncthreads();
        mma_chunk(As, Bs, cacc, wm, wn, g, t);
        __syncthreads();
    }
    #pragma unroll
    for (int mi=0;mi<2;mi++){
        int rl0 = wm*32 + mi*16 + g, rl1 = rl0 + 8;
        float mx0 = -3.0e38f, mx1 = -3.0e38f;
        #pragma unroll
        for (int nj=0;nj<8;nj++){
            int col = n0 + wn*64 + nj*8 + 2*t;
            float c0 = cacc[mi][nj][0], c1 = cacc[mi][nj][1];
            float c2 = cacc[mi][nj][2], c3 = cacc[mi][nj][3];
            *(float2*)&d_sim[(size_t)(m0+rl0)*NN + col] = make_float2(c0, c1);
            *(float2*)&d_sim[(size_t)(m0+rl1)*NN + col] = make_float2(c2, c3);
            mx0 = fmaxf(mx0, fmaxf(c0, c1));
            mx1 = fmaxf(mx1, fmaxf(c2, c3));
        }
        mx0 = fmaxf(mx0, __shfl_xor_sync(0xffffffffu, mx0, 1));
        mx0 = fmaxf(mx0, __shfl_xor_sync(0xffffffffu, mx0, 2));
        mx1 = fmaxf(mx1, __shfl_xor_sync(0xffffffffu, mx1, 1));
        mx1 = fmaxf(mx1, __shfl_xor_sync(0xffffffffu, mx1, 2));
        if (t == 0){ redm[rl0][wn] = mx0; redm[rl1][wn] = mx1; }
    }
    __syncthreads();
    if (tid < 128)
        d_pmax[(size_t)(m0+tid)*NTSIM + blockIdx.x] = fmaxf(redm[tid][0], redm[tid][1]);
}

// ================= softmax + interpolation =================
__global__ void k_smax(){
    extern __shared__ float esm[];
    __shared__ float red[256];
    int r = blockIdx.x;
    int head = r >> 7, b = r & 127;
    float beta  = d_scal[b*4 + head*2];
    float gamma = d_scal[b*4 + head*2 + 1];
    int tid = threadIdx.x;

    red[tid] = (tid < NTSIM) ? d_pmax[(size_t)r*NTSIM + tid] : -3.0e38f;
    __syncthreads();
    for (int o=128;o;o>>=1){ if (tid<o) red[tid] = fmaxf(red[tid], red[tid+o]); __syncthreads(); }
    float m = red[0];
    __syncthreads();

    const float* simrow = d_sim + (size_t)r*NN;
    float s = 0.f;
    for (int n = tid; n < NN; n += 256){
        float e = __expf(beta*(simrow[n] - m));
        esm[n] = e; s += e;
    }
    red[tid] = s; __syncthreads();
    for (int o=128;o;o>>=1){ if (tid<o) red[tid] += red[tid+o]; __syncthreads(); }
    float inv = 1.f / red[0];

    if (head == 0){
        float* rw = d_rw + (size_t)b*NN;
        __nv_bfloat16* rwb = d_rwb + (size_t)b*NN;
        for (int n = tid; n < NN; n += 256){
            float w = esm[n]*inv;
            float v = gamma*w + (1.f-gamma)*rw[n];
            rw[n] = v;
            rwb[n] = __float2bfloat16(v);
        }
    } else {
        const float u = 1.f/NN;
        for (int n = tid; n < NN; n += 256){
            float w = esm[n]*inv;
            float v = gamma*w + (1.f-gamma)*u;
            d_wwT[(size_t)n*BB + b] = __float2bfloat16(v);
        }
    }
}

// ================= memory update =================
__global__ void __launch_bounds__(256) k_memupdT(){
    extern __shared__ __nv_bfloat16 smb[];
    __nv_bfloat16* As = smb;
    __nv_bfloat16* Bs = smb + 128*72;
    float* Esm = (float*)(smb + 2*128*72);
    __shared__ float redm[128][2];
    __shared__ float invsm[128];
    int tid = threadIdx.x, lane = tid & 31, wid = tid >> 5;
    int wm = wid >> 1, wn = wid & 1, g = lane >> 2, t = lane & 3;
    int q0 = blockIdx.x*128;

    float cacc[2][8][4] = {};
    #pragma unroll
    for (int ph=0; ph<2; ph++){
        #pragma unroll
        for (int kc=0;kc<2;kc++){
            load_chunk(As, d_wwT + (size_t)q0*BB + kc*64, BB, tid);
            load_chunk(Bs, d_eradT + ph*128*BB + kc*64, BB, tid);
            __syncthreads();
            mma_chunk(As, Bs, cacc, wm, wn, g, t);
            __syncthreads();
        }
        if (ph == 0){
            #pragma unroll
            for (int mi=0;mi<2;mi++){
                int rl0 = wm*32 + mi*16 + g, rl1 = rl0 + 8;
                #pragma unroll
                for (int nj=0;nj<8;nj++){
                    int cl = wn*64 + nj*8 + 2*t;
                    Esm[rl0*132 + cl]   = cacc[mi][nj][0];
                    Esm[rl0*132 + cl+1] = cacc[mi][nj][1];
                    Esm[rl1*132 + cl]   = cacc[mi][nj][2];
                    Esm[rl1*132 + cl+1] = cacc[mi][nj][3];
                    cacc[mi][nj][0]=0.f; cacc[mi][nj][1]=0.f;
                    cacc[mi][nj][2]=0.f; cacc[mi][nj][3]=0.f;
                }
            }
        }
    }
    float ssq[2][2] = {};
    #pragma unroll
    for (int mi=0;mi<2;mi++){
        int rl0 = wm*32 + mi*16 + g, rl1 = rl0 + 8;
        #pragma unroll
        for (int nj=0;nj<8;nj++){
            int cl = wn*64 + nj*8 + 2*t;
            float2 m0v = *(const float2*)&d_mem[(size_t)(q0+rl0)*WW + cl];
            float2 m1v = *(const float2*)&d_mem[(size_t)(q0+rl1)*WW + cl];
            float v00 = m0v.x*(1.f - Esm[rl0*132+cl])   + cacc[mi][nj][0];
            float v01 = m0v.y*(1.f - Esm[rl0*132+cl+1]) + cacc[mi][nj][1];
            float v10 = m1v.x*(1.f - Esm[rl1*132+cl])   + cacc[mi][nj][2];
            float v11 = m1v.y*(1.f - Esm[rl1*132+cl+1]) + cacc[mi][nj][3];
            cacc[mi][nj][0]=v00; cacc[mi][nj][1]=v01; cacc[mi][nj][2]=v10; cacc[mi][nj][3]=v11;
            ssq[mi][0] += v00*v00 + v01*v01;
            ssq[mi][1] += v10*v10 + v11*v11;
        }
    }
    #pragma unroll
    for (int mi=0;mi<2;mi++){
        #pragma unroll
        for (int h=0;h<2;h++){
            float s = ssq[mi][h];
            s += __shfl_xor_sync(0xffffffffu, s, 1);
            s += __shfl_xor_sync(0xffffffffu, s, 2);
            if (t == 0) redm[wm*32 + mi*16 + h*8 + g][wn] = s;
        }
    }
    __syncthreads();
    if (tid < 128) invsm[tid] = 1.f / fmaxf(sqrtf(redm[tid][0] + redm[tid][1]), 1e-12f);
    __syncthreads();
    __nv_bfloat16* Vsm = (__nv_bfloat16*)Esm;      // [128][136]
    #pragma unroll
    for (int mi=0;mi<2;mi++){
        int rl0 = wm*32 + mi*16 + g, rl1 = rl0 + 8;
        float i0 = invsm[rl0], i1 = invsm[rl1];
        #pragma unroll
        for (int nj=0;nj<8;nj++){
            int cl = wn*64 + nj*8 + 2*t;
            float v00=cacc[mi][nj][0], v01=cacc[mi][nj][1], v10=cacc[mi][nj][2], v11=cacc[mi][nj][3];
            *(float2*)&d_mem[(size_t)(q0+rl0)*WW + cl] = make_float2(v00, v01);
            *(float2*)&d_mem[(size_t)(q0+rl1)*WW + cl] = make_float2(v10, v11);
            *(__nv_bfloat162*)&d_memn[(size_t)(q0+rl0)*WW + cl] = __floats2bfloat162_rn(v00*i0, v01*i0);
            *(__nv_bfloat162*)&d_memn[(size_t)(q0+rl1)*WW + cl] = __floats2bfloat162_rn(v10*i1, v11*i1);
            Vsm[cl*136 + rl0]     = __float2bfloat16(v00);
            Vsm[(cl+1)*136 + rl0] = __float2bfloat16(v01);
            Vsm[cl*136 + rl1]     = __float2bfloat16(v10);
            Vsm[(cl+1)*136 + rl1] = __float2bfloat16(v11);
        }
    }
    __syncthreads();
    #pragma unroll
    for (int i=0;i<8;i++){
        int idx = tid + i*256;
        int w = idx >> 4, c4 = idx & 15;
        *(uint4*)&d_memTb[(size_t)w*NN + q0 + c4*8] = *(const uint4*)&Vsm[w*136 + c4*8];
    }
}

// ================= rv = rw @ mem (split-K, 32 CTAs) =================
__global__ void __launch_bounds__(256) k_rvT(){
    extern __shared__ __nv_bfloat16 smb[];
    __nv_bfloat16* As = smb;
    __nv_bfloat16* Bs = smb + 128*72;
    int tid = threadIdx.x, lane = tid & 31, wid = tid >> 5;
    int wm = wid >> 1, wn = wid & 1, g = lane >> 2, t = lane & 3;
    size_t kb = (size_t)blockIdx.x * 512;

    float cacc[2][8][4] = {};
    #pragma unroll
    for (int kc=0;kc<8;kc++){
        load_chunk(As, d_rwb   + kb + kc*64, NN, tid);
        load_chunk(Bs, d_memTb + kb + kc*64, NN, tid);
        __syncthreads();
        mma_chunk(As, Bs, cacc, wm, wn, g, t);
        __syncthreads();
    }
    float* dst = d_rvpart + (size_t)blockIdx.x*BB*WW;
    #pragma unroll
    for (int mi=0;mi<2;mi++){
        int rl0 = wm*32 + mi*16 + g, rl1 = rl0 + 8;
        #pragma unroll
        for (int nj=0;nj<8;nj++){
            int cl = wn*64 + nj*8 + 2*t;
            *(float2*)&dst[(size_t)rl0*WW + cl] = make_float2(cacc[mi][nj][0], cacc[mi][nj][1]);
            *(float2*)&dst[(size_t)rl1*WW + cl] = make_float2(cacc[mi][nj][2], cacc[mi][nj][3]);
        }
    }
}

__global__ void k_rvred(){
    int i = blockIdx.x*256 + threadIdx.x;      // 16384 = [b][w]
    float s = 0.f;
    #pragma unroll
    for (int p=0;p<RVSPL;p++) s += d_rvpart[(size_t)p*16384 + i];
    d_rv[i] = s;
    __nv_bfloat16 hi = __float2bfloat16(s);
    d_rvhi[i] = hi;
    d_rvlo[i] = __float2bfloat16(s - __bfloat162float(hi));
}

// ================= launch =================
extern "C" void kernel_launch(void* const* d_in, const int* in_sizes, int n_in,
                              void* d_out, int out_size){
    const float* x      = (const float*)d_in[0];
    const float* memory = (const float*)d_in[1];
    const float* Wih    = (const float*)d_in[2];
    const float* Whh    = (const float*)d_in[3];
    const float* bih    = (const float*)d_in[4];
    const float* bhh    = (const float*)d_in[5];
    const float* Wout   = (const float*)d_in[6];
    const float* bout   = (const float*)d_in[7];
    const float* rkW    = (const float*)d_in[8];
    const float* rkb    = (const float*)d_in[9];
    const float* rbW    = (const float*)d_in[10];
    const float* rbb    = (const float*)d_in[11];
    const float* rgW    = (const float*)d_in[12];
    const float* rgb    = (const float*)d_in[13];
    const float* wkW    = (const float*)d_in[14];
    const float* wkb    = (const float*)d_in[15];
    const float* wbW    = (const float*)d_in[16];
    const float* wbb    = (const float*)d_in[17];
    const float* wgW    = (const float*)d_in[18];
    const float* wgb    = (const float*)d_in[19];
    const float* erW    = (const float*)d_in[20];
    const float* erb    = (const float*)d_in[21];
    const float* adW    = (const float*)d_in[22];
    const float* adb    = (const float*)d_in[23];
    const float* pW     = (const float*)d_in[24];
    const float* pb     = (const float*)d_in[25];
    float* out = (float*)d_out;

    const int SM_GEMM = 2*128*72*2;                  // 36864
    const int SM_MUPD = SM_GEMM + 128*132*4;         // 104448
    cudaFuncSetAttribute(k_memupdT, cudaFuncAttributeMaxDynamicSharedMemorySize, SM_MUPD);
    cudaFuncSetAttribute(k_smax,    cudaFuncAttributeMaxDynamicSharedMemorySize, 65536);

    k_init<<<8192, 256>>>(memory);
    k_wsplit<<<G4*KLSTM/256, 256>>>(Wih, Whh);
    k_xsplit<<<BB*SS*INSZ/256, 256>>>(x);
    k_rownorm<<<2048, 256>>>();
    for (int t = 0; t < SS; t++){
        k_lstmT<<<dim3(64,2), 256>>>(t);
        k_gates<<<512, 256>>>(bih, bhh);
        k_co<<<dim3(29,4), 256>>>(Wout, bout);
        k_projall<<<dim3(33,4), 256>>>(rkW,rkb,wkW,wkb,erW,erb,adW,adb,
                                       rbW,rbb,rgW,rgb,wbW,wbb,wgW,wgb,
                                       pW,pb,out,t);
        if (t + 1 < SS){
            k_keysnorm<<<32, 256>>>();
            k_simT<<<dim3(128,2), 256, SM_GEMM>>>();
            k_smax<<<256, 256, 65536>>>();
            k_memupdT<<<128, 256, SM_MUPD>>>();
            k_rvT<<<RVSPL, 256, SM_GEMM>>>();
            k_rvred<<<64, 256>>>();
        }
    }
}

// round 7
// speedup vs baseline: 2.8444x; 1.1885x over previous
#include <cuda_runtime.h>
#include <cuda_bf16.h>
#include <cstdint>
#include <stdint.h>
#include <math.h>

#define BB    128
#define SS    32
#define INSZ  512
#define HH    1024
#define OUTSZ 512
#define NN    16384
#define WW    128
#define CC    899
#define G4    4096
#define KLSTM 1664
#define NPROJ 1088     // padded combined projection rows
#define NTSIM 128
#define RVSPL 32

// ================= warp-level bf16 MMA =================
#define MMA16816(c, a, b) \
    asm volatile("mma.sync.aligned.m16n8k16.row.col.f32.bf16.bf16.f32 " \
        "{%0,%1,%2,%3}, {%4,%5,%6,%7}, {%8,%9}, {%0,%1,%2,%3};" \
        : "+f"((c)[0]), "+f"((c)[1]), "+f"((c)[2]), "+f"((c)[3]) \
        : "r"((a)[0]), "r"((a)[1]), "r"((a)[2]), "r"((a)[3]), "r"((b)[0]), "r"((b)[1]))

__device__ __forceinline__ void load_chunk(__nv_bfloat16* sm, const __nv_bfloat16* src,
                                           size_t ld, int tid){
    #pragma unroll
    for (int i=0;i<4;i++){
        int idx = tid + i*256;
        int row = idx >> 3, c4 = idx & 7;
        *(uint4*)(sm + row*72 + c4*8) = *(const uint4*)(src + (size_t)row*ld + c4*8);
    }
}
__device__ __forceinline__ void load_chunk64(__nv_bfloat16* sm, const __nv_bfloat16* src,
                                             size_t ld, int tid){
    #pragma unroll
    for (int i=0;i<2;i++){
        int idx = tid + i*256;
        int row = idx >> 3, c4 = idx & 7;
        *(uint4*)(sm + row*72 + c4*8) = *(const uint4*)(src + (size_t)row*ld + c4*8);
    }
}

// CTA 128x128, 8 warps 4(m)x2(n)
__device__ __forceinline__ void mma_chunk(const __nv_bfloat16* As, const __nv_bfloat16* Bs,
                                          float cacc[2][8][4], int wm, int wn, int g, int t){
    #pragma unroll
    for (int ks=0;ks<4;ks++){
        int k = ks*16;
        uint32_t afr[2][4], bfr[8][2];
        #pragma unroll
        for (int mi=0;mi<2;mi++){
            const __nv_bfloat16* ap = As + (wm*32 + mi*16)*72 + k + 2*t;
            afr[mi][0] = *(const uint32_t*)(ap + g*72);
            afr[mi][1] = *(const uint32_t*)(ap + (g+8)*72);
            afr[mi][2] = *(const uint32_t*)(ap + g*72 + 8);
            afr[mi][3] = *(const uint32_t*)(ap + (g+8)*72 + 8);
        }
        #pragma unroll
        for (int nj=0;nj<8;nj++){
            const __nv_bfloat16* bp = Bs + (wn*64 + nj*8 + g)*72 + k + 2*t;
            bfr[nj][0] = *(const uint32_t*)(bp);
            bfr[nj][1] = *(const uint32_t*)(bp + 8);
        }
        #pragma unroll
        for (int mi=0;mi<2;mi++)
            #pragma unroll
            for (int nj=0;nj<8;nj++)
                MMA16816(cacc[mi][nj], afr[mi], bfr[nj]);
    }
}

// CTA 128x64
__device__ __forceinline__ void mma_chunk4(const __nv_bfloat16* As, const __nv_bfloat16* Bs,
                                           float cacc[2][4][4], int wm, int wn, int g, int t){
    #pragma unroll
    for (int ks=0;ks<4;ks++){
        int k = ks*16;
        uint32_t afr[2][4], bfr[4][2];
        #pragma unroll
        for (int mi=0;mi<2;mi++){
            const __nv_bfloat16* ap = As + (wm*32 + mi*16)*72 + k + 2*t;
            afr[mi][0] = *(const uint32_t*)(ap + g*72);
            afr[mi][1] = *(const uint32_t*)(ap + (g+8)*72);
            afr[mi][2] = *(const uint32_t*)(ap + g*72 + 8);
            afr[mi][3] = *(const uint32_t*)(ap + (g+8)*72 + 8);
        }
        #pragma unroll
        for (int nj=0;nj<4;nj++){
            const __nv_bfloat16* bp = Bs + (wn*32 + nj*8 + g)*72 + k + 2*t;
            bfr[nj][0] = *(const uint32_t*)(bp);
            bfr[nj][1] = *(const uint32_t*)(bp + 8);
        }
        #pragma unroll
        for (int mi=0;mi<2;mi++)
            #pragma unroll
            for (int nj=0;nj<4;nj++)
                MMA16816(cacc[mi][nj], afr[mi], bfr[nj]);
    }
}

// ================= device state =================
__device__ float d_mem[NN * WW];
__device__ __nv_bfloat16 d_memn[NN * WW];
__device__ __nv_bfloat16 d_memTb[WW * NN];
__device__ float d_h[BB * HH];
__device__ float d_c[BB * HH];
__device__ __nv_bfloat16 d_keysn[256 * WW];
__device__ __nv_bfloat16 d_eradT[256 * BB];
__device__ float d_scal[BB * 4];
__device__ float d_sim[256 * NN];
__device__ float d_pmax[256 * NTSIM];
__device__ float d_rw[BB * NN];
__device__ __nv_bfloat16 d_rwb[BB * NN];
__device__ __nv_bfloat16 d_wwT[NN * BB];
__device__ float d_rv[BB * WW];
__device__ float d_rvpart[RVSPL * BB * WW];
// split-bf16 LSTM
__device__ __nv_bfloat16 d_Whi[G4 * KLSTM];
__device__ __nv_bfloat16 d_Wlo[G4 * KLSTM];
__device__ __nv_bfloat16 d_xhi[BB * SS * INSZ];
__device__ __nv_bfloat16 d_xlo[BB * SS * INSZ];
__device__ __nv_bfloat16 d_hhi[BB * HH];
__device__ __nv_bfloat16 d_hlo[BB * HH];
__device__ __nv_bfloat16 d_rvhi[BB * WW];
__device__ __nv_bfloat16 d_rvlo[BB * WW];
__device__ float d_gpart[2 * BB * G4];
// combined projection
__device__ __nv_bfloat16 d_Pchi[NPROJ * HH];
__device__ __nv_bfloat16 d_Pclo[NPROJ * HH];
__device__ float d_bcomb[NPROJ];
__device__ float d_ppart[2 * BB * NPROJ];

__device__ __forceinline__ float sigmoidf_(float x){ return 1.f/(1.f+__expf(-x)); }
__device__ __forceinline__ float softplusf_(float x){ return x>15.f ? x : log1pf(__expf(x)); }

// row of combined projection matrix P[n][c] (c < CC)
__device__ __forceinline__ float getP(int n, int c,
    const float* rkW, const float* wkW, const float* erW, const float* adW,
    const float* pW, const float* rbW, const float* rgW,
    const float* wbW, const float* wgW){
    if (n < 128)   return rkW[n*CC + c];
    if (n < 256)   return wkW[(n-128)*CC + c];
    if (n < 384)   return erW[(n-256)*CC + c];
    if (n < 512)   return adW[(n-384)*CC + c];
    if (n < 1024)  return (c < 512) ? pW[(size_t)(n-512)*512 + c] : 0.f;
    if (n == 1024) return rbW[c];
    if (n == 1025) return rgW[c];
    if (n == 1026) return wbW[c];
    if (n == 1027) return wgW[c];
    return 0.f;
}

// ================= init =================
__global__ void k_init(const float* __restrict__ memory){
    int i = blockIdx.x*256 + threadIdx.x;
    d_mem[i] = memory[i];
    d_rw[i]  = 1.0f/NN;
    if (i < BB*HH){ d_h[i]=0.f; d_c[i]=0.f;
        d_hhi[i]=__float2bfloat16(0.f); d_hlo[i]=__float2bfloat16(0.f); }
    if (i < BB*WW){ d_rv[i]=0.f;
        d_rvhi[i]=__float2bfloat16(0.f); d_rvlo[i]=__float2bfloat16(0.f); }
}

__global__ void k_wsplit(const float* __restrict__ Wih, const float* __restrict__ Whh){
    int i = blockIdx.x*256 + threadIdx.x;
    int j = i / KLSTM, k = i - j*KLSTM;
    float w = (k < 640) ? Wih[(size_t)j*640 + k] : Whh[(size_t)j*1024 + (k-640)];
    __nv_bfloat16 hi = __float2bfloat16(w);
    d_Whi[i] = hi;
    d_Wlo[i] = __float2bfloat16(w - __bfloat162float(hi));
}

__global__ void k_xsplit(const float* __restrict__ x){
    int i = blockIdx.x*256 + threadIdx.x;
    float v = x[i];
    __nv_bfloat16 hi = __float2bfloat16(v);
    d_xhi[i] = hi;
    d_xlo[i] = __float2bfloat16(v - __bfloat162float(hi));
}

// Wcomb[n][k] = sum_c P[n][c] * Wout[c][k]  (split to bf16 hi/lo)
__global__ void k_wcomb(const float* __restrict__ Wout,
                        const float* rkW, const float* wkW, const float* erW, const float* adW,
                        const float* pW,  const float* rbW, const float* rgW,
                        const float* wbW, const float* wgW){
    __shared__ float As[32][33];   // [c][n]
    __shared__ float Bs[32][33];   // [c][k]
    int n0 = blockIdx.x*32, k0 = blockIdx.y*32;
    int tid = threadIdx.x, tx = tid & 15, ty = tid >> 4;
    int lk = tid & 31, lr = tid >> 5;
    float acc[2][2] = {};
    for (int c0 = 0; c0 < CC; c0 += 32){
        #pragma unroll
        for (int p=0;p<4;p++){
            int i = lr + p*8;
            int c = c0 + lk;
            As[lk][i] = (c < CC) ? getP(n0+i, c, rkW,wkW,erW,adW,pW,rbW,rgW,wbW,wgW) : 0.f;
            int cb = c0 + i;
            Bs[i][lk] = (cb < CC) ? Wout[(size_t)cb*HH + k0 + lk] : 0.f;
        }
        __syncthreads();
        #pragma unroll
        for (int cc=0;cc<32;cc++){
            float a0 = As[cc][ty*2], a1 = As[cc][ty*2+1];
            float b0 = Bs[cc][tx*2], b1 = Bs[cc][tx*2+1];
            acc[0][0]+=a0*b0; acc[0][1]+=a0*b1; acc[1][0]+=a1*b0; acc[1][1]+=a1*b1;
        }
        __syncthreads();
    }
    #pragma unroll
    for (int i=0;i<2;i++)
        #pragma unroll
        for (int j=0;j<2;j++){
            int n = n0 + ty*2+i, k = k0 + tx*2+j;
            float w = acc[i][j];
            __nv_bfloat16 hi = __float2bfloat16(w);
            d_Pchi[(size_t)n*HH + k] = hi;
            d_Pclo[(size_t)n*HH + k] = __float2bfloat16(w - __bfloat162float(hi));
        }
}

__global__ void k_bcomb(const float* __restrict__ bout,
                        const float* rkW, const float* wkW, const float* erW, const float* adW,
                        const float* pW,  const float* rbW, const float* rgW,
                        const float* wbW, const float* wgW,
                        const float* rkb, const float* wkb, const float* erb, const float* adb,
                        const float* pb,  const float* rbb, const float* rgb,
                        const float* wbb, const float* wgb){
    int n = blockIdx.x*256 + threadIdx.x;
    if (n >= NPROJ) return;
    float s = 0.f;
    for (int c = 0; c < CC; c++)
        s += getP(n, c, rkW,wkW,erW,adW,pW,rbW,rgW,wbW,wgW) * bout[c];
    float bias = 0.f;
    if (n < 128)        bias = rkb[n];
    else if (n < 256)   bias = wkb[n-128];
    else if (n < 384)   bias = erb[n-256];
    else if (n < 512)   bias = adb[n-384];
    else if (n < 1024)  bias = pb[n-512];
    else if (n == 1024) bias = rbb[0];
    else if (n == 1025) bias = rgb[0];
    else if (n == 1026) bias = wbb[0];
    else if (n == 1027) bias = wgb[0];
    d_bcomb[n] = s + bias;
}

__global__ void k_rownorm(){
    int row  = blockIdx.x*8 + (threadIdx.x>>5);
    int lane = threadIdx.x & 31;
    const float4* p = (const float4*)(d_mem + (size_t)row*WW);
    float4 v = p[lane];
    float s = v.x*v.x + v.y*v.y + v.z*v.z + v.w*v.w;
    #pragma unroll
    for (int o=16;o;o>>=1) s += __shfl_xor_sync(0xffffffffu, s, o);
    s = __shfl_sync(0xffffffffu, s, 0);
    float inv = 1.f / fmaxf(sqrtf(s), 1e-12f);
    __nv_bfloat162* nm = (__nv_bfloat162*)(d_memn + (size_t)row*WW + lane*4);
    nm[0] = __floats2bfloat162_rn(v.x*inv, v.y*inv);
    nm[1] = __floats2bfloat162_rn(v.z*inv, v.w*inv);
    float vv[4] = {v.x, v.y, v.z, v.w};
    #pragma unroll
    for (int j=0;j<4;j++) d_memTb[(size_t)(lane*4+j)*NN + row] = __float2bfloat16(vv[j]);
}

// ================= LSTM split-bf16 MMA =================
__global__ void __launch_bounds__(256) k_lstmT(int t){
    __shared__ __nv_bfloat16 As[128*72];
    __shared__ __nv_bfloat16 Bs[64*72];
    int tid = threadIdx.x, lane = tid & 31, wid = tid >> 5;
    int wm = wid >> 1, wn = wid & 1, g = lane >> 2, tq = lane & 3;
    int n0 = blockIdx.x*64;
    int ks = blockIdx.y;

    float cacc[2][4][4] = {};
    #pragma unroll
    for (int pass=0; pass<3; pass++){
        const __nv_bfloat16* Wb = (pass==2) ? d_Wlo : d_Whi;
        #pragma unroll
        for (int cc=0; cc<13; cc++){
            int k0 = (ks*13 + cc)*64;
            const __nv_bfloat16* Asrc; size_t lda;
            if (k0 < 512){
                Asrc = ((pass==1) ? d_xlo : d_xhi) + (size_t)t*INSZ + k0; lda = (size_t)SS*INSZ;
            } else if (k0 < 640){
                Asrc = ((pass==1) ? d_rvlo : d_rvhi) + (k0-512); lda = WW;
            } else {
                Asrc = ((pass==1) ? d_hlo : d_hhi) + (k0-640); lda = HH;
            }
            load_chunk(As, Asrc, lda, tid);
            load_chunk64(Bs, Wb + (size_t)n0*KLSTM + k0, KLSTM, tid);
            __syncthreads();
            mma_chunk4(As, Bs, cacc, wm, wn, g, tq);
            __syncthreads();
        }
    }
    float* gp = d_gpart + (size_t)ks*BB*G4;
    #pragma unroll
    for (int mi=0;mi<2;mi++){
        int rl0 = wm*32 + mi*16 + g, rl1 = rl0 + 8;
        #pragma unroll
        for (int nj=0;nj<4;nj++){
            int col = n0 + wn*32 + nj*8 + 2*tq;
            *(float2*)&gp[(size_t)rl0*G4 + col] = make_float2(cacc[mi][nj][0], cacc[mi][nj][1]);
            *(float2*)&gp[(size_t)rl1*G4 + col] = make_float2(cacc[mi][nj][2], cacc[mi][nj][3]);
        }
    }
}

__global__ void k_gates(const float* __restrict__ bih, const float* __restrict__ bhh){
    int i = blockIdx.x*256 + threadIdx.x;
    int b = i >> 10, u = i & 1023;
    const float* g0 = d_gpart + (size_t)b*G4;
    const float* g1 = d_gpart + (size_t)BB*G4 + (size_t)b*G4;
    float gi = g0[u]      + g1[u]      + bih[u]      + bhh[u];
    float gf = g0[1024+u] + g1[1024+u] + bih[1024+u] + bhh[1024+u];
    float gg = g0[2048+u] + g1[2048+u] + bih[2048+u] + bhh[2048+u];
    float go = g0[3072+u] + g1[3072+u] + bih[3072+u] + bhh[3072+u];
    float c = sigmoidf_(gf)*d_c[i] + sigmoidf_(gi)*tanhf(gg);
    float h = sigmoidf_(go)*tanhf(c);
    d_c[i] = c; d_h[i] = h;
    __nv_bfloat16 hi = __float2bfloat16(h);
    d_hhi[i] = hi;
    d_hlo[i] = __float2bfloat16(h - __bfloat162float(hi));
}

// ================= combined projection GEMM: ppart = h @ Wcomb^T =================
__global__ void __launch_bounds__(256) k_projT(){
    __shared__ __nv_bfloat16 As[128*72];
    __shared__ __nv_bfloat16 Bs[64*72];
    int tid = threadIdx.x, lane = tid & 31, wid = tid >> 5;
    int wm = wid >> 1, wn = wid & 1, g = lane >> 2, tq = lane & 3;
    int n0 = blockIdx.x*64;
    int ks = blockIdx.y;

    float cacc[2][4][4] = {};
    #pragma unroll
    for (int pass=0; pass<3; pass++){
        const __nv_bfloat16* Ab = (pass==1) ? d_hlo : d_hhi;
        const __nv_bfloat16* Wb = (pass==2) ? d_Pclo : d_Pchi;
        #pragma unroll
        for (int cc=0; cc<8; cc++){
            int k0 = ks*512 + cc*64;
            load_chunk(As, Ab + k0, HH, tid);
            load_chunk64(Bs, Wb + (size_t)n0*HH + k0, HH, tid);
            __syncthreads();
            mma_chunk4(As, Bs, cacc, wm, wn, g, tq);
            __syncthreads();
        }
    }
    float* gp = d_ppart + (size_t)ks*BB*NPROJ;
    #pragma unroll
    for (int mi=0;mi<2;mi++){
        int rl0 = wm*32 + mi*16 + g, rl1 = rl0 + 8;
        #pragma unroll
        for (int nj=0;nj<4;nj++){
            int col = n0 + wn*32 + nj*8 + 2*tq;
            *(float2*)&gp[(size_t)rl0*NPROJ + col] = make_float2(cacc[mi][nj][0], cacc[mi][nj][1]);
            *(float2*)&gp[(size_t)rl1*NPROJ + col] = make_float2(cacc[mi][nj][2], cacc[mi][nj][3]);
        }
    }
}

// ================= projection epilogue =================
__global__ void k_posproj(float* __restrict__ out, int t){
    __shared__ float pp[1028];
    __shared__ float wsum[8];
    int b = blockIdx.x, tid = threadIdx.x;
    for (int n = tid; n < 1028; n += 256)
        pp[n] = d_ppart[(size_t)b*NPROJ + n]
              + d_ppart[(size_t)(BB+b)*NPROJ + n]
              + d_bcomb[n];
    __syncthreads();

    int half = tid >> 7, w = tid & 127;
    // keys: L2 normalize per (b, head)
    float v = pp[half*128 + w];
    float sq = v*v;
    #pragma unroll
    for (int o=16;o;o>>=1) sq += __shfl_xor_sync(0xffffffffu, sq, o);
    if (!(tid & 31)) wsum[tid >> 5] = sq;
    __syncthreads();
    int base = half*4;
    float s = wsum[base] + wsum[base+1] + wsum[base+2] + wsum[base+3];
    float inv = 1.f / fmaxf(sqrtf(s), 1e-12f);
    d_keysn[(size_t)(half*128 + b)*WW + w] = __float2bfloat16(v*inv);
    // er / ad
    float ev = half ? tanhf(pp[384 + w]) : sigmoidf_(pp[256 + w]);
    d_eradT[(half*128 + w)*BB + b] = __float2bfloat16(ev);
    // out
    for (int o = tid; o < OUTSZ; o += 256)
        out[((size_t)b*SS + t)*OUTSZ + o] = pp[512 + o];
    // scalars
    if (tid < 4){
        float vv = softplusf_(pp[1024 + tid]);
        if (tid & 1) vv += 1.f;
        d_scal[b*4 + tid] = vv;
    }
}

// ================= sim =================
__global__ void __launch_bounds__(256) k_simT(){
    extern __shared__ __nv_bfloat16 smb[];
    __nv_bfloat16* As = smb;
    __nv_bfloat16* Bs = smb + 128*72;
    __shared__ float redm[128][2];
    int tid = threadIdx.x, lane = tid & 31, wid = tid >> 5;
    int wm = wid >> 1, wn = wid & 1, g = lane >> 2, t = lane & 3;
    int m0 = blockIdx.y*128, n0 = blockIdx.x*128;

    float cacc[2][8][4] = {};
    #pragma unroll
    for (int kc=0;kc<2;kc++){
        load_chunk(As, d_keysn + (size_t)m0*WW + kc*64, WW, tid);
        load_chunk(Bs, d_memn  + (size_t)n0*WW + kc*64, WW, tid);
        __syncthreads();
        mma_chunk(As, Bs, cacc, wm, wn, g, t);
        __syncthreads();
    }
    #pragma unroll
    for (int mi=0;mi<2;mi++){
        int rl0 = wm*32 + mi*16 + g, rl1 = rl0 + 8;
        float mx0 = -3.0e38f, mx1 = -3.0e38f;
        #pragma unroll
        for (int nj=0;nj<8;nj++){
            int col = n0 + wn*64 + nj*8 + 2*t;
            float c0 = cacc[mi][nj][0], c1 = cacc[mi][nj][1];
            float c2 = cacc[mi][nj][2], c3 = cacc[mi][nj][3];
            *(float2*)&d_sim[(size_t)(m0+rl0)*NN + col] = make_float2(c0, c1);
            *(float2*)&d_sim[(size_t)(m0+rl1)*NN + col] = make_float2(c2, c3);
            mx0 = fmaxf(mx0, fmaxf(c0, c1));
            mx1 = fmaxf(mx1, fmaxf(c2, c3));
        }
        mx0 = fmaxf(mx0, __shfl_xor_sync(0xffffffffu, mx0, 1));
        mx0 = fmaxf(mx0, __shfl_xor_sync(0xffffffffu, mx0, 2));
        mx1 = fmaxf(mx1, __shfl_xor_sync(0xffffffffu, mx1, 1));
        mx1 = fmaxf(mx1, __shfl_xor_sync(0xffffffffu, mx1, 2));
        if (t == 0){ redm[rl0][wn] = mx0; redm[rl1][wn] = mx1; }
    }
    __syncthreads();
    if (tid < 128)
        d_pmax[(size_t)(m0+tid)*NTSIM + blockIdx.x] = fmaxf(redm[tid][0], redm[tid][1]);
}

// ================= softmax + interpolation =================
__global__ void k_smax(){
    extern __shared__ float esm[];
    __shared__ float red[256];
    int r = blockIdx.x;
    int head = r >> 7, b = r & 127;
    float beta  = d_scal[b*4 + head*2];
    float gamma = d_scal[b*4 + head*2 + 1];
    int tid = threadIdx.x;

    red[tid] = (tid < NTSIM) ? d_pmax[(size_t)r*NTSIM + tid] : -3.0e38f;
    __syncthreads();
    for (int o=128;o;o>>=1){ if (tid<o) red[tid] = fmaxf(red[tid], red[tid+o]); __syncthreads(); }
    float m = red[0];
    __syncthreads();

    const float* simrow = d_sim + (size_t)r*NN;
    float s = 0.f;
    for (int n = tid; n < NN; n += 256){
        float e = __expf(beta*(simrow[n] - m));
        esm[n] = e; s += e;
    }
    red[tid] = s; __syncthreads();
    for (int o=128;o;o>>=1){ if (tid<o) red[tid] += red[tid+o]; __syncthreads(); }
    float inv = 1.f / red[0];

    if (head == 0){
        float* rw = d_rw + (size_t)b*NN;
        __nv_bfloat16* rwb = d_rwb + (size_t)b*NN;
        for (int n = tid; n < NN; n += 256){
            float w = esm[n]*inv;
            float v = gamma*w + (1.f-gamma)*rw[n];
            rw[n] = v;
            rwb[n] = __float2bfloat16(v);
        }
    } else {
        const float u = 1.f/NN;
        for (int n = tid; n < NN; n += 256){
            float w = esm[n]*inv;
            float v = gamma*w + (1.f-gamma)*u;
            d_wwT[(size_t)n*BB + b] = __float2bfloat16(v);
        }
    }
}

// ================= memory update =================
__global__ void __launch_bounds__(256) k_memupdT(){
    extern __shared__ __nv_bfloat16 smb[];
    __nv_bfloat16* As = smb;
    __nv_bfloat16* Bs = smb + 128*72;
    float* Esm = (float*)(smb + 2*128*72);
    __shared__ float redm[128][2];
    __shared__ float invsm[128];
    int tid = threadIdx.x, lane = tid & 31, wid = tid >> 5;
    int wm = wid >> 1, wn = wid & 1, g = lane >> 2, t = lane & 3;
    int q0 = blockIdx.x*128;

    float cacc[2][8][4] = {};
    #pragma unroll
    for (int ph=0; ph<2; ph++){
        #pragma unroll
        for (int kc=0;kc<2;kc++){
            load_chunk(As, d_wwT + (size_t)q0*BB + kc*64, BB, tid);
            load_chunk(Bs, d_eradT + ph*128*BB + kc*64, BB, tid);
            __syncthreads();
            mma_chunk(As, Bs, cacc, wm, wn, g, t);
            __syncthreads();
        }
        if (ph == 0){
            #pragma unroll
            for (int mi=0;mi<2;mi++){
                int rl0 = wm*32 + mi*16 + g, rl1 = rl0 + 8;
                #pragma unroll
                for (int nj=0;nj<8;nj++){
                    int cl = wn*64 + nj*8 + 2*t;
                    Esm[rl0*132 + cl]   = cacc[mi][nj][0];
                    Esm[rl0*132 + cl+1] = cacc[mi][nj][1];
                    Esm[rl1*132 + cl]   = cacc[mi][nj][2];
                    Esm[rl1*132 + cl+1] = cacc[mi][nj][3];
                    cacc[mi][nj][0]=0.f; cacc[mi][nj][1]=0.f;
                    cacc[mi][nj][2]=0.f; cacc[mi][nj][3]=0.f;
                }
            }
        }
    }
    float ssq[2][2] = {};
    #pragma unroll
    for (int mi=0;mi<2;mi++){
        int rl0 = wm*32 + mi*16 + g, rl1 = rl0 + 8;
        #pragma unroll
        for (int nj=0;nj<8;nj++){
            int cl = wn*64 + nj*8 + 2*t;
            float2 m0v = *(const float2*)&d_mem[(size_t)(q0+rl0)*WW + cl];
            float2 m1v = *(const float2*)&d_mem[(size_t)(q0+rl1)*WW + cl];
            float v00 = m0v.x*(1.f - Esm[rl0*132+cl])   + cacc[mi][nj][0];
            float v01 = m0v.y*(1.f - Esm[rl0*132+cl+1]) + cacc[mi][nj][1];
            float v10 = m1v.x*(1.f - Esm[rl1*132+cl])   + cacc[mi][nj][2];
            float v11 = m1v.y*(1.f - Esm[rl1*132+cl+1]) + cacc[mi][nj][3];
            cacc[mi][nj][0]=v00; cacc[mi][nj][1]=v01; cacc[mi][nj][2]=v10; cacc[mi][nj][3]=v11;
            ssq[mi][0] += v00*v00 + v01*v01;
            ssq[mi][1] += v10*v10 + v11*v11;
        }
    }
    #pragma unroll
    for (int mi=0;mi<2;mi++){
        #pragma unroll
        for (int h=0;h<2;h++){
            float s = ssq[mi][h];
            s += __shfl_xor_sync(0xffffffffu, s, 1);
            s += __shfl_xor_sync(0xffffffffu, s, 2);
            if (t == 0) redm[wm*32 + mi*16 + h*8 + g][wn] = s;
        }
    }
    __syncthreads();
    if (tid < 128) invsm[tid] = 1.f / fmaxf(sqrtf(redm[tid][0] + redm[tid][1]), 1e-12f);
    __syncthreads();
    __nv_bfloat16* Vsm = (__nv_bfloat16*)Esm;      // [128][136]
    #pragma unroll
    for (int mi=0;mi<2;mi++){
        int rl0 = wm*32 + mi*16 + g, rl1 = rl0 + 8;
        float i0 = invsm[rl0], i1 = invsm[rl1];
        #pragma unroll
        for (int nj=0;nj<8;nj++){
            int cl = wn*64 + nj*8 + 2*t;
            float v00=cacc[mi][nj][0], v01=cacc[mi][nj][1], v10=cacc[mi][nj][2], v11=cacc[mi][nj][3];
            *(float2*)&d_mem[(size_t)(q0+rl0)*WW + cl] = make_float2(v00, v01);
            *(float2*)&d_mem[(size_t)(q0+rl1)*WW + cl] = make_float2(v10, v11);
            *(__nv_bfloat162*)&d_memn[(size_t)(q0+rl0)*WW + cl] = __floats2bfloat162_rn(v00*i0, v01*i0);
            *(__nv_bfloat162*)&d_memn[(size_t)(q0+rl1)*WW + cl] = __floats2bfloat162_rn(v10*i1, v11*i1);
            Vsm[cl*136 + rl0]     = __float2bfloat16(v00);
            Vsm[(cl+1)*136 + rl0] = __float2bfloat16(v01);
            Vsm[cl*136 + rl1]     = __float2bfloat16(v10);
            Vsm[(cl+1)*136 + rl1] = __float2bfloat16(v11);
        }
    }
    __syncthreads();
    #pragma unroll
    for (int i=0;i<8;i++){
        int idx = tid + i*256;
        int w = idx >> 4, c4 = idx & 15;
        *(uint4*)&d_memTb[(size_t)w*NN + q0 + c4*8] = *(const uint4*)&Vsm[w*136 + c4*8];
    }
}

// ================= rv = rw @ mem (split-K) =================
__global__ void __launch_bounds__(256) k_rvT(){
    extern __shared__ __nv_bfloat16 smb[];
    __nv_bfloat16* As = smb;
    __nv_bfloat16* Bs = smb + 128*72;
    int tid = threadIdx.x, lane = tid & 31, wid = tid >> 5;
    int wm = wid >> 1, wn = wid & 1, g = lane >> 2, t = lane & 3;
    size_t kb = (size_t)blockIdx.x * 512;

    float cacc[2][8][4] = {};
    #pragma unroll
    for (int kc=0;kc<8;kc++){
        load_chunk(As, d_rwb   + kb + kc*64, NN, tid);
        load_chunk(Bs, d_memTb + kb + kc*64, NN, tid);
        __syncthreads();
        mma_chunk(As, Bs, cacc, wm, wn, g, t);
        __syncthreads();
    }
    float* dst = d_rvpart + (size_t)blockIdx.x*BB*WW;
    #pragma unroll
    for (int mi=0;mi<2;mi++){
        int rl0 = wm*32 + mi*16 + g, rl1 = rl0 + 8;
        #pragma unroll
        for (int nj=0;nj<8;nj++){
            int cl = wn*64 + nj*8 + 2*t;
            *(float2*)&dst[(size_t)rl0*WW + cl] = make_float2(cacc[mi][nj][0], cacc[mi][nj][1]);
            *(float2*)&dst[(size_t)rl1*WW + cl] = make_float2(cacc[mi][nj][2], cacc[mi][nj][3]);
        }
    }
}

__global__ void k_rvred(){
    int i = blockIdx.x*256 + threadIdx.x;
    float s = 0.f;
    #pragma unroll
    for (int p=0;p<RVSPL;p++) s += d_rvpart[(size_t)p*16384 + i];
    d_rv[i] = s;
    __nv_bfloat16 hi = __float2bfloat16(s);
    d_rvhi[i] = hi;
    d_rvlo[i] = __float2bfloat16(s - __bfloat162float(hi));
}

// ================= launch =================
extern "C" void kernel_launch(void* const* d_in, const int* in_sizes, int n_in,
                              void* d_out, int out_size){
    const float* x      = (const float*)d_in[0];
    const float* memory = (const float*)d_in[1];
    const float* Wih    = (const float*)d_in[2];
    const float* Whh    = (const float*)d_in[3];
    const float* bih    = (const float*)d_in[4];
    const float* bhh    = (const float*)d_in[5];
    const float* Wout   = (const float*)d_in[6];
    const float* bout   = (const float*)d_in[7];
    const float* rkW    = (const float*)d_in[8];
    const float* rkb    = (const float*)d_in[9];
    const float* rbW    = (const float*)d_in[10];
    const float* rbb    = (const float*)d_in[11];
    const float* rgW    = (const float*)d_in[12];
    const float* rgb    = (const float*)d_in[13];
    const float* wkW    = (const float*)d_in[14];
    const float* wkb    = (const float*)d_in[15];
    const float* wbW    = (const float*)d_in[16];
    const float* wbb    = (const float*)d_in[17];
    const float* wgW    = (const float*)d_in[18];
    const float* wgb    = (const float*)d_in[19];
    const float* erW    = (const float*)d_in[20];
    const float* erb    = (const float*)d_in[21];
    const float* adW    = (const float*)d_in[22];
    const float* adb    = (const float*)d_in[23];
    const float* pW     = (const float*)d_in[24];
    const float* pb     = (const float*)d_in[25];
    float* out = (float*)d_out;

    const int SM_GEMM = 2*128*72*2;
    const int SM_MUPD = SM_GEMM + 128*132*4;
    cudaFuncSetAttribute(k_memupdT, cudaFuncAttributeMaxDynamicSharedMemorySize, SM_MUPD);
    cudaFuncSetAttribute(k_smax,    cudaFuncAttributeMaxDynamicSharedMemorySize, 65536);

    k_init<<<8192, 256>>>(memory);
    k_wsplit<<<G4*KLSTM/256, 256>>>(Wih, Whh);
    k_xsplit<<<BB*SS*INSZ/256, 256>>>(x);
    k_wcomb<<<dim3(NPROJ/32, HH/32), 256>>>(Wout, rkW,wkW,erW,adW,pW,rbW,rgW,wbW,wgW);
    k_bcomb<<<(NPROJ+255)/256, 256>>>(bout, rkW,wkW,erW,adW,pW,rbW,rgW,wbW,wgW,
                                      rkb,wkb,erb,adb,pb,rbb,rgb,wbb,wgb);
    k_rownorm<<<2048, 256>>>();
    for (int t = 0; t < SS; t++){
        k_lstmT<<<dim3(64,2), 256>>>(t);
        k_gates<<<512, 256>>>(bih, bhh);
        k_projT<<<dim3(NPROJ/64, 2), 256>>>();
        k_posproj<<<128, 256>>>(out, t);
        if (t + 1 < SS){
            k_simT<<<dim3(128,2), 256, SM_GEMM>>>();
            k_smax<<<256, 256, 65536>>>();
            k_memupdT<<<128, 256, SM_MUPD>>>();
            k_rvT<<<RVSPL, 256, SM_GEMM>>>();
            k_rvred<<<64, 256>>>();
        }
    }
}

// round 9
// speedup vs baseline: 2.8630x; 1.0065x over previous
#include <cuda_runtime.h>
#include <cuda_bf16.h>
#include <cuda_fp16.h>
#include <cstdint>
#include <stdint.h>
#include <math.h>

#define BB    128
#define SS    32
#define INSZ  512
#define HH    1024
#define OUTSZ 512
#define NN    16384
#define WW    128
#define CC    899
#define G4    4096
#define KLSTM 1664
#define NPROJ 1088
#define NPAD  1152     // padded P rows for MMA
#define KPAD  960      // padded CC for MMA
#define NTSIM 128
#define RVSPL 32

// ================= warp-level bf16 MMA =================
#define MMA16816(c, a, b) \
    asm volatile("mma.sync.aligned.m16n8k16.row.col.f32.bf16.bf16.f32 " \
        "{%0,%1,%2,%3}, {%4,%5,%6,%7}, {%8,%9}, {%0,%1,%2,%3};" \
        : "+f"((c)[0]), "+f"((c)[1]), "+f"((c)[2]), "+f"((c)[3]) \
        : "r"((a)[0]), "r"((a)[1]), "r"((a)[2]), "r"((a)[3]), "r"((b)[0]), "r"((b)[1]))

__device__ __forceinline__ void load_chunk(__nv_bfloat16* sm, const __nv_bfloat16* src,
                                           size_t ld, int tid){
    #pragma unroll
    for (int i=0;i<4;i++){
        int idx = tid + i*256;
        int row = idx >> 3, c4 = idx & 7;
        *(uint4*)(sm + row*72 + c4*8) = *(const uint4*)(src + (size_t)row*ld + c4*8);
    }
}
__device__ __forceinline__ void load_chunk64(__nv_bfloat16* sm, const __nv_bfloat16* src,
                                             size_t ld, int tid){
    #pragma unroll
    for (int i=0;i<2;i++){
        int idx = tid + i*256;
        int row = idx >> 3, c4 = idx & 7;
        *(uint4*)(sm + row*72 + c4*8) = *(const uint4*)(src + (size_t)row*ld + c4*8);
    }
}

// CTA 128x128, 8 warps 4(m)x2(n)
__device__ __forceinline__ void mma_chunk(const __nv_bfloat16* As, const __nv_bfloat16* Bs,
                                          float cacc[2][8][4], int wm, int wn, int g, int t){
    #pragma unroll
    for (int ks=0;ks<4;ks++){
        int k = ks*16;
        uint32_t afr[2][4], bfr[8][2];
        #pragma unroll
        for (int mi=0;mi<2;mi++){
            const __nv_bfloat16* ap = As + (wm*32 + mi*16)*72 + k + 2*t;
            afr[mi][0] = *(const uint32_t*)(ap + g*72);
            afr[mi][1] = *(const uint32_t*)(ap + (g+8)*72);
            afr[mi][2] = *(const uint32_t*)(ap + g*72 + 8);
            afr[mi][3] = *(const uint32_t*)(ap + (g+8)*72 + 8);
        }
        #pragma unroll
        for (int nj=0;nj<8;nj++){
            const __nv_bfloat16* bp = Bs + (wn*64 + nj*8 + g)*72 + k + 2*t;
            bfr[nj][0] = *(const uint32_t*)(bp);
            bfr[nj][1] = *(const uint32_t*)(bp + 8);
        }
        #pragma unroll
        for (int mi=0;mi<2;mi++)
            #pragma unroll
            for (int nj=0;nj<8;nj++)
                MMA16816(cacc[mi][nj], afr[mi], bfr[nj]);
    }
}

// CTA 128x64
__device__ __forceinline__ void mma_chunk4(const __nv_bfloat16* As, const __nv_bfloat16* Bs,
                                           float cacc[2][4][4], int wm, int wn, int g, int t){
    #pragma unroll
    for (int ks=0;ks<4;ks++){
        int k = ks*16;
        uint32_t afr[2][4], bfr[4][2];
        #pragma unroll
        for (int mi=0;mi<2;mi++){
            const __nv_bfloat16* ap = As + (wm*32 + mi*16)*72 + k + 2*t;
            afr[mi][0] = *(const uint32_t*)(ap + g*72);
            afr[mi][1] = *(const uint32_t*)(ap + (g+8)*72);
            afr[mi][2] = *(const uint32_t*)(ap + g*72 + 8);
            afr[mi][3] = *(const uint32_t*)(ap + (g+8)*72 + 8);
        }
        #pragma unroll
        for (int nj=0;nj<4;nj++){
            const __nv_bfloat16* bp = Bs + (wn*32 + nj*8 + g)*72 + k + 2*t;
            bfr[nj][0] = *(const uint32_t*)(bp);
            bfr[nj][1] = *(const uint32_t*)(bp + 8);
        }
        #pragma unroll
        for (int mi=0;mi<2;mi++)
            #pragma unroll
            for (int nj=0;nj<4;nj++)
                MMA16816(cacc[mi][nj], afr[mi], bfr[nj]);
    }
}

// ================= device state =================
__device__ float d_mem[NN * WW];
__device__ __nv_bfloat16 d_memn[NN * WW];
__device__ __nv_bfloat16 d_memTb[WW * NN];
__device__ float d_c[BB * HH];
__device__ __nv_bfloat16 d_keysn[256 * WW];
__device__ __nv_bfloat16 d_eradT[256 * BB];
__device__ float d_scal[BB * 4];
__device__ __half d_sim[256 * NN];
__device__ float d_pmax[256 * NTSIM];
__device__ float d_rw[BB * NN];
__device__ __nv_bfloat16 d_rwb[BB * NN];
__device__ __nv_bfloat16 d_wwT[NN * BB];
__device__ float d_rvpart[RVSPL * BB * WW];
// split-bf16 LSTM (gate-interleaved row order: row = u*4 + gate)
__device__ __nv_bfloat16 d_Whi[G4 * KLSTM];
__device__ __nv_bfloat16 d_Wlo[G4 * KLSTM];
__device__ __nv_bfloat16 d_xhi[BB * SS * INSZ];
__device__ __nv_bfloat16 d_xlo[BB * SS * INSZ];
__device__ __nv_bfloat16 d_hhi[BB * HH];
__device__ __nv_bfloat16 d_hlo[BB * HH];
__device__ __nv_bfloat16 d_rvhi[BB * WW];
__device__ __nv_bfloat16 d_rvlo[BB * WW];
__device__ float d_gpart[2 * BB * G4];
// combined projection
__device__ __nv_bfloat16 d_PAhi[NPAD * KPAD];
__device__ __nv_bfloat16 d_PAlo[NPAD * KPAD];
__device__ __nv_bfloat16 d_WoThi[HH * KPAD];
__device__ __nv_bfloat16 d_WoTlo[HH * KPAD];
__device__ __nv_bfloat16 d_Pchi[NPROJ * HH];
__device__ __nv_bfloat16 d_Pclo[NPROJ * HH];
__device__ float d_bcomb[NPROJ];
__device__ float d_ppart[2 * BB * NPROJ];
// completion counters (monotonic within replay; zeroed by k_init)
__device__ int d_gcnt[64];
__device__ int d_rvcnt;

__device__ __forceinline__ float sigmoidf_(float x){ return 1.f/(1.f+__expf(-x)); }
__device__ __forceinline__ float softplusf_(float x){ return x>15.f ? x : log1pf(__expf(x)); }

__device__ __forceinline__ float getP(int n, int c,
    const float* rkW, const float* wkW, const float* erW, const float* adW,
    const float* pW, const float* rbW, const float* rgW,
    const float* wbW, const float* wgW){
    if (n < 128)   return rkW[n*CC + c];
    if (n < 256)   return wkW[(n-128)*CC + c];
    if (n < 384)   return erW[(n-256)*CC + c];
    if (n < 512)   return adW[(n-384)*CC + c];
    if (n < 1024)  return (c < 512) ? pW[(size_t)(n-512)*512 + c] : 0.f;
    if (n == 1024) return rbW[c];
    if (n == 1025) return rgW[c];
    if (n == 1026) return wbW[c];
    if (n == 1027) return wgW[c];
    return 0.f;
}

// ================= init =================
__global__ void k_init(const float* __restrict__ memory){
    int i = blockIdx.x*256 + threadIdx.x;
    d_mem[i] = memory[i];
    d_rw[i]  = 1.0f/NN;
    if (i < BB*HH){ d_c[i]=0.f;
        d_hhi[i]=__float2bfloat16(0.f); d_hlo[i]=__float2bfloat16(0.f); }
    if (i < BB*WW){
        d_rvhi[i]=__float2bfloat16(0.f); d_rvlo[i]=__float2bfloat16(0.f); }
    if (i < 64) d_gcnt[i] = 0;
    if (i == 64) d_rvcnt = 0;
}

// split + gate-interleave rows: new row = u*4 + gate
__global__ void k_wsplit(const float* __restrict__ Wih, const float* __restrict__ Whh){
    int i = blockIdx.x*256 + threadIdx.x;
    int j = i / KLSTM, k = i - j*KLSTM;
    float w = (k < 640) ? Wih[(size_t)j*640 + k] : Whh[(size_t)j*1024 + (k-640)];
    int u = j & 1023, gate = j >> 10;
    size_t jn = (size_t)(u*4 + gate)*KLSTM + k;
    __nv_bfloat16 hi = __float2bfloat16(w);
    d_Whi[jn] = hi;
    d_Wlo[jn] = __float2bfloat16(w - __bfloat162float(hi));
}

__global__ void k_xsplit(const float* __restrict__ x){
    int i = blockIdx.x*256 + threadIdx.x;
    float v = x[i];
    __nv_bfloat16 hi = __float2bfloat16(v);
    d_xhi[i] = hi;
    d_xlo[i] = __float2bfloat16(v - __bfloat162float(hi));
}

// P rows -> padded bf16 hi/lo [NPAD x KPAD]
__global__ void k_psplit(const float* rkW, const float* wkW, const float* erW, const float* adW,
                         const float* pW,  const float* rbW, const float* rgW,
                         const float* wbW, const float* wgW){
    int i = blockIdx.x*256 + threadIdx.x;          // NPAD*KPAD
    int n = i / KPAD, c = i - n*KPAD;
    float v = (c < CC && n < NPROJ) ? getP(n, c, rkW,wkW,erW,adW,pW,rbW,rgW,wbW,wgW) : 0.f;
    __nv_bfloat16 hi = __float2bfloat16(v);
    d_PAhi[i] = hi;
    d_PAlo[i] = __float2bfloat16(v - __bfloat162float(hi));
}

// Wout^T -> bf16 hi/lo [HH x KPAD] (tiled transpose)
__global__ void k_woutT(const float* __restrict__ Wout){
    __shared__ float tile[32][33];
    int k0 = blockIdx.x*32, c0 = blockIdx.y*32;
    int tx = threadIdx.x & 31, ty = threadIdx.x >> 5;   // 8 rows per pass
    #pragma unroll
    for (int r=0;r<32;r+=8){
        int c = c0 + ty + r;
        tile[ty+r][tx] = (c < CC) ? Wout[(size_t)c*HH + k0 + tx] : 0.f;
    }
    __syncthreads();
    #pragma unroll
    for (int r=0;r<32;r+=8){
        int k = k0 + ty + r;
        float v = tile[tx][ty+r];
        __nv_bfloat16 hi = __float2bfloat16(v);
        d_WoThi[(size_t)k*KPAD + c0 + tx] = hi;
        d_WoTlo[(size_t)k*KPAD + c0 + tx] = __float2bfloat16(v - __bfloat162float(hi));
    }
}

// Wcomb[n][k] = sum_c P[n][c] * WoutT[k][c]  (split-bf16 MMA, CTA 128x64)
__global__ void __launch_bounds__(256) k_wcombT(){
    __shared__ __nv_bfloat16 As[128*72];
    __shared__ __nv_bfloat16 Bs[64*72];
    int tid = threadIdx.x, lane = tid & 31, wid = tid >> 5;
    int wm = wid >> 1, wn = wid & 1, g = lane >> 2, tq = lane & 3;
    int m0 = blockIdx.x*128;      // P-row tile
    int n0 = blockIdx.y*64;       // k-col tile

    float cacc[2][4][4] = {};
    #pragma unroll
    for (int pass=0; pass<3; pass++){
        const __nv_bfloat16* Ab = (pass==1) ? d_PAlo : d_PAhi;
        const __nv_bfloat16* Wb = (pass==2) ? d_WoTlo : d_WoThi;
        #pragma unroll
        for (int cc=0; cc<15; cc++){
            int k0 = cc*64;
            load_chunk(As, Ab + (size_t)m0*KPAD + k0, KPAD, tid);
            load_chunk64(Bs, Wb + (size_t)n0*KPAD + k0, KPAD, tid);
            __syncthreads();
            mma_chunk4(As, Bs, cacc, wm, wn, g, tq);
            __syncthreads();
        }
    }
    #pragma unroll
    for (int mi=0;mi<2;mi++){
        int rl0 = wm*32 + mi*16 + g, rl1 = rl0 + 8;
        #pragma unroll
        for (int nj=0;nj<4;nj++){
            int col = n0 + wn*32 + nj*8 + 2*tq;
            #pragma unroll
            for (int hh=0;hh<2;hh++){
                int row = m0 + (hh ? rl1 : rl0);
                if (row < NPROJ){
                    float w0 = cacc[mi][nj][hh*2], w1 = cacc[mi][nj][hh*2+1];
                    __nv_bfloat16 h0 = __float2bfloat16(w0), h1 = __float2bfloat16(w1);
                    d_Pchi[(size_t)row*HH + col]   = h0;
                    d_Pchi[(size_t)row*HH + col+1] = h1;
                    d_Pclo[(size_t)row*HH + col]   = __float2bfloat16(w0 - __bfloat162float(h0));
                    d_Pclo[(size_t)row*HH + col+1] = __float2bfloat16(w1 - __bfloat162float(h1));
                }
            }
        }
    }
}

__global__ void k_bcomb(const float* __restrict__ bout,
                        const float* rkW, const float* wkW, const float* erW, const float* adW,
                        const float* pW,  const float* rbW, const float* rgW,
                        const float* wbW, const float* wgW,
                        const float* rkb, const float* wkb, const float* erb, const float* adb,
                        const float* pb,  const float* rbb, const float* rgb,
                        const float* wbb, const float* wgb){
    int n = blockIdx.x*256 + threadIdx.x;
    if (n >= NPROJ) return;
    float s = 0.f;
    for (int c = 0; c < CC; c++)
        s += getP(n, c, rkW,wkW,erW,adW,pW,rbW,rgW,wbW,wgW) * bout[c];
    float bias = 0.f;
    if (n < 128)        bias = rkb[n];
    else if (n < 256)   bias = wkb[n-128];
    else if (n < 384)   bias = erb[n-256];
    else if (n < 512)   bias = adb[n-384];
    else if (n < 1024)  bias = pb[n-512];
    else if (n == 1024) bias = rbb[0];
    else if (n == 1025) bias = rgb[0];
    else if (n == 1026) bias = wbb[0];
    else if (n == 1027) bias = wgb[0];
    d_bcomb[n] = s + bias;
}

__global__ void k_rownorm(){
    int row  = blockIdx.x*8 + (threadIdx.x>>5);
    int lane = threadIdx.x & 31;
    const float4* p = (const float4*)(d_mem + (size_t)row*WW);
    float4 v = p[lane];
    float s = v.x*v.x + v.y*v.y + v.z*v.z + v.w*v.w;
    #pragma unroll
    for (int o=16;o;o>>=1) s += __shfl_xor_sync(0xffffffffu, s, o);
    s = __shfl_sync(0xffffffffu, s, 0);
    float inv = 1.f / fmaxf(sqrtf(s), 1e-12f);
    __nv_bfloat162* nm = (__nv_bfloat162*)(d_memn + (size_t)row*WW + lane*4);
    nm[0] = __floats2bfloat162_rn(v.x*inv, v.y*inv);
    nm[1] = __floats2bfloat162_rn(v.z*inv, v.w*inv);
    float vv[4] = {v.x, v.y, v.z, v.w};
    #pragma unroll
    for (int j=0;j<4;j++) d_memTb[(size_t)(lane*4+j)*NN + row] = __float2bfloat16(vv[j]);
}

// ================= LSTM split-bf16 MMA + fused gates =================
__global__ void __launch_bounds__(256) k_lstmT(int t, const float* __restrict__ bih,
                                               const float* __restrict__ bhh){
    __shared__ __nv_bfloat16 As[128*72];
    __shared__ __nv_bfloat16 Bs[64*72];
    __shared__ int lastflag;
    int tid = threadIdx.x, lane = tid & 31, wid = tid >> 5;
    int wm = wid >> 1, wn = wid & 1, g = lane >> 2, tq = lane & 3;
    int n0 = blockIdx.x*64;
    int ks = blockIdx.y;

    float cacc[2][4][4] = {};
    #pragma unroll
    for (int pass=0; pass<3; pass++){
        const __nv_bfloat16* Wb = (pass==2) ? d_Wlo : d_Whi;
        #pragma unroll
        for (int cc=0; cc<13; cc++){
            int k0 = (ks*13 + cc)*64;
            const __nv_bfloat16* Asrc; size_t lda;
            if (k0 < 512){
                Asrc = ((pass==1) ? d_xlo : d_xhi) + (size_t)t*INSZ + k0; lda = (size_t)SS*INSZ;
            } else if (k0 < 640){
                Asrc = ((pass==1) ? d_rvlo : d_rvhi) + (k0-512); lda = WW;
            } else {
                Asrc = ((pass==1) ? d_hlo : d_hhi) + (k0-640); lda = HH;
            }
            load_chunk(As, Asrc, lda, tid);
            load_chunk64(Bs, Wb + (size_t)n0*KLSTM + k0, KLSTM, tid);
            __syncthreads();
            mma_chunk4(As, Bs, cacc, wm, wn, g, tq);
            __syncthreads();
        }
    }
    float* gp = d_gpart + (size_t)ks*BB*G4;
    #pragma unroll
    for (int mi=0;mi<2;mi++){
        int rl0 = wm*32 + mi*16 + g, rl1 = rl0 + 8;
        #pragma unroll
        for (int nj=0;nj<4;nj++){
            int col = n0 + wn*32 + nj*8 + 2*tq;
            *(float2*)&gp[(size_t)rl0*G4 + col] = make_float2(cacc[mi][nj][0], cacc[mi][nj][1]);
            *(float2*)&gp[(size_t)rl1*G4 + col] = make_float2(cacc[mi][nj][2], cacc[mi][nj][3]);
        }
    }
    // fused gates: last of the 2 split-K CTAs for this tile finishes the job
    __threadfence();
    __syncthreads();
    if (tid == 0){
        int old = atomicAdd(&d_gcnt[blockIdx.x], 1);
        lastflag = (old == 2*t + 1);
    }
    __syncthreads();
    if (lastflag){
        const float* p0 = d_gpart;
        const float* p1 = d_gpart + (size_t)BB*G4;
        int u0 = n0 >> 2;    // 16 units per tile, gate-interleaved columns
        #pragma unroll
        for (int p=0;p<8;p++){
            int pair = tid + p*256;            // 2048 = 128b x 16u
            int b = pair >> 4, ul = pair & 15;
            int u = u0 + ul;
            size_t base = (size_t)b*G4 + u*4;
            float4 a0 = *(const float4*)&p0[base];
            float4 a1 = *(const float4*)&p1[base];
            float gi = a0.x + a1.x + bih[u]      + bhh[u];
            float gf = a0.y + a1.y + bih[1024+u] + bhh[1024+u];
            float gg = a0.z + a1.z + bih[2048+u] + bhh[2048+u];
            float go = a0.w + a1.w + bih[3072+u] + bhh[3072+u];
            int i = b*HH + u;
            float c = sigmoidf_(gf)*d_c[i] + sigmoidf_(gi)*tanhf(gg);
            float h = sigmoidf_(go)*tanhf(c);
            d_c[i] = c;
            __nv_bfloat16 hi = __float2bfloat16(h);
            d_hhi[i] = hi;
            d_hlo[i] = __float2bfloat16(h - __bfloat162float(hi));
        }
    }
}

// ================= combined projection GEMM =================
__global__ void __launch_bounds__(256) k_projT(){
    __shared__ __nv_bfloat16 As[128*72];
    __shared__ __nv_bfloat16 Bs[64*72];
    int tid = threadIdx.x, lane = tid & 31, wid = tid >> 5;
    int wm = wid >> 1, wn = wid & 1, g = lane >> 2, tq = lane & 3;
    int n0 = blockIdx.x*64;
    int ks = blockIdx.y;

    float cacc[2][4][4] = {};
    #pragma unroll
    for (int pass=0; pass<3; pass++){
        const __nv_bfloat16* Ab = (pass==1) ? d_hlo : d_hhi;
        const __nv_bfloat16* Wb = (pass==2) ? d_Pclo : d_Pchi;
        #pragma unroll
        for (int cc=0; cc<8; cc++){
            int k0 = ks*512 + cc*64;
            load_chunk(As, Ab + k0, HH, tid);
            load_chunk64(Bs, Wb + (size_t)n0*HH + k0, HH, tid);
            __syncthreads();
            mma_chunk4(As, Bs, cacc, wm, wn, g, tq);
            __syncthreads();
        }
    }
    float* gp = d_ppart + (size_t)ks*BB*NPROJ;
    #pragma unroll
    for (int mi=0;mi<2;mi++){
        int rl0 = wm*32 + mi*16 + g, rl1 = rl0 + 8;
        #pragma unroll
        for (int nj=0;nj<4;nj++){
            int col = n0 + wn*32 + nj*8 + 2*tq;
            *(float2*)&gp[(size_t)rl0*NPROJ + col] = make_float2(cacc[mi][nj][0], cacc[mi][nj][1]);
            *(float2*)&gp[(size_t)rl1*NPROJ + col] = make_float2(cacc[mi][nj][2], cacc[mi][nj][3]);
        }
    }
}

// ================= projection epilogue =================
__global__ void k_posproj(float* __restrict__ out, int t){
    __shared__ float pp[1028];
    __shared__ float wsum[8];
    int b = blockIdx.x, tid = threadIdx.x;
    for (int n = tid; n < 1028; n += 256)
        pp[n] = d_ppart[(size_t)b*NPROJ + n]
              + d_ppart[(size_t)(BB+b)*NPROJ + n]
              + d_bcomb[n];
    __syncthreads();

    int half = tid >> 7, w = tid & 127;
    float v = pp[half*128 + w];
    float sq = v*v;
    #pragma unroll
    for (int o=16;o;o>>=1) sq += __shfl_xor_sync(0xffffffffu, sq, o);
    if (!(tid & 31)) wsum[tid >> 5] = sq;
    __syncthreads();
    int base = half*4;
    float s = wsum[base] + wsum[base+1] + wsum[base+2] + wsum[base+3];
    float inv = 1.f / fmaxf(sqrtf(s), 1e-12f);
    d_keysn[(size_t)(half*128 + b)*WW + w] = __float2bfloat16(v*inv);
    float ev = half ? tanhf(pp[384 + w]) : sigmoidf_(pp[256 + w]);
    d_eradT[(half*128 + w)*BB + b] = __float2bfloat16(ev);
    for (int o = tid; o < OUTSZ; o += 256)
        out[((size_t)b*SS + t)*OUTSZ + o] = pp[512 + o];
    if (tid < 4){
        float vv = softplusf_(pp[1024 + tid]);
        if (tid & 1) vv += 1.f;
        d_scal[b*4 + tid] = vv;
    }
}

// ================= sim (fp16 output) =================
__global__ void __launch_bounds__(256) k_simT(){
    extern __shared__ __nv_bfloat16 smb[];
    __nv_bfloat16* As = smb;
    __nv_bfloat16* Bs = smb + 128*72;
    __shared__ float redm[128][2];
    int tid = threadIdx.x, lane = tid & 31, wid = tid >> 5;
    int wm = wid >> 1, wn = wid & 1, g = lane >> 2, t = lane & 3;
    int m0 = blockIdx.y*128, n0 = blockIdx.x*128;

    float cacc[2][8][4] = {};
    #pragma unroll
    for (int kc=0;kc<2;kc++){
        load_chunk(As, d_keysn + (size_t)m0*WW + kc*64, WW, tid);
        load_chunk(Bs, d_memn  + (size_t)n0*WW + kc*64, WW, tid);
        __syncthreads();
        mma_chunk(As, Bs, cacc, wm, wn, g, t);
        __syncthreads();
    }
    #pragma unroll
    for (int mi=0;mi<2;mi++){
        int rl0 = wm*32 + mi*16 + g, rl1 = rl0 + 8;
        float mx0 = -3.0e38f, mx1 = -3.0e38f;
        #pragma unroll
        for (int nj=0;nj<8;nj++){
            int col = n0 + wn*64 + nj*8 + 2*t;
            float c0 = cacc[mi][nj][0], c1 = cacc[mi][nj][1];
            float c2 = cacc[mi][nj][2], c3 = cacc[mi][nj][3];
            *(__half2*)&d_sim[(size_t)(m0+rl0)*NN + col] = __floats2half2_rn(c0, c1);
            *(__half2*)&d_sim[(size_t)(m0+rl1)*NN + col] = __floats2half2_rn(c2, c3);
            mx0 = fmaxf(mx0, fmaxf(c0, c1));
            mx1 = fmaxf(mx1, fmaxf(c2, c3));
        }
        mx0 = fmaxf(mx0, __shfl_xor_sync(0xffffffffu, mx0, 1));
        mx0 = fmaxf(mx0, __shfl_xor_sync(0xffffffffu, mx0, 2));
        mx1 = fmaxf(mx1, __shfl_xor_sync(0xffffffffu, mx1, 1));
        mx1 = fmaxf(mx1, __shfl_xor_sync(0xffffffffu, mx1, 2));
        if (t == 0){ redm[rl0][wn] = mx0; redm[rl1][wn] = mx1; }
    }
    __syncthreads();
    if (tid < 128)
        d_pmax[(size_t)(m0+tid)*NTSIM + blockIdx.x] = fmaxf(redm[tid][0], redm[tid][1]);
}

// ================= softmax + interpolation =================
__global__ void k_smax(){
    extern __shared__ float esm[];
    __shared__ float red[256];
    int r = blockIdx.x;
    int head = r >> 7, b = r & 127;
    float beta  = d_scal[b*4 + head*2];
    float gamma = d_scal[b*4 + head*2 + 1];
    int tid = threadIdx.x;

    red[tid] = (tid < NTSIM) ? d_pmax[(size_t)r*NTSIM + tid] : -3.0e38f;
    __syncthreads();
    for (int o=128;o;o>>=1){ if (tid<o) red[tid] = fmaxf(red[tid], red[tid+o]); __syncthreads(); }
    float m = red[0];
    __syncthreads();

    const __half* simrow = d_sim + (size_t)r*NN;
    float s = 0.f;
    for (int n = tid; n < NN; n += 256){
        float e = __expf(beta*(__half2float(simrow[n]) - m));
        esm[n] = e; s += e;
    }
    red[tid] = s; __syncthreads();
    for (int o=128;o;o>>=1){ if (tid<o) red[tid] += red[tid+o]; __syncthreads(); }
    float inv = 1.f / red[0];

    if (head == 0){
        float* rw = d_rw + (size_t)b*NN;
        __nv_bfloat16* rwb = d_rwb + (size_t)b*NN;
        for (int n = tid; n < NN; n += 256){
            float w = esm[n]*inv;
            float v = gamma*w + (1.f-gamma)*rw[n];
            rw[n] = v;
            rwb[n] = __float2bfloat16(v);
        }
    } else {
        const float u = 1.f/NN;
        for (int n = tid; n < NN; n += 256){
            float w = esm[n]*inv;
            float v = gamma*w + (1.f-gamma)*u;
            d_wwT[(size_t)n*BB + b] = __float2bfloat16(v);
        }
    }
}

// ================= memory update =================
__global__ void __launch_bounds__(256) k_memupdT(){
    extern __shared__ __nv_bfloat16 smb[];
    __nv_bfloat16* As = smb;
    __nv_bfloat16* Bs = smb + 128*72;
    float* Esm = (float*)(smb + 2*128*72);
    __shared__ float redm[128][2];
    __shared__ float invsm[128];
    int tid = threadIdx.x, lane = tid & 31, wid = tid >> 5;
    int wm = wid >> 1, wn = wid & 1, g = lane >> 2, t = lane & 3;
    int q0 = blockIdx.x*128;

    float cacc[2][8][4] = {};
    #pragma unroll
    for (int ph=0; ph<2; ph++){
        #pragma unroll
        for (int kc=0;kc<2;kc++){
            load_chunk(As, d_wwT + (size_t)q0*BB + kc*64, BB, tid);
            load_chunk(Bs, d_eradT + ph*128*BB + kc*64, BB, tid);
            __syncthreads();
            mma_chunk(As, Bs, cacc, wm, wn, g, t);
            __syncthreads();
        }
        if (ph == 0){
            #pragma unroll
            for (int mi=0;mi<2;mi++){
                int rl0 = wm*32 + mi*16 + g, rl1 = rl0 + 8;
                #pragma unroll
                for (int nj=0;nj<8;nj++){
                    int cl = wn*64 + nj*8 + 2*t;
                    Esm[rl0*132 + cl]   = cacc[mi][nj][0];
                    Esm[rl0*132 + cl+1] = cacc[mi][nj][1];
                    Esm[rl1*132 + cl]   = cacc[mi][nj][2];
                    Esm[rl1*132 + cl+1] = cacc[mi][nj][3];
                    cacc[mi][nj][0]=0.f; cacc[mi][nj][1]=0.f;
                    cacc[mi][nj][2]=0.f; cacc[mi][nj][3]=0.f;
                }
            }
        }
    }
    float ssq[2][2] = {};
    #pragma unroll
    for (int mi=0;mi<2;mi++){
        int rl0 = wm*32 + mi*16 + g, rl1 = rl0 + 8;
        #pragma unroll
        for (int nj=0;nj<8;nj++){
            int cl = wn*64 + nj*8 + 2*t;
            float2 m0v = *(const float2*)&d_mem[(size_t)(q0+rl0)*WW + cl];
            float2 m1v = *(const float2*)&d_mem[(size_t)(q0+rl1)*WW + cl];
            float v00 = m0v.x*(1.f - Esm[rl0*132+cl])   + cacc[mi][nj][0];
            float v01 = m0v.y*(1.f - Esm[rl0*132+cl+1]) + cacc[mi][nj][1];
            float v10 = m1v.x*(1.f - Esm[rl1*132+cl])   + cacc[mi][nj][2];
            float v11 = m1v.y*(1.f - Esm[rl1*132+cl+1]) + cacc[mi][nj][3];
            cacc[mi][nj][0]=v00; cacc[mi][nj][1]=v01; cacc[mi][nj][2]=v10; cacc[mi][nj][3]=v11;
            ssq[mi][0] += v00*v00 + v01*v01;
            ssq[mi][1] += v10*v10 + v11*v11;
        }
    }
    #pragma unroll
    for (int mi=0;mi<2;mi++){
        #pragma unroll
        for (int h=0;h<2;h++){
            float s = ssq[mi][h];
            s += __shfl_xor_sync(0xffffffffu, s, 1);
            s += __shfl_xor_sync(0xffffffffu, s, 2);
            if (t == 0) redm[wm*32 + mi*16 + h*8 + g][wn] = s;
        }
    }
    __syncthreads();
    if (tid < 128) invsm[tid] = 1.f / fmaxf(sqrtf(redm[tid][0] + redm[tid][1]), 1e-12f);
    __syncthreads();
    __nv_bfloat16* Vsm = (__nv_bfloat16*)Esm;      // [128][136]
    #pragma unroll
    for (int mi=0;mi<2;mi++){
        int rl0 = wm*32 + mi*16 + g, rl1 = rl0 + 8;
        float i0 = invsm[rl0], i1 = invsm[rl1];
        #pragma unroll
        for (int nj=0;nj<8;nj++){
            int cl = wn*64 + nj*8 + 2*t;
            float v00=cacc[mi][nj][0], v01=cacc[mi][nj][1], v10=cacc[mi][nj][2], v11=cacc[mi][nj][3];
            *(float2*)&d_mem[(size_t)(q0+rl0)*WW + cl] = make_float2(v00, v01);
            *(float2*)&d_mem[(size_t)(q0+rl1)*WW + cl] = make_float2(v10, v11);
            *(__nv_bfloat162*)&d_memn[(size_t)(q0+rl0)*WW + cl] = __floats2bfloat162_rn(v00*i0, v01*i0);
            *(__nv_bfloat162*)&d_memn[(size_t)(q0+rl1)*WW + cl] = __floats2bfloat162_rn(v10*i1, v11*i1);
            Vsm[cl*136 + rl0]     = __float2bfloat16(v00);
            Vsm[(cl+1)*136 + rl0] = __float2bfloat16(v01);
            Vsm[cl*136 + rl1]     = __float2bfloat16(v10);
            Vsm[(cl+1)*136 + rl1] = __float2bfloat16(v11);
        }
    }
    __syncthreads();
    #pragma unroll
    for (int i=0;i<8;i++){
        int idx = tid + i*256;
        int w = idx >> 4, c4 = idx & 15;
        *(uint4*)&d_memTb[(size_t)w*NN + q0 + c4*8] = *(const uint4*)&Vsm[w*136 + c4*8];
    }
}

// ================= rv = rw @ mem (split-K + fused reduction) =================
__global__ void __launch_bounds__(256) k_rvT(int iter){
    extern __shared__ __nv_bfloat16 smb[];
    __nv_bfloat16* As = smb;
    __nv_bfloat16* Bs = smb + 128*72;
    int tid = threadIdx.x, lane = tid & 31, wid = tid >> 5;
    int wm = wid >> 1, wn = wid & 1, g = lane >> 2, t = lane & 3;
    size_t kb = (size_t)blockIdx.x * 512;

    float cacc[2][8][4] = {};
    #pragma unroll
    for (int kc=0;kc<8;kc++){
        load_chunk(As, d_rwb   + kb + kc*64, NN, tid);
        load_chunk(Bs, d_memTb + kb + kc*64, NN, tid);
        __syncthreads();
        mma_chunk(As, Bs, cacc, wm, wn, g, t);
        __syncthreads();
    }
    float* dst = d_rvpart + (size_t)blockIdx.x*BB*WW;
    #pragma unroll
    for (int mi=0;mi<2;mi++){
        int rl0 = wm*32 + mi*16 + g, rl1 = rl0 + 8;
        #pragma unroll
        for (int nj=0;nj<8;nj++){
            int cl = wn*64 + nj*8 + 2*t;
            *(float2*)&dst[(size_t)rl0*WW + cl] = make_float2(cacc[mi][nj][0], cacc[mi][nj][1]);
            *(float2*)&dst[(size_t)rl1*WW + cl] = make_float2(cacc[mi][nj][2], cacc[mi][nj][3]);
        }
    }
    // fused reduction: all 32 CTAs resident -> spin until all partials landed
    __threadfence();
    __syncthreads();
    if (tid == 0){
        atomicAdd(&d_rvcnt, 1);
        int target = 32*(iter+1);
        while (atomicAdd(&d_rvcnt, 0) < target) {}
    }
    __syncthreads();
    #pragma unroll
    for (int rep=0; rep<2; rep++){
        int idx = blockIdx.x*512 + tid + rep*256;
        float s = 0.f;
        #pragma unroll
        for (int p=0;p<RVSPL;p++) s += d_rvpart[(size_t)p*16384 + idx];
        __nv_bfloat16 hi = __float2bfloat16(s);
        d_rvhi[idx] = hi;
        d_rvlo[idx] = __float2bfloat16(s - __bfloat162float(hi));
    }
}

// ================= launch =================
extern "C" void kernel_launch(void* const* d_in, const int* in_sizes, int n_in,
                              void* d_out, int out_size){
    const float* x      = (const float*)d_in[0];
    const float* memory = (const float*)d_in[1];
    const float* Wih    = (const float*)d_in[2];
    const float* Whh    = (const float*)d_in[3];
    const float* bih    = (const float*)d_in[4];
    const float* bhh    = (const float*)d_in[5];
    const float* Wout   = (const float*)d_in[6];
    const float* bout   = (const float*)d_in[7];
    const float* rkW    = (const float*)d_in[8];
    const float* rkb    = (const float*)d_in[9];
    const float* rbW    = (const float*)d_in[10];
    const float* rbb    = (const float*)d_in[11];
    const float* rgW    = (const float*)d_in[12];
    const float* rgb    = (const float*)d_in[13];
    const float* wkW    = (const float*)d_in[14];
    const float* wkb    = (const float*)d_in[15];
    const float* wbW    = (const float*)d_in[16];
    const float* wbb    = (const float*)d_in[17];
    const float* wgW    = (const float*)d_in[18];
    const float* wgb    = (const float*)d_in[19];
    const float* erW    = (const float*)d_in[20];
    const float* erb    = (const float*)d_in[21];
    const float* adW    = (const float*)d_in[22];
    const float* adb    = (const float*)d_in[23];
    const float* pW     = (const float*)d_in[24];
    const float* pb     = (const float*)d_in[25];
    float* out = (float*)d_out;

    const int SM_GEMM = 2*128*72*2;
    const int SM_MUPD = SM_GEMM + 128*132*4;
    cudaFuncSetAttribute(k_memupdT, cudaFuncAttributeMaxDynamicSharedMemorySize, SM_MUPD);
    cudaFuncSetAttribute(k_smax,    cudaFuncAttributeMaxDynamicSharedMemorySize, 65536);

    k_init<<<8192, 256>>>(memory);
    k_wsplit<<<G4*KLSTM/256, 256>>>(Wih, Whh);
    k_xsplit<<<BB*SS*INSZ/256, 256>>>(x);
    k_psplit<<<NPAD*KPAD/256, 256>>>(rkW,wkW,erW,adW,pW,rbW,rgW,wbW,wgW);
    k_woutT<<<dim3(HH/32, KPAD/32), 256>>>(Wout);
    k_wcombT<<<dim3(NPAD/128, HH/64), 256>>>();
    k_bcomb<<<(NPROJ+255)/256, 256>>>(bout, rkW,wkW,erW,adW,pW,rbW,rgW,wbW,wgW,
                                      rkb,wkb,erb,adb,pb,rbb,rgb,wbb,wgb);
    k_rownorm<<<2048, 256>>>();
    for (int t = 0; t < SS; t++){
        k_lstmT<<<dim3(64,2), 256>>>(t, bih, bhh);
        k_projT<<<dim3(NPROJ/64, 2), 256>>>();
        k_posproj<<<128, 256>>>(out, t);
        if (t + 1 < SS){
            k_simT<<<dim3(128,2), 256, SM_GEMM>>>();
            k_smax<<<256, 256, 65536>>>();
            k_memupdT<<<128, 256, SM_MUPD>>>();
            k_rvT<<<RVSPL, 256, SM_GEMM>>>(t);
        }
    }
}

// round 12
// speedup vs baseline: 3.3142x; 1.1576x over previous
#include <cuda_runtime.h>
#include <cuda_bf16.h>
#include <cuda_fp16.h>
#include <cuda_pipeline.h>
#include <cstdint>
#include <stdint.h>
#include <math.h>

#define BB    128
#define SS    32
#define INSZ  512
#define HH    1024
#define OUTSZ 512
#define NN    16384
#define WW    128
#define CC    899
#define G4    4096
#define KLSTM 1664
#define NPROJ 1088
#define NPAD  1152
#define KPAD  960
#define NTSIM 128
#define RVSPL 32

// ================= warp-level bf16 MMA =================
#define MMA16816(c, a, b) \
    asm volatile("mma.sync.aligned.m16n8k16.row.col.f32.bf16.bf16.f32 " \
        "{%0,%1,%2,%3}, {%4,%5,%6,%7}, {%8,%9}, {%0,%1,%2,%3};" \
        : "+f"((c)[0]), "+f"((c)[1]), "+f"((c)[2]), "+f"((c)[3]) \
        : "r"((a)[0]), "r"((a)[1]), "r"((a)[2]), "r"((a)[3]), "r"((b)[0]), "r"((b)[1]))

// sync fills (used by non-pipelined kernels)
__device__ __forceinline__ void load_chunk(__nv_bfloat16* sm, const __nv_bfloat16* src,
                                           size_t ld, int tid){
    #pragma unroll
    for (int i=0;i<4;i++){
        int idx = tid + i*256;
        int row = idx >> 3, c4 = idx & 7;
        *(uint4*)(sm + row*72 + c4*8) = *(const uint4*)(src + (size_t)row*ld + c4*8);
    }
}
__device__ __forceinline__ void load_chunk64(__nv_bfloat16* sm, const __nv_bfloat16* src,
                                             size_t ld, int tid){
    #pragma unroll
    for (int i=0;i<2;i++){
        int idx = tid + i*256;
        int row = idx >> 3, c4 = idx & 7;
        *(uint4*)(sm + row*72 + c4*8) = *(const uint4*)(src + (size_t)row*ld + c4*8);
    }
}
// async fills (cp.async)
__device__ __forceinline__ void cp_chunk(__nv_bfloat16* sm, const __nv_bfloat16* src,
                                         size_t ld, int tid){
    #pragma unroll
    for (int i=0;i<4;i++){
        int idx = tid + i*256;
        int row = idx >> 3, c4 = idx & 7;
        __pipeline_memcpy_async(sm + row*72 + c4*8, src + (size_t)row*ld + c4*8, 16);
    }
}
__device__ __forceinline__ void cp_chunk64(__nv_bfloat16* sm, const __nv_bfloat16* src,
                                           size_t ld, int tid){
    #pragma unroll
    for (int i=0;i<2;i++){
        int idx = tid + i*256;
        int row = idx >> 3, c4 = idx & 7;
        __pipeline_memcpy_async(sm + row*72 + c4*8, src + (size_t)row*ld + c4*8, 16);
    }
}

// CTA 128x128, 8 warps 4(m)x2(n)
__device__ __forceinline__ void mma_chunk(const __nv_bfloat16* As, const __nv_bfloat16* Bs,
                                          float cacc[2][8][4], int wm, int wn, int g, int t){
    #pragma unroll
    for (int ks=0;ks<4;ks++){
        int k = ks*16;
        uint32_t afr[2][4], bfr[8][2];
        #pragma unroll
        for (int mi=0;mi<2;mi++){
            const __nv_bfloat16* ap = As + (wm*32 + mi*16)*72 + k + 2*t;
            afr[mi][0] = *(const uint32_t*)(ap + g*72);
            afr[mi][1] = *(const uint32_t*)(ap + (g+8)*72);
            afr[mi][2] = *(const uint32_t*)(ap + g*72 + 8);
            afr[mi][3] = *(const uint32_t*)(ap + (g+8)*72 + 8);
        }
        #pragma unroll
        for (int nj=0;nj<8;nj++){
            const __nv_bfloat16* bp = Bs + (wn*64 + nj*8 + g)*72 + k + 2*t;
            bfr[nj][0] = *(const uint32_t*)(bp);
            bfr[nj][1] = *(const uint32_t*)(bp + 8);
        }
        #pragma unroll
        for (int mi=0;mi<2;mi++)
            #pragma unroll
            for (int nj=0;nj<8;nj++)
                MMA16816(cacc[mi][nj], afr[mi], bfr[nj]);
    }
}

// CTA 128x64
__device__ __forceinline__ void mma_chunk4(const __nv_bfloat16* As, const __nv_bfloat16* Bs,
                                           float cacc[2][4][4], int wm, int wn, int g, int t){
    #pragma unroll
    for (int ks=0;ks<4;ks++){
        int k = ks*16;
        uint32_t afr[2][4], bfr[4][2];
        #pragma unroll
        for (int mi=0;mi<2;mi++){
            const __nv_bfloat16* ap = As + (wm*32 + mi*16)*72 + k + 2*t;
            afr[mi][0] = *(const uint32_t*)(ap + g*72);
            afr[mi][1] = *(const uint32_t*)(ap + (g+8)*72);
            afr[mi][2] = *(const uint32_t*)(ap + g*72 + 8);
            afr[mi][3] = *(const uint32_t*)(ap + (g+8)*72 + 8);
        }
        #pragma unroll
        for (int nj=0;nj<4;nj++){
            const __nv_bfloat16* bp = Bs + (wn*32 + nj*8 + g)*72 + k + 2*t;
            bfr[nj][0] = *(const uint32_t*)(bp);
            bfr[nj][1] = *(const uint32_t*)(bp + 8);
        }
        #pragma unroll
        for (int mi=0;mi<2;mi++)
            #pragma unroll
            for (int nj=0;nj<4;nj++)
                MMA16816(cacc[mi][nj], afr[mi], bfr[nj]);
    }
}

// ================= device state =================
__device__ float d_mem[NN * WW];
__device__ __nv_bfloat16 d_memn[NN * WW];
__device__ __nv_bfloat16 d_memTb[WW * NN];
__device__ float d_c[BB * HH];
__device__ __nv_bfloat16 d_keysn[256 * WW];
__device__ __nv_bfloat16 d_eradT[256 * BB];
__device__ float d_scal[BB * 4];
__device__ __half d_sim[256 * NN];         // holds exp(beta*sim) fp16
__device__ float d_psum[256 * NTSIM];
__device__ float d_rw[BB * NN];
__device__ __nv_bfloat16 d_rwb[BB * NN];
__device__ __nv_bfloat16 d_wwT[NN * BB];
__device__ float d_rvpart[RVSPL * BB * WW];
// split-bf16 LSTM (gate-interleaved row order: row = u*4 + gate)
__device__ __nv_bfloat16 d_Whi[G4 * KLSTM];
__device__ __nv_bfloat16 d_Wlo[G4 * KLSTM];
__device__ __nv_bfloat16 d_xhi[BB * SS * INSZ];
__device__ __nv_bfloat16 d_xlo[BB * SS * INSZ];
__device__ __nv_bfloat16 d_hhi[BB * HH];
__device__ __nv_bfloat16 d_hlo[BB * HH];
__device__ __nv_bfloat16 d_rvhi[BB * WW];
__device__ __nv_bfloat16 d_rvlo[BB * WW];
__device__ float d_gpart[2 * BB * G4];
__device__ float d_gx[SS * BB * G4];       // precomputed x @ Wx^T (gate-interleaved cols)
// combined projection
__device__ __nv_bfloat16 d_PAhi[NPAD * KPAD];
__device__ __nv_bfloat16 d_PAlo[NPAD * KPAD];
__device__ __nv_bfloat16 d_WoThi[HH * KPAD];
__device__ __nv_bfloat16 d_WoTlo[HH * KPAD];
__device__ __nv_bfloat16 d_Pchi[NPROJ * HH];
__device__ __nv_bfloat16 d_Pclo[NPROJ * HH];
__device__ float d_bcomb[NPROJ];
__device__ float d_ppart[2 * BB * NPROJ];
// counters
__device__ int d_gcnt[64];
__device__ int d_rvcnt;

__device__ __forceinline__ float sigmoidf_(float x){ return 1.f/(1.f+__expf(-x)); }
__device__ __forceinline__ float softplusf_(float x){ return x>15.f ? x : log1pf(__expf(x)); }

__device__ __forceinline__ float getP(int n, int c,
    const float* rkW, const float* wkW, const float* erW, const float* adW,
    const float* pW, const float* rbW, const float* rgW,
    const float* wbW, const float* wgW){
    if (n < 128)   return rkW[n*CC + c];
    if (n < 256)   return wkW[(n-128)*CC + c];
    if (n < 384)   return erW[(n-256)*CC + c];
    if (n < 512)   return adW[(n-384)*CC + c];
    if (n < 1024)  return (c < 512) ? pW[(size_t)(n-512)*512 + c] : 0.f;
    if (n == 1024) return rbW[c];
    if (n == 1025) return rgW[c];
    if (n == 1026) return wbW[c];
    if (n == 1027) return wgW[c];
    return 0.f;
}

// ================= init =================
__global__ void k_init(const float* __restrict__ memory){
    int i = blockIdx.x*256 + threadIdx.x;
    d_mem[i] = memory[i];
    d_rw[i]  = 1.0f/NN;
    if (i < BB*HH){ d_c[i]=0.f;
        d_hhi[i]=__float2bfloat16(0.f); d_hlo[i]=__float2bfloat16(0.f); }
    if (i < BB*WW){
        d_rvhi[i]=__float2bfloat16(0.f); d_rvlo[i]=__float2bfloat16(0.f); }
    if (i < 64) d_gcnt[i] = 0;
    if (i == 64) d_rvcnt = 0;
}

__global__ void k_wsplit(const float* __restrict__ Wih, const float* __restrict__ Whh){
    int i = blockIdx.x*256 + threadIdx.x;
    int j = i / KLSTM, k = i - j*KLSTM;
    float w = (k < 640) ? Wih[(size_t)j*640 + k] : Whh[(size_t)j*1024 + (k-640)];
    int u = j & 1023, gate = j >> 10;
    size_t jn = (size_t)(u*4 + gate)*KLSTM + k;
    __nv_bfloat16 hi = __float2bfloat16(w);
    d_Whi[jn] = hi;
    d_Wlo[jn] = __float2bfloat16(w - __bfloat162float(hi));
}

__global__ void k_xsplit(const float* __restrict__ x){
    int i = blockIdx.x*256 + threadIdx.x;
    float v = x[i];
    __nv_bfloat16 hi = __float2bfloat16(v);
    d_xhi[i] = hi;
    d_xlo[i] = __float2bfloat16(v - __bfloat162float(hi));
}

__global__ void k_psplit(const float* rkW, const float* wkW, const float* erW, const float* adW,
                         const float* pW,  const float* rbW, const float* rgW,
                         const float* wbW, const float* wgW){
    int i = blockIdx.x*256 + threadIdx.x;
    int n = i / KPAD, c = i - n*KPAD;
    float v = (c < CC && n < NPROJ) ? getP(n, c, rkW,wkW,erW,adW,pW,rbW,rgW,wbW,wgW) : 0.f;
    __nv_bfloat16 hi = __float2bfloat16(v);
    d_PAhi[i] = hi;
    d_PAlo[i] = __float2bfloat16(v - __bfloat162float(hi));
}

__global__ void k_woutT(const float* __restrict__ Wout){
    __shared__ float tile[32][33];
    int k0 = blockIdx.x*32, c0 = blockIdx.y*32;
    int tx = threadIdx.x & 31, ty = threadIdx.x >> 5;
    #pragma unroll
    for (int r=0;r<32;r+=8){
        int c = c0 + ty + r;
        tile[ty+r][tx] = (c < CC) ? Wout[(size_t)c*HH + k0 + tx] : 0.f;
    }
    __syncthreads();
    #pragma unroll
    for (int r=0;r<32;r+=8){
        int k = k0 + ty + r;
        float v = tile[tx][ty+r];
        __nv_bfloat16 hi = __float2bfloat16(v);
        d_WoThi[(size_t)k*KPAD + c0 + tx] = hi;
        d_WoTlo[(size_t)k*KPAD + c0 + tx] = __float2bfloat16(v - __bfloat162float(hi));
    }
}

// Wcomb via MMA (one-time, unpipelined ok)
__global__ void __launch_bounds__(256) k_wcombT(){
    __shared__ __nv_bfloat16 As[128*72];
    __shared__ __nv_bfloat16 Bs[64*72];
    int tid = threadIdx.x, lane = tid & 31, wid = tid >> 5;
    int wm = wid >> 1, wn = wid & 1, g = lane >> 2, tq = lane & 3;
    int m0 = blockIdx.x*128;
    int n0 = blockIdx.y*64;

    float cacc[2][4][4] = {};
    #pragma unroll
    for (int pass=0; pass<3; pass++){
        const __nv_bfloat16* Ab = (pass==1) ? d_PAlo : d_PAhi;
        const __nv_bfloat16* Wb = (pass==2) ? d_WoTlo : d_WoThi;
        #pragma unroll
        for (int cc=0; cc<15; cc++){
            int k0 = cc*64;
            load_chunk(As, Ab + (size_t)m0*KPAD + k0, KPAD, tid);
            load_chunk64(Bs, Wb + (size_t)n0*KPAD + k0, KPAD, tid);
            __syncthreads();
            mma_chunk4(As, Bs, cacc, wm, wn, g, tq);
            __syncthreads();
        }
    }
    #pragma unroll
    for (int mi=0;mi<2;mi++){
        int rl0 = wm*32 + mi*16 + g, rl1 = rl0 + 8;
        #pragma unroll
        for (int nj=0;nj<4;nj++){
            int col = n0 + wn*32 + nj*8 + 2*tq;
            #pragma unroll
            for (int hh=0;hh<2;hh++){
                int row = m0 + (hh ? rl1 : rl0);
                if (row < NPROJ){
                    float w0 = cacc[mi][nj][hh*2], w1 = cacc[mi][nj][hh*2+1];
                    __nv_bfloat16 h0 = __float2bfloat16(w0), h1 = __float2bfloat16(w1);
                    d_Pchi[(size_t)row*HH + col]   = h0;
                    d_Pchi[(size_t)row*HH + col+1] = h1;
                    d_Pclo[(size_t)row*HH + col]   = __float2bfloat16(w0 - __bfloat162float(h0));
                    d_Pclo[(size_t)row*HH + col+1] = __float2bfloat16(w1 - __bfloat162float(h1));
                }
            }
        }
    }
}

__global__ void k_bcomb(const float* __restrict__ bout,
                        const float* rkW, const float* wkW, const float* erW, const float* adW,
                        const float* pW,  const float* rbW, const float* rgW,
                        const float* wbW, const float* wgW,
                        const float* rkb, const float* wkb, const float* erb, const float* adb,
                        const float* pb,  const float* rbb, const float* rgb,
                        const float* wbb, const float* wgb){
    int n = blockIdx.x*256 + threadIdx.x;
    if (n >= NPROJ) return;
    float s = 0.f;
    for (int c = 0; c < CC; c++)
        s += getP(n, c, rkW,wkW,erW,adW,pW,rbW,rgW,wbW,wgW) * bout[c];
    float bias = 0.f;
    if (n < 128)        bias = rkb[n];
    else if (n < 256)   bias = wkb[n-128];
    else if (n < 384)   bias = erb[n-256];
    else if (n < 512)   bias = adb[n-384];
    else if (n < 1024)  bias = pb[n-512];
    else if (n == 1024) bias = rbb[0];
    else if (n == 1025) bias = rgb[0];
    else if (n == 1026) bias = wbb[0];
    else if (n == 1027) bias = wgb[0];
    d_bcomb[n] = s + bias;
}

__global__ void k_rownorm(){
    int row  = blockIdx.x*8 + (threadIdx.x>>5);
    int lane = threadIdx.x & 31;
    const float4* p = (const float4*)(d_mem + (size_t)row*WW);
    float4 v = p[lane];
    float s = v.x*v.x + v.y*v.y + v.z*v.z + v.w*v.w;
    #pragma unroll
    for (int o=16;o;o>>=1) s += __shfl_xor_sync(0xffffffffu, s, o);
    s = __shfl_sync(0xffffffffu, s, 0);
    float inv = 1.f / fmaxf(sqrtf(s), 1e-12f);
    __nv_bfloat162* nm = (__nv_bfloat162*)(d_memn + (size_t)row*WW + lane*4);
    nm[0] = __floats2bfloat162_rn(v.x*inv, v.y*inv);
    nm[1] = __floats2bfloat162_rn(v.z*inv, v.w*inv);
    float vv[4] = {v.x, v.y, v.z, v.w};
    #pragma unroll
    for (int j=0;j<4;j++) d_memTb[(size_t)(lane*4+j)*NN + row] = __float2bfloat16(vv[j]);
}

// ================= one-time xW GEMM: gx[t] = x_t @ Wx^T =================
__global__ void __launch_bounds__(256) k_xw(){
    extern __shared__ __nv_bfloat16 smp[];
    __nv_bfloat16* Asb[2] = { smp, smp + 128*72 };
    __nv_bfloat16* Bsb[2] = { smp + 2*128*72, smp + 2*128*72 + 64*72 };
    int tid = threadIdx.x, lane = tid & 31, wid = tid >> 5;
    int wm = wid >> 1, wn = wid & 1, g = lane >> 2, tq = lane & 3;
    int n0 = blockIdx.x*64;
    int t  = blockIdx.y;
    const int NIT = 24;   // 3 passes x 8 chunks

    auto srcA = [&](int it)->const __nv_bfloat16*{
        int pass = it >> 3, k0 = (it & 7)*64;
        return ((pass==1) ? d_xlo : d_xhi) + (size_t)t*INSZ + k0;
    };
    auto srcB = [&](int it)->const __nv_bfloat16*{
        int pass = it >> 3, k0 = (it & 7)*64;
        return ((pass==2) ? d_Wlo : d_Whi) + (size_t)n0*KLSTM + k0;
    };

    float cacc[2][4][4] = {};
    cp_chunk(Asb[0], srcA(0), (size_t)SS*INSZ, tid);
    cp_chunk64(Bsb[0], srcB(0), KLSTM, tid);
    __pipeline_commit();
    for (int it=0; it<NIT; it++){
        if (it+1 < NIT){
            cp_chunk(Asb[(it+1)&1], srcA(it+1), (size_t)SS*INSZ, tid);
            cp_chunk64(Bsb[(it+1)&1], srcB(it+1), KLSTM, tid);
            __pipeline_commit();
            __pipeline_wait_prior(1);
        } else __pipeline_wait_prior(0);
        __syncthreads();
        mma_chunk4(Asb[it&1], Bsb[it&1], cacc, wm, wn, g, tq);
        __syncthreads();
    }
    float* gp = d_gx + (size_t)t*BB*G4;
    #pragma unroll
    for (int mi=0;mi<2;mi++){
        int rl0 = wm*32 + mi*16 + g, rl1 = rl0 + 8;
        #pragma unroll
        for (int nj=0;nj<4;nj++){
            int col = n0 + wn*32 + nj*8 + 2*tq;
            *(float2*)&gp[(size_t)rl0*G4 + col] = make_float2(cacc[mi][nj][0], cacc[mi][nj][1]);
            *(float2*)&gp[(size_t)rl1*G4 + col] = make_float2(cacc[mi][nj][2], cacc[mi][nj][3]);
        }
    }
}

// ================= LSTM recurrent GEMM (K=1152) + fused gates =================
__global__ void __launch_bounds__(256) k_lstmT(int t, const float* __restrict__ bih,
                                               const float* __restrict__ bhh){
    extern __shared__ __nv_bfloat16 smp[];
    __nv_bfloat16* Asb[2] = { smp, smp + 128*72 };
    __nv_bfloat16* Bsb[2] = { smp + 2*128*72, smp + 2*128*72 + 64*72 };
    __shared__ int lastflag;
    int tid = threadIdx.x, lane = tid & 31, wid = tid >> 5;
    int wm = wid >> 1, wn = wid & 1, g = lane >> 2, tq = lane & 3;
    int n0 = blockIdx.x*64;
    int ks = blockIdx.y;
    const int NIT = 27;   // 3 passes x 9 chunks (K half = 576)

    auto srcA = [&](int it, size_t& lda)->const __nv_bfloat16*{
        int pass = it/9, cc = it - pass*9;
        int k0 = 512 + (ks*9 + cc)*64;
        if (k0 < 640){ lda = WW; return ((pass==1) ? d_rvlo : d_rvhi) + (k0-512); }
        lda = HH; return ((pass==1) ? d_hlo : d_hhi) + (k0-640);
    };
    auto srcB = [&](int it)->const __nv_bfloat16*{
        int pass = it/9, cc = it - pass*9;
        int k0 = 512 + (ks*9 + cc)*64;
        return ((pass==2) ? d_Wlo : d_Whi) + (size_t)n0*KLSTM + k0;
    };

    float cacc[2][4][4] = {};
    { size_t lda; const __nv_bfloat16* a = srcA(0, lda);
      cp_chunk(Asb[0], a, lda, tid); cp_chunk64(Bsb[0], srcB(0), KLSTM, tid);
      __pipeline_commit(); }
    for (int it=0; it<NIT; it++){
        if (it+1 < NIT){
            size_t lda; const __nv_bfloat16* a = srcA(it+1, lda);
            cp_chunk(Asb[(it+1)&1], a, lda, tid);
            cp_chunk64(Bsb[(it+1)&1], srcB(it+1), KLSTM, tid);
            __pipeline_commit();
            __pipeline_wait_prior(1);
        } else __pipeline_wait_prior(0);
        __syncthreads();
        mma_chunk4(Asb[it&1], Bsb[it&1], cacc, wm, wn, g, tq);
        __syncthreads();
    }
    float* gp = d_gpart + (size_t)ks*BB*G4;
    #pragma unroll
    for (int mi=0;mi<2;mi++){
        int rl0 = wm*32 + mi*16 + g, rl1 = rl0 + 8;
        #pragma unroll
        for (int nj=0;nj<4;nj++){
            int col = n0 + wn*32 + nj*8 + 2*tq;
            *(float2*)&gp[(size_t)rl0*G4 + col] = make_float2(cacc[mi][nj][0], cacc[mi][nj][1]);
            *(float2*)&gp[(size_t)rl1*G4 + col] = make_float2(cacc[mi][nj][2], cacc[mi][nj][3]);
        }
    }
    __threadfence();
    __syncthreads();
    if (tid == 0){
        int old = atomicAdd(&d_gcnt[blockIdx.x], 1);
        lastflag = (old == 2*t + 1);
    }
    __syncthreads();
    if (lastflag){
        const float* p0 = d_gpart;
        const float* p1 = d_gpart + (size_t)BB*G4;
        const float* px = d_gx + (size_t)t*BB*G4;
        int u0 = n0 >> 2;
        #pragma unroll
        for (int p=0;p<8;p++){
            int pair = tid + p*256;
            int b = pair >> 4, ul = pair & 15;
            int u = u0 + ul;
            size_t base = (size_t)b*G4 + u*4;
            float4 a0 = *(const float4*)&p0[base];
            float4 a1 = *(const float4*)&p1[base];
            float4 ax = *(const float4*)&px[base];
            float gi = a0.x + a1.x + ax.x + bih[u]      + bhh[u];
            float gf = a0.y + a1.y + ax.y + bih[1024+u] + bhh[1024+u];
            float gg = a0.z + a1.z + ax.z + bih[2048+u] + bhh[2048+u];
            float go = a0.w + a1.w + ax.w + bih[3072+u] + bhh[3072+u];
            int i = b*HH + u;
            float c = sigmoidf_(gf)*d_c[i] + sigmoidf_(gi)*tanhf(gg);
            float h = sigmoidf_(go)*tanhf(c);
            d_c[i] = c;
            __nv_bfloat16 hi = __float2bfloat16(h);
            d_hhi[i] = hi;
            d_hlo[i] = __float2bfloat16(h - __bfloat162float(hi));
        }
    }
}

// ================= combined projection GEMM (pipelined) =================
__global__ void __launch_bounds__(256) k_projT(){
    extern __shared__ __nv_bfloat16 smp[];
    __nv_bfloat16* Asb[2] = { smp, smp + 128*72 };
    __nv_bfloat16* Bsb[2] = { smp + 2*128*72, smp + 2*128*72 + 64*72 };
    int tid = threadIdx.x, lane = tid & 31, wid = tid >> 5;
    int wm = wid >> 1, wn = wid & 1, g = lane >> 2, tq = lane & 3;
    int n0 = blockIdx.x*64;
    int ks = blockIdx.y;
    const int NIT = 24;   // 3 passes x 8 chunks

    auto srcA = [&](int it)->const __nv_bfloat16*{
        int pass = it >> 3, k0 = ks*512 + (it & 7)*64;
        return ((pass==1) ? d_hlo : d_hhi) + k0;
    };
    auto srcB = [&](int it)->const __nv_bfloat16*{
        int pass = it >> 3, k0 = ks*512 + (it & 7)*64;
        return ((pass==2) ? d_Pclo : d_Pchi) + (size_t)n0*HH + k0;
    };

    float cacc[2][4][4] = {};
    cp_chunk(Asb[0], srcA(0), HH, tid);
    cp_chunk64(Bsb[0], srcB(0), HH, tid);
    __pipeline_commit();
    for (int it=0; it<NIT; it++){
        if (it+1 < NIT){
            cp_chunk(Asb[(it+1)&1], srcA(it+1), HH, tid);
            cp_chunk64(Bsb[(it+1)&1], srcB(it+1), HH, tid);
            __pipeline_commit();
            __pipeline_wait_prior(1);
        } else __pipeline_wait_prior(0);
        __syncthreads();
        mma_chunk4(Asb[it&1], Bsb[it&1], cacc, wm, wn, g, tq);
        __syncthreads();
    }
    float* gp = d_ppart + (size_t)ks*BB*NPROJ;
    #pragma unroll
    for (int mi=0;mi<2;mi++){
        int rl0 = wm*32 + mi*16 + g, rl1 = rl0 + 8;
        #pragma unroll
        for (int nj=0;nj<4;nj++){
            int col = n0 + wn*32 + nj*8 + 2*tq;
            *(float2*)&gp[(size_t)rl0*NPROJ + col] = make_float2(cacc[mi][nj][0], cacc[mi][nj][1]);
            *(float2*)&gp[(size_t)rl1*NPROJ + col] = make_float2(cacc[mi][nj][2], cacc[mi][nj][3]);
        }
    }
}

// ================= projection epilogue =================
__global__ void k_posproj(float* __restrict__ out, int t){
    __shared__ float pp[1028];
    __shared__ float wsum[8];
    int b = blockIdx.x, tid = threadIdx.x;
    for (int n = tid; n < 1028; n += 256)
        pp[n] = d_ppart[(size_t)b*NPROJ + n]
              + d_ppart[(size_t)(BB+b)*NPROJ + n]
              + d_bcomb[n];
    __syncthreads();

    int half = tid >> 7, w = tid & 127;
    float v = pp[half*128 + w];
    float sq = v*v;
    #pragma unroll
    for (int o=16;o;o>>=1) sq += __shfl_xor_sync(0xffffffffu, sq, o);
    if (!(tid & 31)) wsum[tid >> 5] = sq;
    __syncthreads();
    int base = half*4;
    float s = wsum[base] + wsum[base+1] + wsum[base+2] + wsum[base+3];
    float inv = 1.f / fmaxf(sqrtf(s), 1e-12f);
    d_keysn[(size_t)(half*128 + b)*WW + w] = __float2bfloat16(v*inv);
    float ev = half ? tanhf(pp[384 + w]) : sigmoidf_(pp[256 + w]);
    d_eradT[(half*128 + w)*BB + b] = __float2bfloat16(ev);
    for (int o = tid; o < OUTSZ; o += 256)
        out[((size_t)b*SS + t)*OUTSZ + o] = pp[512 + o];
    if (tid < 4){
        float vv = softplusf_(pp[1024 + tid]);
        if (tid & 1) vv += 1.f;
        d_scal[b*4 + tid] = vv;
    }
}

// ================= sim + exp fused (no-max softmax numerator) =================
__global__ void __launch_bounds__(256) k_simT(){
    extern __shared__ __nv_bfloat16 smp[];
    __nv_bfloat16* Asb[2] = { smp, smp + 128*72 };
    __nv_bfloat16* Bsb[2] = { smp + 2*128*72, smp + 3*128*72 };
    __shared__ float redm[128][2];
    int tid = threadIdx.x, lane = tid & 31, wid = tid >> 5;
    int wm = wid >> 1, wn = wid & 1, g = lane >> 2, t = lane & 3;
    int m0 = blockIdx.y*128, n0 = blockIdx.x*128;
    int head = m0 >> 7;

    float cacc[2][8][4] = {};
    cp_chunk(Asb[0], d_keysn + (size_t)m0*WW, WW, tid);
    cp_chunk(Bsb[0], d_memn  + (size_t)n0*WW, WW, tid);
    __pipeline_commit();
    #pragma unroll
    for (int it=0; it<2; it++){
        if (it == 0){
            cp_chunk(Asb[1], d_keysn + (size_t)m0*WW + 64, WW, tid);
            cp_chunk(Bsb[1], d_memn  + (size_t)n0*WW + 64, WW, tid);
            __pipeline_commit();
            __pipeline_wait_prior(1);
        } else __pipeline_wait_prior(0);
        __syncthreads();
        mma_chunk(Asb[it], Bsb[it], cacc, wm, wn, g, t);
        __syncthreads();
    }
    #pragma unroll
    for (int mi=0;mi<2;mi++){
        int rl0 = wm*32 + mi*16 + g, rl1 = rl0 + 8;
        float beta0 = d_scal[((m0+rl0)&127)*4 + head*2];
        float beta1 = d_scal[((m0+rl1)&127)*4 + head*2];
        float s0 = 0.f, s1 = 0.f;
        #pragma unroll
        for (int nj=0;nj<8;nj++){
            int col = n0 + wn*64 + nj*8 + 2*t;
            float e0 = __expf(beta0*cacc[mi][nj][0]);
            float e1 = __expf(beta0*cacc[mi][nj][1]);
            float e2 = __expf(beta1*cacc[mi][nj][2]);
            float e3 = __expf(beta1*cacc[mi][nj][3]);
            *(__half2*)&d_sim[(size_t)(m0+rl0)*NN + col] = __floats2half2_rn(e0, e1);
            *(__half2*)&d_sim[(size_t)(m0+rl1)*NN + col] = __floats2half2_rn(e2, e3);
            s0 += e0 + e1;
            s1 += e2 + e3;
        }
        s0 += __shfl_xor_sync(0xffffffffu, s0, 1);
        s0 += __shfl_xor_sync(0xffffffffu, s0, 2);
        s1 += __shfl_xor_sync(0xffffffffu, s1, 1);
        s1 += __shfl_xor_sync(0xffffffffu, s1, 2);
        if (t == 0){ redm[rl0][wn] = s0; redm[rl1][wn] = s1; }
    }
    __syncthreads();
    if (tid < 128)
        d_psum[(size_t)(m0+tid)*NTSIM + blockIdx.x] = redm[tid][0] + redm[tid][1];
}

// ================= softmax normalize + interpolation (no exp) =================
__global__ void k_smax(){
    __shared__ float red[256];
    int r = blockIdx.x;
    int head = r >> 7, b = r & 127;
    float gamma = d_scal[b*4 + head*2 + 1];
    int tid = threadIdx.x;

    red[tid] = (tid < NTSIM) ? d_psum[(size_t)r*NTSIM + tid] : 0.f;
    __syncthreads();
    for (int o=128;o;o>>=1){ if (tid<o) red[tid] += red[tid+o]; __syncthreads(); }
    float inv = 1.f / red[0];

    const __half* simrow = d_sim + (size_t)r*NN;
    if (head == 0){
        float* rw = d_rw + (size_t)b*NN;
        __nv_bfloat16* rwb = d_rwb + (size_t)b*NN;
        for (int n = tid; n < NN; n += 256){
            float w = __half2float(simrow[n])*inv;
            float v = gamma*w + (1.f-gamma)*rw[n];
            rw[n] = v;
            rwb[n] = __float2bfloat16(v);
        }
    } else {
        const float u = 1.f/NN;
        for (int n = tid; n < NN; n += 256){
            float w = __half2float(simrow[n])*inv;
            float v = gamma*w + (1.f-gamma)*u;
            d_wwT[(size_t)n*BB + b] = __float2bfloat16(v);
        }
    }
}

// ================= memory update =================
__global__ void __launch_bounds__(256) k_memupdT(){
    extern __shared__ __nv_bfloat16 smb[];
    __nv_bfloat16* As = smb;
    __nv_bfloat16* Bs = smb + 128*72;
    float* Esm = (float*)(smb + 2*128*72);
    __shared__ float redm[128][2];
    __shared__ float invsm[128];
    int tid = threadIdx.x, lane = tid & 31, wid = tid >> 5;
    int wm = wid >> 1, wn = wid & 1, g = lane >> 2, t = lane & 3;
    int q0 = blockIdx.x*128;

    float cacc[2][8][4] = {};
    #pragma unroll
    for (int ph=0; ph<2; ph++){
        #pragma unroll
        for (int kc=0;kc<2;kc++){
            load_chunk(As, d_wwT + (size_t)q0*BB + kc*64, BB, tid);
            load_chunk(Bs, d_eradT + ph*128*BB + kc*64, BB, tid);
            __syncthreads();
            mma_chunk(As, Bs, cacc, wm, wn, g, t);
            __syncthreads();
        }
        if (ph == 0){
            #pragma unroll
            for (int mi=0;mi<2;mi++){
                int rl0 = wm*32 + mi*16 + g, rl1 = rl0 + 8;
                #pragma unroll
                for (int nj=0;nj<8;nj++){
                    int cl = wn*64 + nj*8 + 2*t;
                    Esm[rl0*132 + cl]   = cacc[mi][nj][0];
                    Esm[rl0*132 + cl+1] = cacc[mi][nj][1];
                    Esm[rl1*132 + cl]   = cacc[mi][nj][2];
                    Esm[rl1*132 + cl+1] = cacc[mi][nj][3];
                    cacc[mi][nj][0]=0.f; cacc[mi][nj][1]=0.f;
                    cacc[mi][nj][2]=0.f; cacc[mi][nj][3]=0.f;
                }
            }
        }
    }
    float ssq[2][2] = {};
    #pragma unroll
    for (int mi=0;mi<2;mi++){
        int rl0 = wm*32 + mi*16 + g, rl1 = rl0 + 8;
        #pragma unroll
        for (int nj=0;nj<8;nj++){
            int cl = wn*64 + nj*8 + 2*t;
            float2 m0v = *(const float2*)&d_mem[(size_t)(q0+rl0)*WW + cl];
            float2 m1v = *(const float2*)&d_mem[(size_t)(q0+rl1)*WW + cl];
            float v00 = m0v.x*(1.f - Esm[rl0*132+cl])   + cacc[mi][nj][0];
            float v01 = m0v.y*(1.f - Esm[rl0*132+cl+1]) + cacc[mi][nj][1];
            float v10 = m1v.x*(1.f - Esm[rl1*132+cl])   + cacc[mi][nj][2];
            float v11 = m1v.y*(1.f - Esm[rl1*132+cl+1]) + cacc[mi][nj][3];
            cacc[mi][nj][0]=v00; cacc[mi][nj][1]=v01; cacc[mi][nj][2]=v10; cacc[mi][nj][3]=v11;
            ssq[mi][0] += v00*v00 + v01*v01;
            ssq[mi][1] += v10*v10 + v11*v11;
        }
    }
    #pragma unroll
    for (int mi=0;mi<2;mi++){
        #pragma unroll
        for (int h=0;h<2;h++){
            float s = ssq[mi][h];
            s += __shfl_xor_sync(0xffffffffu, s, 1);
            s += __shfl_xor_sync(0xffffffffu, s, 2);
            if (t == 0) redm[wm*32 + mi*16 + h*8 + g][wn] = s;
        }
    }
    __syncthreads();
    if (tid < 128) invsm[tid] = 1.f / fmaxf(sqrtf(redm[tid][0] + redm[tid][1]), 1e-12f);
    __syncthreads();
    __nv_bfloat16* Vsm = (__nv_bfloat16*)Esm;
    #pragma unroll
    for (int mi=0;mi<2;mi++){
        int rl0 = wm*32 + mi*16 + g, rl1 = rl0 + 8;
        float i0 = invsm[rl0], i1 = invsm[rl1];
        #pragma unroll
        for (int nj=0;nj<8;nj++){
            int cl = wn*64 + nj*8 + 2*t;
            float v00=cacc[mi][nj][0], v01=cacc[mi][nj][1], v10=cacc[mi][nj][2], v11=cacc[mi][nj][3];
            *(float2*)&d_mem[(size_t)(q0+rl0)*WW + cl] = make_float2(v00, v01);
            *(float2*)&d_mem[(size_t)(q0+rl1)*WW + cl] = make_float2(v10, v11);
            *(__nv_bfloat162*)&d_memn[(size_t)(q0+rl0)*WW + cl] = __floats2bfloat162_rn(v00*i0, v01*i0);
            *(__nv_bfloat162*)&d_memn[(size_t)(q0+rl1)*WW + cl] = __floats2bfloat162_rn(v10*i1, v11*i1);
            Vsm[cl*136 + rl0]     = __float2bfloat16(v00);
            Vsm[(cl+1)*136 + rl0] = __float2bfloat16(v01);
            Vsm[cl*136 + rl1]     = __float2bfloat16(v10);
            Vsm[(cl+1)*136 + rl1] = __float2bfloat16(v11);
        }
    }
    __syncthreads();
    #pragma unroll
    for (int i=0;i<8;i++){
        int idx = tid + i*256;
        int w = idx >> 4, c4 = idx & 15;
        *(uint4*)&d_memTb[(size_t)w*NN + q0 + c4*8] = *(const uint4*)&Vsm[w*136 + c4*8];
    }
}

// ================= rv = rw @ mem (split-K, pipelined, fused reduction) =================
__global__ void __launch_bounds__(256) k_rvT(int iter){
    extern __shared__ __nv_bfloat16 smp[];
    __nv_bfloat16* Asb[2] = { smp, smp + 128*72 };
    __nv_bfloat16* Bsb[2] = { smp + 2*128*72, smp + 3*128*72 };
    int tid = threadIdx.x, lane = tid & 31, wid = tid >> 5;
    int wm = wid >> 1, wn = wid & 1, g = lane >> 2, t = lane & 3;
    size_t kb = (size_t)blockIdx.x * 512;

    float cacc[2][8][4] = {};
    cp_chunk(Asb[0], d_rwb + kb, NN, tid);
    cp_chunk(Bsb[0], d_memTb + kb, NN, tid);
    __pipeline_commit();
    #pragma unroll
    for (int it=0; it<8; it++){
        if (it+1 < 8){
            cp_chunk(Asb[(it+1)&1], d_rwb   + kb + (it+1)*64, NN, tid);
            cp_chunk(Bsb[(it+1)&1], d_memTb + kb + (it+1)*64, NN, tid);
            __pipeline_commit();
            __pipeline_wait_prior(1);
        } else __pipeline_wait_prior(0);
        __syncthreads();
        mma_chunk(Asb[it&1], Bsb[it&1], cacc, wm, wn, g, t);
        __syncthreads();
    }
    float* dst = d_rvpart + (size_t)blockIdx.x*BB*WW;
    #pragma unroll
    for (int mi=0;mi<2;mi++){
        int rl0 = wm*32 + mi*16 + g, rl1 = rl0 + 8;
        #pragma unroll
        for (int nj=0;nj<8;nj++){
            int cl = wn*64 + nj*8 + 2*t;
            *(float2*)&dst[(size_t)rl0*WW + cl] = make_float2(cacc[mi][nj][0], cacc[mi][nj][1]);
            *(float2*)&dst[(size_t)rl1*WW + cl] = make_float2(cacc[mi][nj][2], cacc[mi][nj][3]);
        }
    }
    __threadfence();
    __syncthreads();
    if (tid == 0){
        atomicAdd(&d_rvcnt, 1);
        int target = 32*(iter+1);
        while (atomicAdd(&d_rvcnt, 0) < target) {}
    }
    __syncthreads();
    #pragma unroll
    for (int rep=0; rep<2; rep++){
        int idx = blockIdx.x*512 + tid + rep*256;
        float s = 0.f;
        #pragma unroll
        for (int p=0;p<RVSPL;p++) s += d_rvpart[(size_t)p*16384 + idx];
        __nv_bfloat16 hi = __float2bfloat16(s);
        d_rvhi[idx] = hi;
        d_rvlo[idx] = __float2bfloat16(s - __bfloat162float(hi));
    }
}

// ================= launch =================
extern "C" void kernel_launch(void* const* d_in, const int* in_sizes, int n_in,
                              void* d_out, int out_size){
    const float* x      = (const float*)d_in[0];
    const float* memory = (const float*)d_in[1];
    const float* Wih    = (const float*)d_in[2];
    const float* Whh    = (const float*)d_in[3];
    const float* bih    = (const float*)d_in[4];
    const float* bhh    = (const float*)d_in[5];
    const float* Wout   = (const float*)d_in[6];
    const float* bout   = (const float*)d_in[7];
    const float* rkW    = (const float*)d_in[8];
    const float* rkb    = (const float*)d_in[9];
    const float* rbW    = (const float*)d_in[10];
    const float* rbb    = (const float*)d_in[11];
    const float* rgW    = (const float*)d_in[12];
    const float* rgb    = (const float*)d_in[13];
    const float* wkW    = (const float*)d_in[14];
    const float* wkb    = (const float*)d_in[15];
    const float* wbW    = (const float*)d_in[16];
    const float* wbb    = (const float*)d_in[17];
    const float* wgW    = (const float*)d_in[18];
    const float* wgb    = (const float*)d_in[19];
    const float* erW    = (const float*)d_in[20];
    const float* erb    = (const float*)d_in[21];
    const float* adW    = (const float*)d_in[22];
    const float* adb    = (const float*)d_in[23];
    const float* pW     = (const float*)d_in[24];
    const float* pb     = (const float*)d_in[25];
    float* out = (float*)d_out;

    const int SM_P64  = (2*128*72 + 2*64*72)*2;      // 55296
    const int SM_P128 = (4*128*72)*2;                // 73728
    const int SM_MUPD = 2*128*72*2 + 128*132*4;      // 104448
    cudaFuncSetAttribute(k_lstmT,   cudaFuncAttributeMaxDynamicSharedMemorySize, SM_P64);
    cudaFuncSetAttribute(k_projT,   cudaFuncAttributeMaxDynamicSharedMemorySize, SM_P64);
    cudaFuncSetAttribute(k_xw,      cudaFuncAttributeMaxDynamicSharedMemorySize, SM_P64);
    cudaFuncSetAttribute(k_simT,    cudaFuncAttributeMaxDynamicSharedMemorySize, SM_P128);
    cudaFuncSetAttribute(k_rvT,     cudaFuncAttributeMaxDynamicSharedMemorySize, SM_P128);
    cudaFuncSetAttribute(k_memupdT, cudaFuncAttributeMaxDynamicSharedMemorySize, SM_MUPD);

    k_init<<<8192, 256>>>(memory);
    k_wsplit<<<G4*KLSTM/256, 256>>>(Wih, Whh);
    k_xsplit<<<BB*SS*INSZ/256, 256>>>(x);
    k_psplit<<<NPAD*KPAD/256, 256>>>(rkW,wkW,erW,adW,pW,rbW,rgW,wbW,wgW);
    k_woutT<<<dim3(HH/32, KPAD/32), 256>>>(Wout);
    k_wcombT<<<dim3(NPAD/128, HH/64), 256>>>();
    k_bcomb<<<(NPROJ+255)/256, 256>>>(bout, rkW,wkW,erW,adW,pW,rbW,rgW,wbW,wgW,
                                      rkb,wkb,erb,adb,pb,rbb,rgb,wbb,wgb);
    k_xw<<<dim3(64, SS), 256, SM_P64>>>();
    k_rownorm<<<2048, 256>>>();
    for (int t = 0; t < SS; t++){
        k_lstmT<<<dim3(64,2), 256, SM_P64>>>(t, bih, bhh);
        k_projT<<<dim3(NPROJ/64, 2), 256, SM_P64>>>();
        k_posproj<<<128, 256>>>(out, t);
        if (t + 1 < SS){
            k_simT<<<dim3(128,2), 256, SM_P128>>>();
            k_smax<<<256, 256>>>();
            k_memupdT<<<128, 256, SM_MUPD>>>();
            k_rvT<<<RVSPL, 256, SM_P128>>>(t);
        }
    }
}

// round 15
// speedup vs baseline: 3.6473x; 1.1005x over previous
#include <cuda_runtime.h>
#include <cuda_bf16.h>
#include <cuda_fp16.h>
#include <cuda_pipeline.h>
#include <cstdint>
#include <stdint.h>
#include <math.h>

#define BB    128
#define SS    32
#define INSZ  512
#define HH    1024
#define OUTSZ 512
#define NN    16384
#define WW    128
#define CC    899
#define G4    4096
#define KLSTM 1664
#define NPROJ 1088
#define NPAD  1152
#define KPAD  960
#define NTSIM 128
#define PKS   4        // projT split-K

// ================= warp-level bf16 MMA =================
#define MMA16816(c, a, b) \
    asm volatile("mma.sync.aligned.m16n8k16.row.col.f32.bf16.bf16.f32 " \
        "{%0,%1,%2,%3}, {%4,%5,%6,%7}, {%8,%9}, {%0,%1,%2,%3};" \
        : "+f"((c)[0]), "+f"((c)[1]), "+f"((c)[2]), "+f"((c)[3]) \
        : "r"((a)[0]), "r"((a)[1]), "r"((a)[2]), "r"((a)[3]), "r"((b)[0]), "r"((b)[1]))

__device__ __forceinline__ void load_chunk(__nv_bfloat16* sm, const __nv_bfloat16* src,
                                           size_t ld, int tid){
    #pragma unroll
    for (int i=0;i<4;i++){
        int idx = tid + i*256;
        int row = idx >> 3, c4 = idx & 7;
        *(uint4*)(sm + row*72 + c4*8) = *(const uint4*)(src + (size_t)row*ld + c4*8);
    }
}
__device__ __forceinline__ void load_chunk64(__nv_bfloat16* sm, const __nv_bfloat16* src,
                                             size_t ld, int tid){
    #pragma unroll
    for (int i=0;i<2;i++){
        int idx = tid + i*256;
        int row = idx >> 3, c4 = idx & 7;
        *(uint4*)(sm + row*72 + c4*8) = *(const uint4*)(src + (size_t)row*ld + c4*8);
    }
}
__device__ __forceinline__ void cp_chunk(__nv_bfloat16* sm, const __nv_bfloat16* src,
                                         size_t ld, int tid){
    #pragma unroll
    for (int i=0;i<4;i++){
        int idx = tid + i*256;
        int row = idx >> 3, c4 = idx & 7;
        __pipeline_memcpy_async(sm + row*72 + c4*8, src + (size_t)row*ld + c4*8, 16);
    }
}
__device__ __forceinline__ void cp_chunk64(__nv_bfloat16* sm, const __nv_bfloat16* src,
                                           size_t ld, int tid){
    #pragma unroll
    for (int i=0;i<2;i++){
        int idx = tid + i*256;
        int row = idx >> 3, c4 = idx & 7;
        __pipeline_memcpy_async(sm + row*72 + c4*8, src + (size_t)row*ld + c4*8, 16);
    }
}

// CTA 128x128, 8 warps 4(m)x2(n)
__device__ __forceinline__ void mma_chunk(const __nv_bfloat16* As, const __nv_bfloat16* Bs,
                                          float cacc[2][8][4], int wm, int wn, int g, int t){
    #pragma unroll
    for (int ks=0;ks<4;ks++){
        int k = ks*16;
        uint32_t afr[2][4], bfr[8][2];
        #pragma unroll
        for (int mi=0;mi<2;mi++){
            const __nv_bfloat16* ap = As + (wm*32 + mi*16)*72 + k + 2*t;
            afr[mi][0] = *(const uint32_t*)(ap + g*72);
            afr[mi][1] = *(const uint32_t*)(ap + (g+8)*72);
            afr[mi][2] = *(const uint32_t*)(ap + g*72 + 8);
            afr[mi][3] = *(const uint32_t*)(ap + (g+8)*72 + 8);
        }
        #pragma unroll
        for (int nj=0;nj<8;nj++){
            const __nv_bfloat16* bp = Bs + (wn*64 + nj*8 + g)*72 + k + 2*t;
            bfr[nj][0] = *(const uint32_t*)(bp);
            bfr[nj][1] = *(const uint32_t*)(bp + 8);
        }
        #pragma unroll
        for (int mi=0;mi<2;mi++)
            #pragma unroll
            for (int nj=0;nj<8;nj++)
                MMA16816(cacc[mi][nj], afr[mi], bfr[nj]);
    }
}
// same but B row stride 136 (for Vsm tile)
__device__ __forceinline__ void mma_chunk_rv(const __nv_bfloat16* As, const __nv_bfloat16* Bs,
                                             float cacc[2][8][4], int wm, int wn, int g, int t){
    #pragma unroll
    for (int ks=0;ks<4;ks++){
        int k = ks*16;
        uint32_t afr[2][4], bfr[8][2];
        #pragma unroll
        for (int mi=0;mi<2;mi++){
            const __nv_bfloat16* ap = As + (wm*32 + mi*16)*72 + k + 2*t;
            afr[mi][0] = *(const uint32_t*)(ap + g*72);
            afr[mi][1] = *(const uint32_t*)(ap + (g+8)*72);
            afr[mi][2] = *(const uint32_t*)(ap + g*72 + 8);
            afr[mi][3] = *(const uint32_t*)(ap + (g+8)*72 + 8);
        }
        #pragma unroll
        for (int nj=0;nj<8;nj++){
            const __nv_bfloat16* bp = Bs + (wn*64 + nj*8 + g)*136 + k + 2*t;
            bfr[nj][0] = *(const uint32_t*)(bp);
            bfr[nj][1] = *(const uint32_t*)(bp + 8);
        }
        #pragma unroll
        for (int mi=0;mi<2;mi++)
            #pragma unroll
            for (int nj=0;nj<8;nj++)
                MMA16816(cacc[mi][nj], afr[mi], bfr[nj]);
    }
}

// CTA 128x64
__device__ __forceinline__ void mma_chunk4(const __nv_bfloat16* As, const __nv_bfloat16* Bs,
                                           float cacc[2][4][4], int wm, int wn, int g, int t){
    #pragma unroll
    for (int ks=0;ks<4;ks++){
        int k = ks*16;
        uint32_t afr[2][4], bfr[4][2];
        #pragma unroll
        for (int mi=0;mi<2;mi++){
            const __nv_bfloat16* ap = As + (wm*32 + mi*16)*72 + k + 2*t;
            afr[mi][0] = *(const uint32_t*)(ap + g*72);
            afr[mi][1] = *(const uint32_t*)(ap + (g+8)*72);
            afr[mi][2] = *(const uint32_t*)(ap + g*72 + 8);
            afr[mi][3] = *(const uint32_t*)(ap + (g+8)*72 + 8);
        }
        #pragma unroll
        for (int nj=0;nj<4;nj++){
            const __nv_bfloat16* bp = Bs + (wn*32 + nj*8 + g)*72 + k + 2*t;
            bfr[nj][0] = *(const uint32_t*)(bp);
            bfr[nj][1] = *(const uint32_t*)(bp + 8);
        }
        #pragma unroll
        for (int mi=0;mi<2;mi++)
            #pragma unroll
            for (int nj=0;nj<4;nj++)
                MMA16816(cacc[mi][nj], afr[mi], bfr[nj]);
    }
}

// ================= device state =================
__device__ float d_mem[NN * WW];
__device__ __nv_bfloat16 d_memn[NN * WW];
__device__ float d_c[BB * HH];
__device__ __nv_bfloat16 d_keysn[256 * WW];
__device__ __nv_bfloat16 d_eradT[256 * BB];
__device__ float d_scal[BB * 4];
__device__ __half d_sim[256 * NN];         // exp(beta*sim) fp16
__device__ float d_psum[256 * NTSIM];
__device__ float d_rw[BB * NN];
__device__ __nv_bfloat16 d_rwb[BB * NN];
__device__ __nv_bfloat16 d_wwT[NN * BB];
__device__ float d_rvpart[128 * BB * WW];  // 128 split-K partials (one per memupd CTA)
// split-bf16 LSTM (gate-interleaved row order: row = u*4 + gate)
__device__ __nv_bfloat16 d_Whi[G4 * KLSTM];
__device__ __nv_bfloat16 d_Wlo[G4 * KLSTM];
__device__ __nv_bfloat16 d_xhi[BB * SS * INSZ];
__device__ __nv_bfloat16 d_xlo[BB * SS * INSZ];
__device__ __nv_bfloat16 d_hhi[BB * HH];
__device__ __nv_bfloat16 d_hlo[BB * HH];
__device__ __nv_bfloat16 d_rvhi[BB * WW];
__device__ __nv_bfloat16 d_rvlo[BB * WW];
__device__ float d_gpart[2 * BB * G4];
__device__ float d_gx[SS * BB * G4];
// combined projection
__device__ __nv_bfloat16 d_PAhi[NPAD * KPAD];
__device__ __nv_bfloat16 d_PAlo[NPAD * KPAD];
__device__ __nv_bfloat16 d_WoThi[HH * KPAD];
__device__ __nv_bfloat16 d_WoTlo[HH * KPAD];
__device__ __nv_bfloat16 d_Pchi[NPROJ * HH];
__device__ __nv_bfloat16 d_Pclo[NPROJ * HH];
__device__ float d_bcomb[NPROJ];
__device__ float d_ppart[PKS * BB * NPROJ];
// counters
__device__ int d_gcnt[64];
__device__ int d_rvcnt;

__device__ __forceinline__ float sigmoidf_(float x){ return 1.f/(1.f+__expf(-x)); }
__device__ __forceinline__ float softplusf_(float x){ return x>15.f ? x : log1pf(__expf(x)); }

__device__ __forceinline__ float getP(int n, int c,
    const float* rkW, const float* wkW, const float* erW, const float* adW,
    const float* pW, const float* rbW, const float* rgW,
    const float* wbW, const float* wgW){
    if (n < 128)   return rkW[n*CC + c];
    if (n < 256)   return wkW[(n-128)*CC + c];
    if (n < 384)   return erW[(n-256)*CC + c];
    if (n < 512)   return adW[(n-384)*CC + c];
    if (n < 1024)  return (c < 512) ? pW[(size_t)(n-512)*512 + c] : 0.f;
    if (n == 1024) return rbW[c];
    if (n == 1025) return rgW[c];
    if (n == 1026) return wbW[c];
    if (n == 1027) return wgW[c];
    return 0.f;
}

// ================= init =================
__global__ void k_init(const float* __restrict__ memory){
    int i = blockIdx.x*256 + threadIdx.x;
    d_mem[i] = memory[i];
    d_rw[i]  = 1.0f/NN;
    if (i < BB*HH){ d_c[i]=0.f;
        d_hhi[i]=__float2bfloat16(0.f); d_hlo[i]=__float2bfloat16(0.f); }
    if (i < BB*WW){
        d_rvhi[i]=__float2bfloat16(0.f); d_rvlo[i]=__float2bfloat16(0.f); }
    if (i < 64) d_gcnt[i] = 0;
    if (i == 64) d_rvcnt = 0;
}

__global__ void k_wsplit(const float* __restrict__ Wih, const float* __restrict__ Whh){
    int i = blockIdx.x*256 + threadIdx.x;
    int j = i / KLSTM, k = i - j*KLSTM;
    float w = (k < 640) ? Wih[(size_t)j*640 + k] : Whh[(size_t)j*1024 + (k-640)];
    int u = j & 1023, gate = j >> 10;
    size_t jn = (size_t)(u*4 + gate)*KLSTM + k;
    __nv_bfloat16 hi = __float2bfloat16(w);
    d_Whi[jn] = hi;
    d_Wlo[jn] = __float2bfloat16(w - __bfloat162float(hi));
}

__global__ void k_xsplit(const float* __restrict__ x){
    int i = blockIdx.x*256 + threadIdx.x;
    float v = x[i];
    __nv_bfloat16 hi = __float2bfloat16(v);
    d_xhi[i] = hi;
    d_xlo[i] = __float2bfloat16(v - __bfloat162float(hi));
}

__global__ void k_psplit(const float* rkW, const float* wkW, const float* erW, const float* adW,
                         const float* pW,  const float* rbW, const float* rgW,
                         const float* wbW, const float* wgW){
    int i = blockIdx.x*256 + threadIdx.x;
    int n = i / KPAD, c = i - n*KPAD;
    float v = (c < CC && n < NPROJ) ? getP(n, c, rkW,wkW,erW,adW,pW,rbW,rgW,wbW,wgW) : 0.f;
    __nv_bfloat16 hi = __float2bfloat16(v);
    d_PAhi[i] = hi;
    d_PAlo[i] = __float2bfloat16(v - __bfloat162float(hi));
}

__global__ void k_woutT(const float* __restrict__ Wout){
    __shared__ float tile[32][33];
    int k0 = blockIdx.x*32, c0 = blockIdx.y*32;
    int tx = threadIdx.x & 31, ty = threadIdx.x >> 5;
    #pragma unroll
    for (int r=0;r<32;r+=8){
        int c = c0 + ty + r;
        tile[ty+r][tx] = (c < CC) ? Wout[(size_t)c*HH + k0 + tx] : 0.f;
    }
    __syncthreads();
    #pragma unroll
    for (int r=0;r<32;r+=8){
        int k = k0 + ty + r;
        float v = tile[tx][ty+r];
        __nv_bfloat16 hi = __float2bfloat16(v);
        d_WoThi[(size_t)k*KPAD + c0 + tx] = hi;
        d_WoTlo[(size_t)k*KPAD + c0 + tx] = __float2bfloat16(v - __bfloat162float(hi));
    }
}

__global__ void __launch_bounds__(256) k_wcombT(){
    __shared__ __nv_bfloat16 As[128*72];
    __shared__ __nv_bfloat16 Bs[64*72];
    int tid = threadIdx.x, lane = tid & 31, wid = tid >> 5;
    int wm = wid >> 1, wn = wid & 1, g = lane >> 2, tq = lane & 3;
    int m0 = blockIdx.x*128;
    int n0 = blockIdx.y*64;

    float cacc[2][4][4] = {};
    #pragma unroll
    for (int pass=0; pass<3; pass++){
        const __nv_bfloat16* Ab = (pass==1) ? d_PAlo : d_PAhi;
        const __nv_bfloat16* Wb = (pass==2) ? d_WoTlo : d_WoThi;
        #pragma unroll
        for (int cc=0; cc<15; cc++){
            int k0 = cc*64;
            load_chunk(As, Ab + (size_t)m0*KPAD + k0, KPAD, tid);
            load_chunk64(Bs, Wb + (size_t)n0*KPAD + k0, KPAD, tid);
            __syncthreads();
            mma_chunk4(As, Bs, cacc, wm, wn, g, tq);
            __syncthreads();
        }
    }
    #pragma unroll
    for (int mi=0;mi<2;mi++){
        int rl0 = wm*32 + mi*16 + g, rl1 = rl0 + 8;
        #pragma unroll
        for (int nj=0;nj<4;nj++){
            int col = n0 + wn*32 + nj*8 + 2*tq;
            #pragma unroll
            for (int hh=0;hh<2;hh++){
                int row = m0 + (hh ? rl1 : rl0);
                if (row < NPROJ){
                    float w0 = cacc[mi][nj][hh*2], w1 = cacc[mi][nj][hh*2+1];
                    __nv_bfloat16 h0 = __float2bfloat16(w0), h1 = __float2bfloat16(w1);
                    d_Pchi[(size_t)row*HH + col]   = h0;
                    d_Pchi[(size_t)row*HH + col+1] = h1;
                    d_Pclo[(size_t)row*HH + col]   = __float2bfloat16(w0 - __bfloat162float(h0));
                    d_Pclo[(size_t)row*HH + col+1] = __float2bfloat16(w1 - __bfloat162float(h1));
                }
            }
        }
    }
}

__global__ void k_bcomb(const float* __restrict__ bout,
                        const float* rkW, const float* wkW, const float* erW, const float* adW,
                        const float* pW,  const float* rbW, const float* rgW,
                        const float* wbW, const float* wgW,
                        const float* rkb, const float* wkb, const float* erb, const float* adb,
                        const float* pb,  const float* rbb, const float* rgb,
                        const float* wbb, const float* wgb){
    int n = blockIdx.x*256 + threadIdx.x;
    if (n >= NPROJ) return;
    float s = 0.f;
    for (int c = 0; c < CC; c++)
        s += getP(n, c, rkW,wkW,erW,adW,pW,rbW,rgW,wbW,wgW) * bout[c];
    float bias = 0.f;
    if (n < 128)        bias = rkb[n];
    else if (n < 256)   bias = wkb[n-128];
    else if (n < 384)   bias = erb[n-256];
    else if (n < 512)   bias = adb[n-384];
    else if (n < 1024)  bias = pb[n-512];
    else if (n == 1024) bias = rbb[0];
    else if (n == 1025) bias = rgb[0];
    else if (n == 1026) bias = wbb[0];
    else if (n == 1027) bias = wgb[0];
    d_bcomb[n] = s + bias;
}

__global__ void k_rownorm(){
    int row  = blockIdx.x*8 + (threadIdx.x>>5);
    int lane = threadIdx.x & 31;
    const float4* p = (const float4*)(d_mem + (size_t)row*WW);
    float4 v = p[lane];
    float s = v.x*v.x + v.y*v.y + v.z*v.z + v.w*v.w;
    #pragma unroll
    for (int o=16;o;o>>=1) s += __shfl_xor_sync(0xffffffffu, s, o);
    s = __shfl_sync(0xffffffffu, s, 0);
    float inv = 1.f / fmaxf(sqrtf(s), 1e-12f);
    __nv_bfloat162* nm = (__nv_bfloat162*)(d_memn + (size_t)row*WW + lane*4);
    nm[0] = __floats2bfloat162_rn(v.x*inv, v.y*inv);
    nm[1] = __floats2bfloat162_rn(v.z*inv, v.w*inv);
}

// ================= one-time xW GEMM =================
__global__ void __launch_bounds__(256) k_xw(){
    extern __shared__ __nv_bfloat16 smp[];
    __nv_bfloat16* Asb[2] = { smp, smp + 128*72 };
    __nv_bfloat16* Bsb[2] = { smp + 2*128*72, smp + 2*128*72 + 64*72 };
    int tid = threadIdx.x, lane = tid & 31, wid = tid >> 5;
    int wm = wid >> 1, wn = wid & 1, g = lane >> 2, tq = lane & 3;
    int n0 = blockIdx.x*64;
    int t  = blockIdx.y;
    const int NIT = 24;

    auto srcA = [&](int it)->const __nv_bfloat16*{
        int pass = it >> 3, k0 = (it & 7)*64;
        return ((pass==1) ? d_xlo : d_xhi) + (size_t)t*INSZ + k0;
    };
    auto srcB = [&](int it)->const __nv_bfloat16*{
        int pass = it >> 3, k0 = (it & 7)*64;
        return ((pass==2) ? d_Wlo : d_Whi) + (size_t)n0*KLSTM + k0;
    };

    float cacc[2][4][4] = {};
    cp_chunk(Asb[0], srcA(0), (size_t)SS*INSZ, tid);
    cp_chunk64(Bsb[0], srcB(0), KLSTM, tid);
    __pipeline_commit();
    for (int it=0; it<NIT; it++){
        if (it+1 < NIT){
            cp_chunk(Asb[(it+1)&1], srcA(it+1), (size_t)SS*INSZ, tid);
            cp_chunk64(Bsb[(it+1)&1], srcB(it+1), KLSTM, tid);
            __pipeline_commit();
            __pipeline_wait_prior(1);
        } else __pipeline_wait_prior(0);
        __syncthreads();
        mma_chunk4(Asb[it&1], Bsb[it&1], cacc, wm, wn, g, tq);
        __syncthreads();
    }
    float* gp = d_gx + (size_t)t*BB*G4;
    #pragma unroll
    for (int mi=0;mi<2;mi++){
        int rl0 = wm*32 + mi*16 + g, rl1 = rl0 + 8;
        #pragma unroll
        for (int nj=0;nj<4;nj++){
            int col = n0 + wn*32 + nj*8 + 2*tq;
            *(float2*)&gp[(size_t)rl0*G4 + col] = make_float2(cacc[mi][nj][0], cacc[mi][nj][1]);
            *(float2*)&gp[(size_t)rl1*G4 + col] = make_float2(cacc[mi][nj][2], cacc[mi][nj][3]);
        }
    }
}

// ================= LSTM recurrent GEMM + fused gates =================
__global__ void __launch_bounds__(256) k_lstmT(int t, const float* __restrict__ bih,
                                               const float* __restrict__ bhh){
    extern __shared__ __nv_bfloat16 smp[];
    __nv_bfloat16* Asb[2] = { smp, smp + 128*72 };
    __nv_bfloat16* Bsb[2] = { smp + 2*128*72, smp + 2*128*72 + 64*72 };
    __shared__ int lastflag;
    int tid = threadIdx.x, lane = tid & 31, wid = tid >> 5;
    int wm = wid >> 1, wn = wid & 1, g = lane >> 2, tq = lane & 3;
    int n0 = blockIdx.x*64;
    int ks = blockIdx.y;
    const int NIT = 27;

    auto srcA = [&](int it, size_t& lda)->const __nv_bfloat16*{
        int pass = it/9, cc = it - pass*9;
        int k0 = 512 + (ks*9 + cc)*64;
        if (k0 < 640){ lda = WW; return ((pass==1) ? d_rvlo : d_rvhi) + (k0-512); }
        lda = HH; return ((pass==1) ? d_hlo : d_hhi) + (k0-640);
    };
    auto srcB = [&](int it)->const __nv_bfloat16*{
        int pass = it/9, cc = it - pass*9;
        int k0 = 512 + (ks*9 + cc)*64;
        return ((pass==2) ? d_Wlo : d_Whi) + (size_t)n0*KLSTM + k0;
    };

    float cacc[2][4][4] = {};
    { size_t lda; const __nv_bfloat16* a = srcA(0, lda);
      cp_chunk(Asb[0], a, lda, tid); cp_chunk64(Bsb[0], srcB(0), KLSTM, tid);
      __pipeline_commit(); }
    for (int it=0; it<NIT; it++){
        if (it+1 < NIT){
            size_t lda; const __nv_bfloat16* a = srcA(it+1, lda);
            cp_chunk(Asb[(it+1)&1], a, lda, tid);
            cp_chunk64(Bsb[(it+1)&1], srcB(it+1), KLSTM, tid);
            __pipeline_commit();
            __pipeline_wait_prior(1);
        } else __pipeline_wait_prior(0);
        __syncthreads();
        mma_chunk4(Asb[it&1], Bsb[it&1], cacc, wm, wn, g, tq);
        __syncthreads();
    }
    float* gp = d_gpart + (size_t)ks*BB*G4;
    #pragma unroll
    for (int mi=0;mi<2;mi++){
        int rl0 = wm*32 + mi*16 + g, rl1 = rl0 + 8;
        #pragma unroll
        for (int nj=0;nj<4;nj++){
            int col = n0 + wn*32 + nj*8 + 2*tq;
            *(float2*)&gp[(size_t)rl0*G4 + col] = make_float2(cacc[mi][nj][0], cacc[mi][nj][1]);
            *(float2*)&gp[(size_t)rl1*G4 + col] = make_float2(cacc[mi][nj][2], cacc[mi][nj][3]);
        }
    }
    __threadfence();
    __syncthreads();
    if (tid == 0){
        int old = atomicAdd(&d_gcnt[blockIdx.x], 1);
        lastflag = (old == 2*t + 1);
    }
    __syncthreads();
    if (lastflag){
        const float* p0 = d_gpart;
        const float* p1 = d_gpart + (size_t)BB*G4;
        const float* px = d_gx + (size_t)t*BB*G4;
        int u0 = n0 >> 2;
        #pragma unroll
        for (int p=0;p<8;p++){
            int pair = tid + p*256;
            int b = pair >> 4, ul = pair & 15;
            int u = u0 + ul;
            size_t base = (size_t)b*G4 + u*4;
            float4 a0 = *(const float4*)&p0[base];
            float4 a1 = *(const float4*)&p1[base];
            float4 ax = *(const float4*)&px[base];
            float gi = a0.x + a1.x + ax.x + bih[u]      + bhh[u];
            float gf = a0.y + a1.y + ax.y + bih[1024+u] + bhh[1024+u];
            float gg = a0.z + a1.z + ax.z + bih[2048+u] + bhh[2048+u];
            float go = a0.w + a1.w + ax.w + bih[3072+u] + bhh[3072+u];
            int i = b*HH + u;
            float c = sigmoidf_(gf)*d_c[i] + sigmoidf_(gi)*tanhf(gg);
            float h = sigmoidf_(go)*tanhf(c);
            d_c[i] = c;
            __nv_bfloat16 hi = __float2bfloat16(h);
            d_hhi[i] = hi;
            d_hlo[i] = __float2bfloat16(h - __bfloat162float(hi));
        }
    }
}

// ================= combined projection GEMM (split-K 4) =================
__global__ void __launch_bounds__(256) k_projT(){
    extern __shared__ __nv_bfloat16 smp[];
    __nv_bfloat16* Asb[2] = { smp, smp + 128*72 };
    __nv_bfloat16* Bsb[2] = { smp + 2*128*72, smp + 2*128*72 + 64*72 };
    int tid = threadIdx.x, lane = tid & 31, wid = tid >> 5;
    int wm = wid >> 1, wn = wid & 1, g = lane >> 2, tq = lane & 3;
    int n0 = blockIdx.x*64;
    int ks = blockIdx.y;
    const int NIT = 12;   // 3 passes x 4 chunks (K quarter = 256)

    auto srcA = [&](int it)->const __nv_bfloat16*{
        int pass = it >> 2, k0 = ks*256 + (it & 3)*64;
        return ((pass==1) ? d_hlo : d_hhi) + k0;
    };
    auto srcB = [&](int it)->const __nv_bfloat16*{
        int pass = it >> 2, k0 = ks*256 + (it & 3)*64;
        return ((pass==2) ? d_Pclo : d_Pchi) + (size_t)n0*HH + k0;
    };

    float cacc[2][4][4] = {};
    cp_chunk(Asb[0], srcA(0), HH, tid);
    cp_chunk64(Bsb[0], srcB(0), HH, tid);
    __pipeline_commit();
    for (int it=0; it<NIT; it++){
        if (it+1 < NIT){
            cp_chunk(Asb[(it+1)&1], srcA(it+1), HH, tid);
            cp_chunk64(Bsb[(it+1)&1], srcB(it+1), HH, tid);
            __pipeline_commit();
            __pipeline_wait_prior(1);
        } else __pipeline_wait_prior(0);
        __syncthreads();
        mma_chunk4(Asb[it&1], Bsb[it&1], cacc, wm, wn, g, tq);
        __syncthreads();
    }
    float* gp = d_ppart + (size_t)ks*BB*NPROJ;
    #pragma unroll
    for (int mi=0;mi<2;mi++){
        int rl0 = wm*32 + mi*16 + g, rl1 = rl0 + 8;
        #pragma unroll
        for (int nj=0;nj<4;nj++){
            int col = n0 + wn*32 + nj*8 + 2*tq;
            *(float2*)&gp[(size_t)rl0*NPROJ + col] = make_float2(cacc[mi][nj][0], cacc[mi][nj][1]);
            *(float2*)&gp[(size_t)rl1*NPROJ + col] = make_float2(cacc[mi][nj][2], cacc[mi][nj][3]);
        }
    }
}

// ================= projection epilogue =================
__global__ void k_posproj(float* __restrict__ out, int t){
    __shared__ float pp[1028];
    __shared__ float wsum[8];
    int b = blockIdx.x, tid = threadIdx.x;
    for (int n = tid; n < 1028; n += 256){
        float v = d_bcomb[n];
        #pragma unroll
        for (int p=0;p<PKS;p++) v += d_ppart[(size_t)(p*BB+b)*NPROJ + n];
        pp[n] = v;
    }
    __syncthreads();

    int half = tid >> 7, w = tid & 127;
    float v = pp[half*128 + w];
    float sq = v*v;
    #pragma unroll
    for (int o=16;o;o>>=1) sq += __shfl_xor_sync(0xffffffffu, sq, o);
    if (!(tid & 31)) wsum[tid >> 5] = sq;
    __syncthreads();
    int base = half*4;
    float s = wsum[base] + wsum[base+1] + wsum[base+2] + wsum[base+3];
    float inv = 1.f / fmaxf(sqrtf(s), 1e-12f);
    d_keysn[(size_t)(half*128 + b)*WW + w] = __float2bfloat16(v*inv);
    float ev = half ? tanhf(pp[384 + w]) : sigmoidf_(pp[256 + w]);
    d_eradT[(half*128 + w)*BB + b] = __float2bfloat16(ev);
    for (int o = tid; o < OUTSZ; o += 256)
        out[((size_t)b*SS + t)*OUTSZ + o] = pp[512 + o];
    if (tid < 4){
        float vv = softplusf_(pp[1024 + tid]);
        if (tid & 1) vv += 1.f;
        d_scal[b*4 + tid] = vv;
    }
}

// ================= sim + exp fused =================
__global__ void __launch_bounds__(256) k_simT(){
    extern __shared__ __nv_bfloat16 smp[];
    __nv_bfloat16* Asb[2] = { smp, smp + 128*72 };
    __nv_bfloat16* Bsb[2] = { smp + 2*128*72, smp + 3*128*72 };
    __shared__ float redm[128][2];
    int tid = threadIdx.x, lane = tid & 31, wid = tid >> 5;
    int wm = wid >> 1, wn = wid & 1, g = lane >> 2, t = lane & 3;
    int m0 = blockIdx.y*128, n0 = blockIdx.x*128;
    int head = m0 >> 7;

    float cacc[2][8][4] = {};
    cp_chunk(Asb[0], d_keysn + (size_t)m0*WW, WW, tid);
    cp_chunk(Bsb[0], d_memn  + (size_t)n0*WW, WW, tid);
    __pipeline_commit();
    #pragma unroll
    for (int it=0; it<2; it++){
        if (it == 0){
            cp_chunk(Asb[1], d_keysn + (size_t)m0*WW + 64, WW, tid);
            cp_chunk(Bsb[1], d_memn  + (size_t)n0*WW + 64, WW, tid);
            __pipeline_commit();
            __pipeline_wait_prior(1);
        } else __pipeline_wait_prior(0);
        __syncthreads();
        mma_chunk(Asb[it], Bsb[it], cacc, wm, wn, g, t);
        __syncthreads();
    }
    #pragma unroll
    for (int mi=0;mi<2;mi++){
        int rl0 = wm*32 + mi*16 + g, rl1 = rl0 + 8;
        float beta0 = d_scal[((m0+rl0)&127)*4 + head*2];
        float beta1 = d_scal[((m0+rl1)&127)*4 + head*2];
        float s0 = 0.f, s1 = 0.f;
        #pragma unroll
        for (int nj=0;nj<8;nj++){
            int col = n0 + wn*64 + nj*8 + 2*t;
            float e0 = __expf(beta0*cacc[mi][nj][0]);
            float e1 = __expf(beta0*cacc[mi][nj][1]);
            float e2 = __expf(beta1*cacc[mi][nj][2]);
            float e3 = __expf(beta1*cacc[mi][nj][3]);
            *(__half2*)&d_sim[(size_t)(m0+rl0)*NN + col] = __floats2half2_rn(e0, e1);
            *(__half2*)&d_sim[(size_t)(m0+rl1)*NN + col] = __floats2half2_rn(e2, e3);
            s0 += e0 + e1;
            s1 += e2 + e3;
        }
        s0 += __shfl_xor_sync(0xffffffffu, s0, 1);
        s0 += __shfl_xor_sync(0xffffffffu, s0, 2);
        s1 += __shfl_xor_sync(0xffffffffu, s1, 1);
        s1 += __shfl_xor_sync(0xffffffffu, s1, 2);
        if (t == 0){ redm[rl0][wn] = s0; redm[rl1][wn] = s1; }
    }
    __syncthreads();
    if (tid < 128)
        d_psum[(size_t)(m0+tid)*NTSIM + blockIdx.x] = redm[tid][0] + redm[tid][1];
}

// ================= softmax normalize + interpolation =================
__global__ void k_smax(){
    __shared__ float red[256];
    int r = blockIdx.x;
    int head = r >> 7, b = r & 127;
    float gamma = d_scal[b*4 + head*2 + 1];
    int tid = threadIdx.x;

    red[tid] = (tid < NTSIM) ? d_psum[(size_t)r*NTSIM + tid] : 0.f;
    __syncthreads();
    for (int o=128;o;o>>=1){ if (tid<o) red[tid] += red[tid+o]; __syncthreads(); }
    float inv = 1.f / red[0];

    const __half* simrow = d_sim + (size_t)r*NN;
    if (head == 0){
        float* rw = d_rw + (size_t)b*NN;
        __nv_bfloat16* rwb = d_rwb + (size_t)b*NN;
        for (int n = tid; n < NN; n += 256){
            float w = __half2float(simrow[n])*inv;
            float v = gamma*w + (1.f-gamma)*rw[n];
            rw[n] = v;
            rwb[n] = __float2bfloat16(v);
        }
    } else {
        const float u = 1.f/NN;
        for (int n = tid; n < NN; n += 256){
            float w = __half2float(simrow[n])*inv;
            float v = gamma*w + (1.f-gamma)*u;
            d_wwT[(size_t)n*BB + b] = __float2bfloat16(v);
        }
    }
}

// ================= memory update + fused rv =================
__global__ void __launch_bounds__(256) k_memupdT(int iter){
    extern __shared__ __nv_bfloat16 smb[];
    __nv_bfloat16* As = smb;
    __nv_bfloat16* Bs = smb + 128*72;
    float* Esm = (float*)(smb + 2*128*72);          // [128][132] fp32, later Vsm bf16 [128][136]
    __shared__ float redm[128][2];
    __shared__ float invsm[128];
    int tid = threadIdx.x, lane = tid & 31, wid = tid >> 5;
    int wm = wid >> 1, wn = wid & 1, g = lane >> 2, t = lane & 3;
    int q0 = blockIdx.x*128;

    float cacc[2][8][4] = {};
    #pragma unroll
    for (int ph=0; ph<2; ph++){
        #pragma unroll
        for (int kc=0;kc<2;kc++){
            load_chunk(As, d_wwT + (size_t)q0*BB + kc*64, BB, tid);
            load_chunk(Bs, d_eradT + ph*128*BB + kc*64, BB, tid);
            __syncthreads();
            mma_chunk(As, Bs, cacc, wm, wn, g, t);
            __syncthreads();
        }
        if (ph == 0){
            #pragma unroll
            for (int mi=0;mi<2;mi++){
                int rl0 = wm*32 + mi*16 + g, rl1 = rl0 + 8;
                #pragma unroll
                for (int nj=0;nj<8;nj++){
                    int cl = wn*64 + nj*8 + 2*t;
                    Esm[rl0*132 + cl]   = cacc[mi][nj][0];
                    Esm[rl0*132 + cl+1] = cacc[mi][nj][1];
                    Esm[rl1*132 + cl]   = cacc[mi][nj][2];
                    Esm[rl1*132 + cl+1] = cacc[mi][nj][3];
                    cacc[mi][nj][0]=0.f; cacc[mi][nj][1]=0.f;
                    cacc[mi][nj][2]=0.f; cacc[mi][nj][3]=0.f;
                }
            }
        }
    }
    float ssq[2][2] = {};
    #pragma unroll
    for (int mi=0;mi<2;mi++){
        int rl0 = wm*32 + mi*16 + g, rl1 = rl0 + 8;
        #pragma unroll
        for (int nj=0;nj<8;nj++){
            int cl = wn*64 + nj*8 + 2*t;
            float2 m0v = *(const float2*)&d_mem[(size_t)(q0+rl0)*WW + cl];
            float2 m1v = *(const float2*)&d_mem[(size_t)(q0+rl1)*WW + cl];
            float v00 = m0v.x*(1.f - Esm[rl0*132+cl])   + cacc[mi][nj][0];
            float v01 = m0v.y*(1.f - Esm[rl0*132+cl+1]) + cacc[mi][nj][1];
            float v10 = m1v.x*(1.f - Esm[rl1*132+cl])   + cacc[mi][nj][2];
            float v11 = m1v.y*(1.f - Esm[rl1*132+cl+1]) + cacc[mi][nj][3];
            cacc[mi][nj][0]=v00; cacc[mi][nj][1]=v01; cacc[mi][nj][2]=v10; cacc[mi][nj][3]=v11;
            ssq[mi][0] += v00*v00 + v01*v01;
            ssq[mi][1] += v10*v10 + v11*v11;
        }
    }
    #pragma unroll
    for (int mi=0;mi<2;mi++){
        #pragma unroll
        for (int h=0;h<2;h++){
            float s = ssq[mi][h];
            s += __shfl_xor_sync(0xffffffffu, s, 1);
            s += __shfl_xor_sync(0xffffffffu, s, 2);
            if (t == 0) redm[wm*32 + mi*16 + h*8 + g][wn] = s;
        }
    }
    __syncthreads();
    if (tid < 128) invsm[tid] = 1.f / fmaxf(sqrtf(redm[tid][0] + redm[tid][1]), 1e-12f);
    __syncthreads();
    __nv_bfloat16* Vsm = (__nv_bfloat16*)Esm;       // [w=128][n=128] stride 136 (transposed tile)
    #pragma unroll
    for (int mi=0;mi<2;mi++){
        int rl0 = wm*32 + mi*16 + g, rl1 = rl0 + 8;
        float i0 = invsm[rl0], i1 = invsm[rl1];
        #pragma unroll
        for (int nj=0;nj<8;nj++){
            int cl = wn*64 + nj*8 + 2*t;
            float v00=cacc[mi][nj][0], v01=cacc[mi][nj][1], v10=cacc[mi][nj][2], v11=cacc[mi][nj][3];
            *(float2*)&d_mem[(size_t)(q0+rl0)*WW + cl] = make_float2(v00, v01);
            *(float2*)&d_mem[(size_t)(q0+rl1)*WW + cl] = make_float2(v10, v11);
            *(__nv_bfloat162*)&d_memn[(size_t)(q0+rl0)*WW + cl] = __floats2bfloat162_rn(v00*i0, v01*i0);
            *(__nv_bfloat162*)&d_memn[(size_t)(q0+rl1)*WW + cl] = __floats2bfloat162_rn(v10*i1, v11*i1);
            Vsm[cl*136 + rl0]     = __float2bfloat16(v00);
            Vsm[(cl+1)*136 + rl0] = __float2bfloat16(v01);
            Vsm[cl*136 + rl1]     = __float2bfloat16(v10);
            Vsm[(cl+1)*136 + rl1] = __float2bfloat16(v11);
        }
    }
    __syncthreads();
    // ---- fused rv partial: rvpart[blk] = rwb[:, q0:q0+128] @ mem_new[q0:q0+128, :] ----
    load_chunk(As, d_rwb + q0, NN, tid);        // A chunk k=0..63 (n-cols q0..q0+63)
    load_chunk(Bs, d_rwb + q0 + 64, NN, tid);   // A chunk k=64..127
    #pragma unroll
    for (int mi=0;mi<2;mi++)
        #pragma unroll
        for (int nj=0;nj<8;nj++)
            #pragma unroll
            for (int q=0;q<4;q++) cacc[mi][nj][q] = 0.f;
    __syncthreads();
    mma_chunk_rv(As, Vsm,      cacc, wm, wn, g, t);
    mma_chunk_rv(Bs, Vsm + 64, cacc, wm, wn, g, t);
    float* dst = d_rvpart + (size_t)blockIdx.x*BB*WW;
    #pragma unroll
    for (int mi=0;mi<2;mi++){
        int rl0 = wm*32 + mi*16 + g, rl1 = rl0 + 8;
        #pragma unroll
        for (int nj=0;nj<8;nj++){
            int cl = wn*64 + nj*8 + 2*t;
            *(float2*)&dst[(size_t)rl0*WW + cl] = make_float2(cacc[mi][nj][0], cacc[mi][nj][1]);
            *(float2*)&dst[(size_t)rl1*WW + cl] = make_float2(cacc[mi][nj][2], cacc[mi][nj][3]);
        }
    }
    // ---- all 128 CTAs resident: spin, then each reduces a 128-slice ----
    __threadfence();
    __syncthreads();
    if (tid == 0){
        atomicAdd(&d_rvcnt, 1);
        int target = 128*(iter+1);
        while (atomicAdd(&d_rvcnt, 0) < target) {}
    }
    __syncthreads();
    if (tid < 128){
        int idx = blockIdx.x*128 + tid;
        float s = 0.f;
        #pragma unroll 8
        for (int p=0;p<128;p++) s += d_rvpart[(size_t)p*16384 + idx];
        __nv_bfloat16 hi = __float2bfloat16(s);
        d_rvhi[idx] = hi;
        d_rvlo[idx] = __float2bfloat16(s - __bfloat162float(hi));
    }
}

// ================= launch =================
extern "C" void kernel_launch(void* const* d_in, const int* in_sizes, int n_in,
                              void* d_out, int out_size){
    const float* x      = (const float*)d_in[0];
    const float* memory = (const float*)d_in[1];
    const float* Wih    = (const float*)d_in[2];
    const float* Whh    = (const float*)d_in[3];
    const float* bih    = (const float*)d_in[4];
    const float* bhh    = (const float*)d_in[5];
    const float* Wout   = (const float*)d_in[6];
    const float* bout   = (const float*)d_in[7];
    const float* rkW    = (const float*)d_in[8];
    const float* rkb    = (const float*)d_in[9];
    const float* rbW    = (const float*)d_in[10];
    const float* rbb    = (const float*)d_in[11];
    const float* rgW    = (const float*)d_in[12];
    const float* rgb    = (const float*)d_in[13];
    const float* wkW    = (const float*)d_in[14];
    const float* wkb    = (const float*)d_in[15];
    const float* wbW    = (const float*)d_in[16];
    const float* wbb    = (const float*)d_in[17];
    const float* wgW    = (const float*)d_in[18];
    const float* wgb    = (const float*)d_in[19];
    const float* erW    = (const float*)d_in[20];
    const float* erb    = (const float*)d_in[21];
    const float* adW    = (const float*)d_in[22];
    const float* adb    = (const float*)d_in[23];
    const float* pW     = (const float*)d_in[24];
    const float* pb     = (const float*)d_in[25];
    float* out = (float*)d_out;

    const int SM_P64  = (2*128*72 + 2*64*72)*2;      // 55296
    const int SM_P128 = (4*128*72)*2;                // 73728
    const int SM_MUPD = 2*128*72*2 + 128*132*4;      // 104448
    cudaFuncSetAttribute(k_lstmT,   cudaFuncAttributeMaxDynamicSharedMemorySize, SM_P64);
    cudaFuncSetAttribute(k_projT,   cudaFuncAttributeMaxDynamicSharedMemorySize, SM_P64);
    cudaFuncSetAttribute(k_xw,      cudaFuncAttributeMaxDynamicSharedMemorySize, SM_P64);
    cudaFuncSetAttribute(k_simT,    cudaFuncAttributeMaxDynamicSharedMemorySize, SM_P128);
    cudaFuncSetAttribute(k_memupdT, cudaFuncAttributeMaxDynamicSharedMemorySize, SM_MUPD);

    k_init<<<8192, 256>>>(memory);
    k_wsplit<<<G4*KLSTM/256, 256>>>(Wih, Whh);
    k_xsplit<<<BB*SS*INSZ/256, 256>>>(x);
    k_psplit<<<NPAD*KPAD/256, 256>>>(rkW,wkW,erW,adW,pW,rbW,rgW,wbW,wgW);
    k_woutT<<<dim3(HH/32, KPAD/32), 256>>>(Wout);
    k_wcombT<<<dim3(NPAD/128, HH/64), 256>>>();
    k_bcomb<<<(NPROJ+255)/256, 256>>>(bout, rkW,wkW,erW,adW,pW,rbW,rgW,wbW,wgW,
                                      rkb,wkb,erb,adb,pb,rbb,rgb,wbb,wgb);
    k_xw<<<dim3(64, SS), 256, SM_P64>>>();
    k_rownorm<<<2048, 256>>>();
    for (int t = 0; t < SS; t++){
        k_lstmT<<<dim3(64,2), 256, SM_P64>>>(t, bih, bhh);
        k_projT<<<dim3(NPROJ/64, PKS), 256, SM_P64>>>();
        k_posproj<<<128, 256>>>(out, t);
        if (t + 1 < SS){
            k_simT<<<dim3(128,2), 256, SM_P128>>>();
            k_smax<<<256, 256>>>();
            k_memupdT<<<128, 256, SM_MUPD>>>(t);
        }
    }
}